// round 5
// baseline (speedup 1.0000x reference)
#include <cuda_runtime.h>
#include <cstdint>
#include <cstddef>

#define TT    243
#define NJ    17
#define BB    4
#define HH    8
#define HD    64
#define CC    512
#define EE    4
#define MROWS (BB*TT*NJ)   // 16524
#define NQKV  1536

// ---- scratch (static device globals; no allocations allowed) ----
__device__ float g_qkv[(size_t)MROWS * NQKV];   // ~101.5 MB
__device__ float g_gate[(size_t)MROWS * EE];
__device__ float g_eo[(size_t)MROWS * CC];      // ~33.8 MB

static __device__ __forceinline__ float warp_sum(float v) {
    #pragma unroll
    for (int o = 16; o; o >>= 1) v += __shfl_xor_sync(0xffffffffu, v, o);
    return v;
}
static __device__ __forceinline__ float warp_max(float v) {
    #pragma unroll
    for (int o = 16; o; o >>= 1) v = fmaxf(v, __shfl_xor_sync(0xffffffffu, v, o));
    return v;
}

static __device__ __forceinline__ uint32_t f2tf32(float x) {
    uint32_t r;
    asm("cvt.rna.tf32.f32 %0, %1;" : "=r"(r) : "f"(x));
    return r;
}
static __device__ __forceinline__ uint32_t ld_tf32(const float* p) {
    return f2tf32(*p);
}

static __device__ __forceinline__ void mma_m16n8k8(
    float* c, const uint32_t* a, const uint32_t* b)
{
    asm volatile(
        "mma.sync.aligned.m16n8k8.row.col.f32.tf32.tf32.f32 "
        "{%0,%1,%2,%3}, {%4,%5,%6,%7}, {%8,%9}, {%0,%1,%2,%3};\n"
        : "+f"(c[0]), "+f"(c[1]), "+f"(c[2]), "+f"(c[3])
        : "r"(a[0]), "r"(a[1]), "r"(a[2]), "r"(a[3]),
          "r"(b[0]), "r"(b[1]));
}

static __device__ __forceinline__ void cp_async16(float* dst_smem, const float* src, bool pred) {
    uint32_t daddr = (uint32_t)__cvta_generic_to_shared(dst_smem);
    int sz = pred ? 16 : 0;
    asm volatile("cp.async.cg.shared.global [%0], [%1], 16, %2;\n"
                 :: "r"(daddr), "l"(src), "r"(sz));
}
#define CP_COMMIT() asm volatile("cp.async.commit_group;\n" ::: "memory")
#define CP_WAIT0()  asm volatile("cp.async.wait_group 0;\n" ::: "memory")
#define CP_WAIT1()  asm volatile("cp.async.wait_group 1;\n" ::: "memory")

// ============================================================================
// K1/K4: tf32 tensor-core GEMM, cp.async double-buffered.
// BM=BN=128, BK=16, 256 threads, 8 warps (2m x 4n), warptile 64x32.
// Raw fp32 staged in smem; cvt.rna.tf32 at fragment-load time (same values,
// same rounding as R3 => numerically identical).
// ============================================================================
#define AP 20
#define BP 136

template <bool BIAS>
__global__ __launch_bounds__(256) void gemm_tf32(
    const float* __restrict__ A, const float* __restrict__ B,
    const float* __restrict__ bias, float* __restrict__ C,
    int M, int N, int K)
{
    __shared__ float As[2][128 * AP];
    __shared__ float Bs[2][16 * BP];

    const int tid  = threadIdx.x;
    const int warp = tid >> 5, lane = tid & 31;
    const int g    = lane >> 2, tig = lane & 3;
    const int wm   = warp & 1,  wn  = warp >> 1;
    const int m0   = blockIdx.y * 128, n0 = blockIdx.x * 128;

    // per-thread staging coordinates (2 chunks of 256 threads each)
    // A: 128 rows x 4 float4 / row ; B: 16 rows x 32 float4 / row
    int ar[2], ac4[2], br[2], bc4[2];
    bool apred[2];
    #pragma unroll
    for (int l = 0; l < 2; l++) {
        int li = tid + l * 256;
        ar[l] = li >> 2; ac4[l] = (li & 3) * 4;
        apred[l] = (m0 + ar[l]) < M;
        br[l] = li >> 5; bc4[l] = (li & 31) * 4;
    }

    float c[4][4][4];
    #pragma unroll
    for (int i = 0; i < 4; i++)
        #pragma unroll
        for (int j = 0; j < 4; j++)
            #pragma unroll
            for (int f = 0; f < 4; f++) c[i][j][f] = 0.f;

    const int niter = K / 16;

    // ---- preload k0 = 0 into buffer 0 ----
    #pragma unroll
    for (int l = 0; l < 2; l++) {
        int garow = apred[l] ? (m0 + ar[l]) : (M - 1);
        cp_async16(&As[0][ar[l] * AP + ac4[l]], A + (size_t)garow * K + ac4[l], apred[l]);
        cp_async16(&Bs[0][br[l] * BP + bc4[l]], B + (size_t)br[l] * N + n0 + bc4[l], true);
    }
    CP_COMMIT();

    for (int it = 0; it < niter; it++) {
        int cur = it & 1, nxt = cur ^ 1;
        if (it + 1 < niter) {
            int k0n = (it + 1) * 16;
            #pragma unroll
            for (int l = 0; l < 2; l++) {
                int garow = apred[l] ? (m0 + ar[l]) : (M - 1);
                cp_async16(&As[nxt][ar[l] * AP + ac4[l]],
                           A + (size_t)garow * K + k0n + ac4[l], apred[l]);
                cp_async16(&Bs[nxt][br[l] * BP + bc4[l]],
                           B + (size_t)(k0n + br[l]) * N + n0 + bc4[l], true);
            }
            CP_COMMIT();
            CP_WAIT1();
        } else {
            CP_WAIT0();
        }
        __syncthreads();

        const float* as = As[cur];
        const float* bs = Bs[cur];
        #pragma unroll
        for (int kk = 0; kk < 16; kk += 8) {
            uint32_t af[4][4];
            #pragma unroll
            for (int mt = 0; mt < 4; mt++) {
                int base = wm * 64 + mt * 16;
                af[mt][0] = ld_tf32(&as[(base + g)     * AP + kk + tig]);
                af[mt][1] = ld_tf32(&as[(base + g + 8) * AP + kk + tig]);
                af[mt][2] = ld_tf32(&as[(base + g)     * AP + kk + tig + 4]);
                af[mt][3] = ld_tf32(&as[(base + g + 8) * AP + kk + tig + 4]);
            }
            uint32_t bf[4][2];
            #pragma unroll
            for (int nt = 0; nt < 4; nt++) {
                int n = wn * 32 + nt * 8 + g;
                bf[nt][0] = ld_tf32(&bs[(kk + tig)     * BP + n]);
                bf[nt][1] = ld_tf32(&bs[(kk + tig + 4) * BP + n]);
            }
            #pragma unroll
            for (int mt = 0; mt < 4; mt++)
                #pragma unroll
                for (int nt = 0; nt < 4; nt++)
                    mma_m16n8k8(c[mt][nt], af[mt], bf[nt]);
        }
        __syncthreads();
    }

    #pragma unroll
    for (int mt = 0; mt < 4; mt++) {
        int row0 = m0 + wm * 64 + mt * 16 + g;
        #pragma unroll
        for (int nt = 0; nt < 4; nt++) {
            int col = n0 + wn * 32 + nt * 8 + 2 * tig;
            float b0 = 0.f, b1 = 0.f;
            if (BIAS) { b0 = bias[col]; b1 = bias[col + 1]; }
            if (row0 < M) {
                float2 o = make_float2(c[mt][nt][0] + b0, c[mt][nt][1] + b1);
                *(float2*)(C + (size_t)row0 * N + col) = o;
            }
            if (row0 + 8 < M) {
                float2 o = make_float2(c[mt][nt][2] + b0, c[mt][nt][3] + b1);
                *(float2*)(C + (size_t)(row0 + 8) * N + col) = o;
            }
        }
    }
}

// ============================================================================
// K2: gating (unchanged)
// ============================================================================
__global__ __launch_bounds__(256) void gate_kernel(
    const float* __restrict__ x, const float* __restrict__ tw,
    const float* __restrict__ tb, float* __restrict__ gate)
{
    int row = blockIdx.x * 8 + (threadIdx.x >> 5);
    if (row >= MROWS) return;
    int lane = threadIdx.x & 31;
    const float* xr = x + (size_t)row * CC;
    float s0 = 0.f, s1 = 0.f, s2 = 0.f, s3 = 0.f;
    for (int c = lane; c < CC; c += 32) {
        float xv = xr[c];
        float4 w = *(const float4*)(tw + c * 4);
        s0 += xv * w.x; s1 += xv * w.y; s2 += xv * w.z; s3 += xv * w.w;
    }
    s0 = warp_sum(s0); s1 = warp_sum(s1); s2 = warp_sum(s2); s3 = warp_sum(s3);
    float l0 = s0 + tb[0], l1 = s1 + tb[1], l2 = s2 + tb[2], l3 = s3 + tb[3];
    float m = fmaxf(fmaxf(l0, l1), fmaxf(l2, l3));
    float e0 = __expf(l0 - m), e1 = __expf(l1 - m);
    float e2 = __expf(l2 - m), e3 = __expf(l3 - m);
    float inv = 1.f / (e0 + e1 + e2 + e3);
    if (lane == 0) {
        float4 o = make_float4(e0 * inv, e1 * inv, e2 * inv, e3 * inv);
        *(float4*)(gate + (size_t)row * 4) = o;
    }
}

// ============================================================================
// K3: tensor-core attention, 512 threads (16 warps), one CTA per (b,h,n).
// Same math as R3: split-tf32 QK^T, fp32 nested-window softmax + gate fold,
// tf32 PV. Warp grid 4m x 4n over the 64x64 tile.
// ============================================================================
#define QP 68
#define KP 68
#define VP 72
#define PP 260
#define ATTN_SMEM_FLOATS (64*QP*2 + 64*KP*2 + 248*VP + 64*PP)
#define ATTN_SMEM_BYTES  (ATTN_SMEM_FLOATS * 4)

__global__ __launch_bounds__(512) void attn_tc_kernel(
    const float* __restrict__ qkv, const float* __restrict__ gate,
    float* __restrict__ eo)
{
    extern __shared__ float sm[];
    float* sQh = sm;                    // [64][QP]
    float* sQl = sQh + 64 * QP;
    float* sKh = sQl + 64 * QP;         // [64][KP]
    float* sKl = sKh + 64 * KP;
    float* sV  = sKl + 64 * KP;         // [248][VP] (tf32 values)
    float* sP  = sV + 248 * VP;         // [64][PP]

    const int tid  = threadIdx.x;
    const int warp = tid >> 5, lane = tid & 31;
    const int g    = lane >> 2, tig = lane & 3;
    const int wm   = warp & 3,  wn  = warp >> 2;   // 4m x 4n warp grid
    const int bid  = blockIdx.x;
    const int b = bid / (HH * NJ);
    const int h = (bid / NJ) % HH;
    const int n = bid % NJ;
    const float scale = 0.125f;

    // ---- load V once (tf32), zero-pad rows [243,248) ----
    for (int i = tid; i < 248 * 16; i += 512) {
        int s = i >> 4, c4 = (i & 15) * 4;
        uint4 vt = make_uint4(0u, 0u, 0u, 0u);
        if (s < TT) {
            const float* src = qkv + ((size_t)((b * TT + s) * NJ + n)) * NQKV + h * HD + 1024;
            float4 vv = *(const float4*)(src + c4);
            vt.x = f2tf32(vv.x); vt.y = f2tf32(vv.y);
            vt.z = f2tf32(vv.z); vt.w = f2tf32(vv.w);
        }
        *(uint4*)&sV[s * VP + c4] = vt;
    }

    for (int t0 = 0; t0 < TT; t0 += 64) {
        // ---- load Q tile, split hi/lo ----
        for (int i = tid; i < 64 * 16; i += 512) {
            int r = i >> 4, c4 = (i & 15) * 4;
            int t = t0 + r;
            float4 qv = (t < TT)
                ? *(const float4*)(qkv + ((size_t)((b * TT + t) * NJ + n)) * NQKV + h * HD + c4)
                : make_float4(0.f, 0.f, 0.f, 0.f);
            uint4 hi, lo;
            hi.x = f2tf32(qv.x); lo.x = f2tf32(qv.x - __uint_as_float(hi.x));
            hi.y = f2tf32(qv.y); lo.y = f2tf32(qv.y - __uint_as_float(hi.y));
            hi.z = f2tf32(qv.z); lo.z = f2tf32(qv.z - __uint_as_float(hi.z));
            hi.w = f2tf32(qv.w); lo.w = f2tf32(qv.w - __uint_as_float(hi.w));
            *(uint4*)&sQh[r * QP + c4] = hi;
            *(uint4*)&sQl[r * QP + c4] = lo;
        }

        // ---- S = Q K^T over 4 K-chunks of 64 ----
        for (int s0 = 0; s0 < 256; s0 += 64) {
            __syncthreads();
            for (int i = tid; i < 64 * 16; i += 512) {
                int sl = i >> 4, c4 = (i & 15) * 4;
                int s = s0 + sl;
                float4 kv = (s < TT)
                    ? *(const float4*)(qkv + ((size_t)((b * TT + s) * NJ + n)) * NQKV + h * HD + 512 + c4)
                    : make_float4(0.f, 0.f, 0.f, 0.f);
                uint4 hi, lo;
                hi.x = f2tf32(kv.x); lo.x = f2tf32(kv.x - __uint_as_float(hi.x));
                hi.y = f2tf32(kv.y); lo.y = f2tf32(kv.y - __uint_as_float(hi.y));
                hi.z = f2tf32(kv.z); lo.z = f2tf32(kv.z - __uint_as_float(hi.z));
                hi.w = f2tf32(kv.w); lo.w = f2tf32(kv.w - __uint_as_float(hi.w));
                *(uint4*)&sKh[sl * KP + c4] = hi;
                *(uint4*)&sKl[sl * KP + c4] = lo;
            }
            __syncthreads();

            float acc[2][4];
            #pragma unroll
            for (int j = 0; j < 2; j++)
                #pragma unroll
                for (int f = 0; f < 4; f++) acc[j][f] = 0.f;

            #pragma unroll
            for (int kk = 0; kk < 64; kk += 8) {
                uint32_t ah[4], al[4];
                int base = wm * 16;
                ah[0] = __float_as_uint(sQh[(base + g)     * QP + kk + tig]);
                ah[1] = __float_as_uint(sQh[(base + g + 8) * QP + kk + tig]);
                ah[2] = __float_as_uint(sQh[(base + g)     * QP + kk + tig + 4]);
                ah[3] = __float_as_uint(sQh[(base + g + 8) * QP + kk + tig + 4]);
                al[0] = __float_as_uint(sQl[(base + g)     * QP + kk + tig]);
                al[1] = __float_as_uint(sQl[(base + g + 8) * QP + kk + tig]);
                al[2] = __float_as_uint(sQl[(base + g)     * QP + kk + tig + 4]);
                al[3] = __float_as_uint(sQl[(base + g + 8) * QP + kk + tig + 4]);
                uint32_t bh[2][2], bl[2][2];
                #pragma unroll
                for (int nt = 0; nt < 2; nt++) {
                    int nl = wn * 16 + nt * 8 + g;
                    bh[nt][0] = __float_as_uint(sKh[nl * KP + kk + tig]);
                    bh[nt][1] = __float_as_uint(sKh[nl * KP + kk + tig + 4]);
                    bl[nt][0] = __float_as_uint(sKl[nl * KP + kk + tig]);
                    bl[nt][1] = __float_as_uint(sKl[nl * KP + kk + tig + 4]);
                }
                #pragma unroll
                for (int nt = 0; nt < 2; nt++) {
                    mma_m16n8k8(acc[nt], ah, bh[nt]);
                    mma_m16n8k8(acc[nt], ah, bl[nt]);
                    mma_m16n8k8(acc[nt], al, bh[nt]);
                }
            }

            int row = wm * 16 + g;
            #pragma unroll
            for (int nt = 0; nt < 2; nt++) {
                int col = s0 + wn * 16 + nt * 8 + 2 * tig;
                *(float2*)&sP[row * PP + col] =
                    make_float2(acc[nt][0] * scale, acc[nt][1] * scale);
                *(float2*)&sP[(row + 8) * PP + col] =
                    make_float2(acc[nt][2] * scale, acc[nt][3] * scale);
            }
        }
        __syncthreads();

        // ---- nested-window softmax + gate folding; write back tf32 ----
        for (int rr = 0; rr < 4; rr++) {
            int r = warp * 4 + rr;
            int t = t0 + r;
            if (t >= TT) break;
            float p[8];
            float m = -1e30f;
            #pragma unroll
            for (int i2 = 0; i2 < 8; i2++) {
                int s = lane + 32 * i2;
                float v = (s < TT) ? sP[r * PP + s] : -1e30f;
                p[i2] = v;
                m = fmaxf(m, v);
            }
            m = warp_max(m);
            int a9 = (t / 9) * 9, a27 = (t / 27) * 27, a81 = (t / 81) * 81;
            float z9 = 0.f, z27 = 0.f, z81 = 0.f, z243 = 0.f;
            #pragma unroll
            for (int i2 = 0; i2 < 8; i2++) {
                int s = lane + 32 * i2;
                float e = (s < TT) ? __expf(p[i2] - m) : 0.f;
                p[i2] = e;
                z243 += e;
                if (s >= a81 && s < a81 + 81) z81 += e;
                if (s >= a27 && s < a27 + 27) z27 += e;
                if (s >= a9  && s < a9  + 9)  z9  += e;
            }
            z9 = warp_sum(z9); z27 = warp_sum(z27);
            z81 = warp_sum(z81); z243 = warp_sum(z243);
            const float* gr = gate + ((size_t)((b * TT + t) * NJ + n)) * 4;
            float w9 = gr[0] / z9, w27 = gr[1] / z27;
            float w81 = gr[2] / z81, w243 = gr[3] / z243;
            #pragma unroll
            for (int i2 = 0; i2 < 8; i2++) {
                int s = lane + 32 * i2;
                if (s < 248) {
                    float val = 0.f;
                    if (s < TT) {
                        float cf = w243;
                        if (s >= a81 && s < a81 + 81) cf += w81;
                        if (s >= a27 && s < a27 + 27) cf += w27;
                        if (s >= a9  && s < a9  + 9)  cf += w9;
                        val = __uint_as_float(f2tf32(p[i2] * cf));
                    }
                    sP[r * PP + s] = val;
                }
            }
        }
        __syncthreads();

        // ---- O = P V  (plain tf32 mma), k over 248 ----
        {
            float acc2[2][4];
            #pragma unroll
            for (int j = 0; j < 2; j++)
                #pragma unroll
                for (int f = 0; f < 4; f++) acc2[j][f] = 0.f;

            for (int kk = 0; kk < 248; kk += 8) {
                uint32_t af[4];
                int base = wm * 16;
                af[0] = __float_as_uint(sP[(base + g)     * PP + kk + tig]);
                af[1] = __float_as_uint(sP[(base + g + 8) * PP + kk + tig]);
                af[2] = __float_as_uint(sP[(base + g)     * PP + kk + tig + 4]);
                af[3] = __float_as_uint(sP[(base + g + 8) * PP + kk + tig + 4]);
                uint32_t bf[2][2];
                #pragma unroll
                for (int nt = 0; nt < 2; nt++) {
                    int nc = wn * 16 + nt * 8 + g;
                    bf[nt][0] = __float_as_uint(sV[(kk + tig)     * VP + nc]);
                    bf[nt][1] = __float_as_uint(sV[(kk + tig + 4) * VP + nc]);
                }
                #pragma unroll
                for (int nt = 0; nt < 2; nt++)
                    mma_m16n8k8(acc2[nt], af, bf[nt]);
            }

            int row = wm * 16 + g;
            #pragma unroll
            for (int nt = 0; nt < 2; nt++) {
                int col = wn * 16 + nt * 8 + 2 * tig;
                int t = t0 + row;
                if (t < TT) {
                    *(float2*)(eo + ((size_t)((b * TT + t) * NJ + n)) * CC + h * HD + col) =
                        make_float2(acc2[nt][0], acc2[nt][1]);
                }
                if (t + 8 < TT) {
                    *(float2*)(eo + ((size_t)((b * TT + t + 8) * NJ + n)) * CC + h * HD + col) =
                        make_float2(acc2[nt][2], acc2[nt][3]);
                }
            }
        }
        __syncthreads();
    }
}

// ============================================================================
extern "C" void kernel_launch(void* const* d_in, const int* in_sizes, int n_in,
                              void* d_out, int out_size)
{
    const float* x      = (const float*)d_in[0];
    const float* qkv_w  = (const float*)d_in[1];
    const float* proj_w = (const float*)d_in[2];
    const float* proj_b = (const float*)d_in[3];
    const float* te_w   = (const float*)d_in[4];
    const float* te_b   = (const float*)d_in[5];
    float* out = (float*)d_out;

    float *qkv_p, *gate_p, *eo_p;
    cudaGetSymbolAddress((void**)&qkv_p,  g_qkv);
    cudaGetSymbolAddress((void**)&gate_p, g_gate);
    cudaGetSymbolAddress((void**)&eo_p,   g_eo);

    cudaFuncSetAttribute(attn_tc_kernel, cudaFuncAttributeMaxDynamicSharedMemorySize,
                         ATTN_SMEM_BYTES);

    // K1: qkv = x @ qkv_w   (16524 x 1536 x 512)  — tf32 TC + cp.async pipeline
    gemm_tf32<false><<<dim3(NQKV / 128, (MROWS + 127) / 128), 256>>>(
        x, qkv_w, nullptr, qkv_p, MROWS, NQKV, CC);

    // K2: gate = softmax(x @ te_w + te_b)
    gate_kernel<<<(MROWS + 7) / 8, 256>>>(x, te_w, te_b, gate_p);

    // K3: tensor-core multi-window attention + expert recombination (512 thr)
    attn_tc_kernel<<<BB * HH * NJ, 512, ATTN_SMEM_BYTES>>>(qkv_p, gate_p, eo_p);

    // K4: out = eo @ proj_w + proj_b   (16524 x 512 x 512) — tf32 TC pipeline
    gemm_tf32<true><<<dim3(CC / 128, (MROWS + 127) / 128), 256>>>(
        eo_p, proj_w, proj_b, out, MROWS, CC, CC);
}

// round 7
// speedup vs baseline: 1.2544x; 1.2544x over previous
#include <cuda_runtime.h>
#include <cstdint>
#include <cstddef>

#define TT    243
#define NJ    17
#define BB    4
#define HH    8
#define HD    64
#define CC    512
#define EE    4
#define MROWS (BB*TT*NJ)   // 16524
#define NQKV  1536

// ---- scratch (static device globals; no allocations allowed) ----
__device__ float g_qkv[(size_t)MROWS * NQKV];   // ~101.5 MB (fp32)
__device__ float g_gate[(size_t)MROWS * EE];
__device__ float g_eo[(size_t)MROWS * CC];      // ~33.8 MB (tf32-valued)
__device__ float g_xtf[(size_t)MROWS * CC];     // x rounded to tf32
__device__ float g_w1[(size_t)CC * NQKV];       // qkv_w rounded to tf32
__device__ float g_w2[(size_t)CC * CC];         // proj_w rounded to tf32

static __device__ __forceinline__ float warp_sum(float v) {
    #pragma unroll
    for (int o = 16; o; o >>= 1) v += __shfl_xor_sync(0xffffffffu, v, o);
    return v;
}
static __device__ __forceinline__ float warp_max(float v) {
    #pragma unroll
    for (int o = 16; o; o >>= 1) v = fmaxf(v, __shfl_xor_sync(0xffffffffu, v, o));
    return v;
}

static __device__ __forceinline__ uint32_t f2tf32(float x) {
    uint32_t r;
    asm("cvt.rna.tf32.f32 %0, %1;" : "=r"(r) : "f"(x));
    return r;
}

static __device__ __forceinline__ void mma_m16n8k8(
    float* c, const uint32_t* a, const uint32_t* b)
{
    asm volatile(
        "mma.sync.aligned.m16n8k8.row.col.f32.tf32.tf32.f32 "
        "{%0,%1,%2,%3}, {%4,%5,%6,%7}, {%8,%9}, {%0,%1,%2,%3};\n"
        : "+f"(c[0]), "+f"(c[1]), "+f"(c[2]), "+f"(c[3])
        : "r"(a[0]), "r"(a[1]), "r"(a[2]), "r"(a[3]),
          "r"(b[0]), "r"(b[1]));
}

static __device__ __forceinline__ void cp_async16(float* dst_smem, const float* src, bool pred) {
    uint32_t daddr = (uint32_t)__cvta_generic_to_shared(dst_smem);
    int sz = pred ? 16 : 0;
    asm volatile("cp.async.cg.shared.global [%0], [%1], 16, %2;\n"
                 :: "r"(daddr), "l"(src), "r"(sz));
}
#define CP_COMMIT() asm volatile("cp.async.commit_group;\n" ::: "memory")
#define CP_WAIT0()  asm volatile("cp.async.wait_group 0;\n" ::: "memory")
#define CP_WAIT1()  asm volatile("cp.async.wait_group 1;\n" ::: "memory")

// ============================================================================
// K0: elementwise tf32 rounding pre-pass (float4 grid-stride)
// ============================================================================
__global__ __launch_bounds__(256) void cvt_tf32_kernel(
    const float* __restrict__ src, float* __restrict__ dst, int n4)
{
    int i = blockIdx.x * 256 + threadIdx.x;
    int stride = gridDim.x * 256;
    for (; i < n4; i += stride) {
        float4 v = ((const float4*)src)[i];
        uint4 o;
        o.x = f2tf32(v.x); o.y = f2tf32(v.y);
        o.z = f2tf32(v.z); o.w = f2tf32(v.w);
        ((uint4*)dst)[i] = o;
    }
}

// ============================================================================
// K1/K4: tf32 tensor-core GEMM, cp.async double-buffered.
// Inputs are ALREADY tf32-valued fp32 => inner loop is pure LDS + MMA.
// BM=BN=128, BK=16, 256 threads, 8 warps (2m x 4n), warptile 64x32.
// ============================================================================
#define AP 20
#define BP 136

template <bool BIAS>
__global__ __launch_bounds__(256) void gemm_tf32(
    const float* __restrict__ A, const float* __restrict__ B,
    const float* __restrict__ bias, float* __restrict__ C,
    int M, int N, int K)
{
    __shared__ float As[2][128 * AP];
    __shared__ float Bs[2][16 * BP];

    const int tid  = threadIdx.x;
    const int warp = tid >> 5, lane = tid & 31;
    const int g    = lane >> 2, tig = lane & 3;
    const int wm   = warp & 1,  wn  = warp >> 1;
    const int m0   = blockIdx.y * 128, n0 = blockIdx.x * 128;

    int ar[2], ac4[2], br[2], bc4[2];
    bool apred[2];
    #pragma unroll
    for (int l = 0; l < 2; l++) {
        int li = tid + l * 256;
        ar[l] = li >> 2; ac4[l] = (li & 3) * 4;
        apred[l] = (m0 + ar[l]) < M;
        br[l] = li >> 5; bc4[l] = (li & 31) * 4;
    }

    float c[4][4][4];
    #pragma unroll
    for (int i = 0; i < 4; i++)
        #pragma unroll
        for (int j = 0; j < 4; j++)
            #pragma unroll
            for (int f = 0; f < 4; f++) c[i][j][f] = 0.f;

    const int niter = K / 16;

    #pragma unroll
    for (int l = 0; l < 2; l++) {
        int garow = apred[l] ? (m0 + ar[l]) : (M - 1);
        cp_async16(&As[0][ar[l] * AP + ac4[l]], A + (size_t)garow * K + ac4[l], apred[l]);
        cp_async16(&Bs[0][br[l] * BP + bc4[l]], B + (size_t)br[l] * N + n0 + bc4[l], true);
    }
    CP_COMMIT();

    for (int it = 0; it < niter; it++) {
        int cur = it & 1, nxt = cur ^ 1;
        if (it + 1 < niter) {
            int k0n = (it + 1) * 16;
            #pragma unroll
            for (int l = 0; l < 2; l++) {
                int garow = apred[l] ? (m0 + ar[l]) : (M - 1);
                cp_async16(&As[nxt][ar[l] * AP + ac4[l]],
                           A + (size_t)garow * K + k0n + ac4[l], apred[l]);
                cp_async16(&Bs[nxt][br[l] * BP + bc4[l]],
                           B + (size_t)(k0n + br[l]) * N + n0 + bc4[l], true);
            }
            CP_COMMIT();
            CP_WAIT1();
        } else {
            CP_WAIT0();
        }
        __syncthreads();

        const float* as = As[cur];
        const float* bs = Bs[cur];
        #pragma unroll
        for (int kk = 0; kk < 16; kk += 8) {
            uint32_t af[4][4];
            #pragma unroll
            for (int mt = 0; mt < 4; mt++) {
                int base = wm * 64 + mt * 16;
                af[mt][0] = __float_as_uint(as[(base + g)     * AP + kk + tig]);
                af[mt][1] = __float_as_uint(as[(base + g + 8) * AP + kk + tig]);
                af[mt][2] = __float_as_uint(as[(base + g)     * AP + kk + tig + 4]);
                af[mt][3] = __float_as_uint(as[(base + g + 8) * AP + kk + tig + 4]);
            }
            uint32_t bf[4][2];
            #pragma unroll
            for (int nt = 0; nt < 4; nt++) {
                int n = wn * 32 + nt * 8 + g;
                bf[nt][0] = __float_as_uint(bs[(kk + tig)     * BP + n]);
                bf[nt][1] = __float_as_uint(bs[(kk + tig + 4) * BP + n]);
            }
            #pragma unroll
            for (int mt = 0; mt < 4; mt++)
                #pragma unroll
                for (int nt = 0; nt < 4; nt++)
                    mma_m16n8k8(c[mt][nt], af[mt], bf[nt]);
        }
        __syncthreads();
    }

    #pragma unroll
    for (int mt = 0; mt < 4; mt++) {
        int row0 = m0 + wm * 64 + mt * 16 + g;
        #pragma unroll
        for (int nt = 0; nt < 4; nt++) {
            int col = n0 + wn * 32 + nt * 8 + 2 * tig;
            float b0 = 0.f, b1 = 0.f;
            if (BIAS) { b0 = bias[col]; b1 = bias[col + 1]; }
            if (row0 < M) {
                float2 o = make_float2(c[mt][nt][0] + b0, c[mt][nt][1] + b1);
                *(float2*)(C + (size_t)row0 * N + col) = o;
            }
            if (row0 + 8 < M) {
                float2 o = make_float2(c[mt][nt][2] + b0, c[mt][nt][3] + b1);
                *(float2*)(C + (size_t)(row0 + 8) * N + col) = o;
            }
        }
    }
}

// ============================================================================
// K2: gating (unchanged; reads original fp32 x)
// ============================================================================
__global__ __launch_bounds__(256) void gate_kernel(
    const float* __restrict__ x, const float* __restrict__ tw,
    const float* __restrict__ tb, float* __restrict__ gate)
{
    int row = blockIdx.x * 8 + (threadIdx.x >> 5);
    if (row >= MROWS) return;
    int lane = threadIdx.x & 31;
    const float* xr = x + (size_t)row * CC;
    float s0 = 0.f, s1 = 0.f, s2 = 0.f, s3 = 0.f;
    for (int c = lane; c < CC; c += 32) {
        float xv = xr[c];
        float4 w = *(const float4*)(tw + c * 4);
        s0 += xv * w.x; s1 += xv * w.y; s2 += xv * w.z; s3 += xv * w.w;
    }
    s0 = warp_sum(s0); s1 = warp_sum(s1); s2 = warp_sum(s2); s3 = warp_sum(s3);
    float l0 = s0 + tb[0], l1 = s1 + tb[1], l2 = s2 + tb[2], l3 = s3 + tb[3];
    float m = fmaxf(fmaxf(l0, l1), fmaxf(l2, l3));
    float e0 = __expf(l0 - m), e1 = __expf(l1 - m);
    float e2 = __expf(l2 - m), e3 = __expf(l3 - m);
    float inv = 1.f / (e0 + e1 + e2 + e3);
    if (lane == 0) {
        float4 o = make_float4(e0 * inv, e1 * inv, e2 * inv, e3 * inv);
        *(float4*)(gate + (size_t)row * 4) = o;
    }
}

// ============================================================================
// K3: tensor-core attention, 256 threads (reverted to R3 shape: 2m x 4n).
// Split-tf32 QK^T, fp32 nested-window softmax + gate fold, tf32 PV.
// eo is written tf32-rounded so K4 consumes it without conversion.
// ============================================================================
#define QP 68
#define KP 68
#define VP 72
#define PP 260
#define ATTN_SMEM_FLOATS (64*QP*2 + 64*KP*2 + 248*VP + 64*PP)
#define ATTN_SMEM_BYTES  (ATTN_SMEM_FLOATS * 4)

__global__ __launch_bounds__(256) void attn_tc_kernel(
    const float* __restrict__ qkv, const float* __restrict__ gate,
    float* __restrict__ eo)
{
    extern __shared__ float sm[];
    float* sQh = sm;                    // [64][QP]
    float* sQl = sQh + 64 * QP;
    float* sKh = sQl + 64 * QP;         // [64][KP]
    float* sKl = sKh + 64 * KP;
    float* sV  = sKl + 64 * KP;         // [248][VP] (tf32 values)
    float* sP  = sV + 248 * VP;         // [64][PP]

    const int tid  = threadIdx.x;
    const int warp = tid >> 5, lane = tid & 31;
    const int g    = lane >> 2, tig = lane & 3;
    const int wm   = warp & 1,  wn  = warp >> 1;   // 2m x 4n warp grid
    const int bid  = blockIdx.x;
    const int b = bid / (HH * NJ);
    const int h = (bid / NJ) % HH;
    const int n = bid % NJ;
    const float scale = 0.125f;

    // ---- load V once (tf32), zero-pad rows [243,248) ----
    for (int i = tid; i < 248 * 16; i += 256) {
        int s = i >> 4, c4 = (i & 15) * 4;
        uint4 vt = make_uint4(0u, 0u, 0u, 0u);
        if (s < TT) {
            const float* src = qkv + ((size_t)((b * TT + s) * NJ + n)) * NQKV + h * HD + 1024;
            float4 vv = *(const float4*)(src + c4);
            vt.x = f2tf32(vv.x); vt.y = f2tf32(vv.y);
            vt.z = f2tf32(vv.z); vt.w = f2tf32(vv.w);
        }
        *(uint4*)&sV[s * VP + c4] = vt;
    }

    for (int t0 = 0; t0 < TT; t0 += 64) {
        // ---- load Q tile, split hi/lo ----
        for (int i = tid; i < 64 * 16; i += 256) {
            int r = i >> 4, c4 = (i & 15) * 4;
            int t = t0 + r;
            float4 qv = (t < TT)
                ? *(const float4*)(qkv + ((size_t)((b * TT + t) * NJ + n)) * NQKV + h * HD + c4)
                : make_float4(0.f, 0.f, 0.f, 0.f);
            uint4 hi, lo;
            hi.x = f2tf32(qv.x); lo.x = f2tf32(qv.x - __uint_as_float(hi.x));
            hi.y = f2tf32(qv.y); lo.y = f2tf32(qv.y - __uint_as_float(hi.y));
            hi.z = f2tf32(qv.z); lo.z = f2tf32(qv.z - __uint_as_float(hi.z));
            hi.w = f2tf32(qv.w); lo.w = f2tf32(qv.w - __uint_as_float(hi.w));
            *(uint4*)&sQh[r * QP + c4] = hi;
            *(uint4*)&sQl[r * QP + c4] = lo;
        }

        // ---- S = Q K^T over 4 K-chunks of 64 ----
        for (int s0 = 0; s0 < 256; s0 += 64) {
            __syncthreads();
            for (int i = tid; i < 64 * 16; i += 256) {
                int sl = i >> 4, c4 = (i & 15) * 4;
                int s = s0 + sl;
                float4 kv = (s < TT)
                    ? *(const float4*)(qkv + ((size_t)((b * TT + s) * NJ + n)) * NQKV + h * HD + 512 + c4)
                    : make_float4(0.f, 0.f, 0.f, 0.f);
                uint4 hi, lo;
                hi.x = f2tf32(kv.x); lo.x = f2tf32(kv.x - __uint_as_float(hi.x));
                hi.y = f2tf32(kv.y); lo.y = f2tf32(kv.y - __uint_as_float(hi.y));
                hi.z = f2tf32(kv.z); lo.z = f2tf32(kv.z - __uint_as_float(hi.z));
                hi.w = f2tf32(kv.w); lo.w = f2tf32(kv.w - __uint_as_float(hi.w));
                *(uint4*)&sKh[sl * KP + c4] = hi;
                *(uint4*)&sKl[sl * KP + c4] = lo;
            }
            __syncthreads();

            float acc[2][2][4];
            #pragma unroll
            for (int i = 0; i < 2; i++)
                #pragma unroll
                for (int j = 0; j < 2; j++)
                    #pragma unroll
                    for (int f = 0; f < 4; f++) acc[i][j][f] = 0.f;

            #pragma unroll
            for (int kk = 0; kk < 64; kk += 8) {
                uint32_t ah[2][4], al[2][4];
                #pragma unroll
                for (int mt = 0; mt < 2; mt++) {
                    int base = wm * 32 + mt * 16;
                    ah[mt][0] = __float_as_uint(sQh[(base + g)     * QP + kk + tig]);
                    ah[mt][1] = __float_as_uint(sQh[(base + g + 8) * QP + kk + tig]);
                    ah[mt][2] = __float_as_uint(sQh[(base + g)     * QP + kk + tig + 4]);
                    ah[mt][3] = __float_as_uint(sQh[(base + g + 8) * QP + kk + tig + 4]);
                    al[mt][0] = __float_as_uint(sQl[(base + g)     * QP + kk + tig]);
                    al[mt][1] = __float_as_uint(sQl[(base + g + 8) * QP + kk + tig]);
                    al[mt][2] = __float_as_uint(sQl[(base + g)     * QP + kk + tig + 4]);
                    al[mt][3] = __float_as_uint(sQl[(base + g + 8) * QP + kk + tig + 4]);
                }
                uint32_t bh[2][2], bl[2][2];
                #pragma unroll
                for (int nt = 0; nt < 2; nt++) {
                    int nl = wn * 16 + nt * 8 + g;
                    bh[nt][0] = __float_as_uint(sKh[nl * KP + kk + tig]);
                    bh[nt][1] = __float_as_uint(sKh[nl * KP + kk + tig + 4]);
                    bl[nt][0] = __float_as_uint(sKl[nl * KP + kk + tig]);
                    bl[nt][1] = __float_as_uint(sKl[nl * KP + kk + tig + 4]);
                }
                #pragma unroll
                for (int mt = 0; mt < 2; mt++)
                    #pragma unroll
                    for (int nt = 0; nt < 2; nt++) {
                        mma_m16n8k8(acc[mt][nt], ah[mt], bh[nt]);
                        mma_m16n8k8(acc[mt][nt], ah[mt], bl[nt]);
                        mma_m16n8k8(acc[mt][nt], al[mt], bh[nt]);
                    }
            }

            #pragma unroll
            for (int mt = 0; mt < 2; mt++) {
                int row = wm * 32 + mt * 16 + g;
                #pragma unroll
                for (int nt = 0; nt < 2; nt++) {
                    int col = s0 + wn * 16 + nt * 8 + 2 * tig;
                    *(float2*)&sP[row * PP + col] =
                        make_float2(acc[mt][nt][0] * scale, acc[mt][nt][1] * scale);
                    *(float2*)&sP[(row + 8) * PP + col] =
                        make_float2(acc[mt][nt][2] * scale, acc[mt][nt][3] * scale);
                }
            }
        }
        __syncthreads();

        // ---- nested-window softmax + gate folding; write back tf32 ----
        for (int rr = 0; rr < 8; rr++) {
            int r = warp * 8 + rr;
            int t = t0 + r;
            if (t >= TT) break;
            float p[8];
            float m = -1e30f;
            #pragma unroll
            for (int i2 = 0; i2 < 8; i2++) {
                int s = lane + 32 * i2;
                float v = (s < TT) ? sP[r * PP + s] : -1e30f;
                p[i2] = v;
                m = fmaxf(m, v);
            }
            m = warp_max(m);
            int a9 = (t / 9) * 9, a27 = (t / 27) * 27, a81 = (t / 81) * 81;
            float z9 = 0.f, z27 = 0.f, z81 = 0.f, z243 = 0.f;
            #pragma unroll
            for (int i2 = 0; i2 < 8; i2++) {
                int s = lane + 32 * i2;
                float e = (s < TT) ? __expf(p[i2] - m) : 0.f;
                p[i2] = e;
                z243 += e;
                if (s >= a81 && s < a81 + 81) z81 += e;
                if (s >= a27 && s < a27 + 27) z27 += e;
                if (s >= a9  && s < a9  + 9)  z9  += e;
            }
            z9 = warp_sum(z9); z27 = warp_sum(z27);
            z81 = warp_sum(z81); z243 = warp_sum(z243);
            const float* gr = gate + ((size_t)((b * TT + t) * NJ + n)) * 4;
            float w9 = gr[0] / z9, w27 = gr[1] / z27;
            float w81 = gr[2] / z81, w243 = gr[3] / z243;
            #pragma unroll
            for (int i2 = 0; i2 < 8; i2++) {
                int s = lane + 32 * i2;
                if (s < 248) {
                    float val = 0.f;
                    if (s < TT) {
                        float cf = w243;
                        if (s >= a81 && s < a81 + 81) cf += w81;
                        if (s >= a27 && s < a27 + 27) cf += w27;
                        if (s >= a9  && s < a9  + 9)  cf += w9;
                        val = __uint_as_float(f2tf32(p[i2] * cf));
                    }
                    sP[r * PP + s] = val;
                }
            }
        }
        __syncthreads();

        // ---- O = P V  (plain tf32 mma), k over 248 ----
        {
            float acc2[2][2][4];
            #pragma unroll
            for (int i = 0; i < 2; i++)
                #pragma unroll
                for (int j = 0; j < 2; j++)
                    #pragma unroll
                    for (int f = 0; f < 4; f++) acc2[i][j][f] = 0.f;

            for (int kk = 0; kk < 248; kk += 8) {
                uint32_t af[2][4];
                #pragma unroll
                for (int mt = 0; mt < 2; mt++) {
                    int base = wm * 32 + mt * 16;
                    af[mt][0] = __float_as_uint(sP[(base + g)     * PP + kk + tig]);
                    af[mt][1] = __float_as_uint(sP[(base + g + 8) * PP + kk + tig]);
                    af[mt][2] = __float_as_uint(sP[(base + g)     * PP + kk + tig + 4]);
                    af[mt][3] = __float_as_uint(sP[(base + g + 8) * PP + kk + tig + 4]);
                }
                uint32_t bf[2][2];
                #pragma unroll
                for (int nt = 0; nt < 2; nt++) {
                    int nc = wn * 16 + nt * 8 + g;
                    bf[nt][0] = __float_as_uint(sV[(kk + tig)     * VP + nc]);
                    bf[nt][1] = __float_as_uint(sV[(kk + tig + 4) * VP + nc]);
                }
                #pragma unroll
                for (int mt = 0; mt < 2; mt++)
                    #pragma unroll
                    for (int nt = 0; nt < 2; nt++)
                        mma_m16n8k8(acc2[mt][nt], af[mt], bf[nt]);
            }

            #pragma unroll
            for (int mt = 0; mt < 2; mt++) {
                int row = wm * 32 + mt * 16 + g;
                #pragma unroll
                for (int nt = 0; nt < 2; nt++) {
                    int col = wn * 16 + nt * 8 + 2 * tig;
                    int t = t0 + row;
                    if (t < TT) {
                        *(float2*)(eo + ((size_t)((b * TT + t) * NJ + n)) * CC + h * HD + col) =
                            make_float2(__uint_as_float(f2tf32(acc2[mt][nt][0])),
                                        __uint_as_float(f2tf32(acc2[mt][nt][1])));
                    }
                    if (t + 8 < TT) {
                        *(float2*)(eo + ((size_t)((b * TT + t + 8) * NJ + n)) * CC + h * HD + col) =
                            make_float2(__uint_as_float(f2tf32(acc2[mt][nt][2])),
                                        __uint_as_float(f2tf32(acc2[mt][nt][3])));
                    }
                }
            }
        }
        __syncthreads();
    }
}

// ============================================================================
extern "C" void kernel_launch(void* const* d_in, const int* in_sizes, int n_in,
                              void* d_out, int out_size)
{
    const float* x      = (const float*)d_in[0];
    const float* qkv_w  = (const float*)d_in[1];
    const float* proj_w = (const float*)d_in[2];
    const float* proj_b = (const float*)d_in[3];
    const float* te_w   = (const float*)d_in[4];
    const float* te_b   = (const float*)d_in[5];
    float* out = (float*)d_out;

    float *qkv_p, *gate_p, *eo_p, *xtf_p, *w1_p, *w2_p;
    cudaGetSymbolAddress((void**)&qkv_p,  g_qkv);
    cudaGetSymbolAddress((void**)&gate_p, g_gate);
    cudaGetSymbolAddress((void**)&eo_p,   g_eo);
    cudaGetSymbolAddress((void**)&xtf_p,  g_xtf);
    cudaGetSymbolAddress((void**)&w1_p,   g_w1);
    cudaGetSymbolAddress((void**)&w2_p,   g_w2);

    cudaFuncSetAttribute(attn_tc_kernel, cudaFuncAttributeMaxDynamicSharedMemorySize,
                         ATTN_SMEM_BYTES);

    // K0: round x, qkv_w, proj_w to tf32 once
    cvt_tf32_kernel<<<592, 256>>>(x, xtf_p, MROWS * CC / 4);
    cvt_tf32_kernel<<<148, 256>>>(qkv_w, w1_p, CC * NQKV / 4);
    cvt_tf32_kernel<<<148, 256>>>(proj_w, w2_p, CC * CC / 4);

    // K1: qkv = x @ qkv_w   — tf32 TC + cp.async pipeline (no in-loop cvt)
    gemm_tf32<false><<<dim3(NQKV / 128, (MROWS + 127) / 128), 256>>>(
        xtf_p, w1_p, nullptr, qkv_p, MROWS, NQKV, CC);

    // K2: gate = softmax(x @ te_w + te_b)
    gate_kernel<<<(MROWS + 7) / 8, 256>>>(x, te_w, te_b, gate_p);

    // K3: tensor-core multi-window attention + expert recombination
    attn_tc_kernel<<<BB * HH * NJ, 256, ATTN_SMEM_BYTES>>>(qkv_p, gate_p, eo_p);

    // K4: out = eo @ proj_w + proj_b   — eo already tf32-valued
    gemm_tf32<true><<<dim3(CC / 128, (MROWS + 127) / 128), 256>>>(
        eo_p, w2_p, proj_b, out, MROWS, CC, CC);
}

// round 9
// speedup vs baseline: 1.5523x; 1.2375x over previous
#include <cuda_runtime.h>
#include <cstdint>
#include <cstddef>

#define TT    243
#define NJ    17
#define BB    4
#define HH    8
#define HD    64
#define CC    512
#define EE    4
#define MROWS (BB*TT*NJ)   // 16524
#define NQKV  1536

// ---- scratch (static device globals; no allocations allowed) ----
__device__ float g_qkv[(size_t)MROWS * NQKV];    // q/k: hi(tf32) ; v: tf32-valued
__device__ float g_qkvlo[(size_t)MROWS * 1024];  // q/k lo residuals (tf32-valued)
__device__ float g_gate[(size_t)MROWS * EE];
__device__ float g_eo[(size_t)MROWS * CC];       // tf32-valued
__device__ float g_xtf[(size_t)MROWS * CC];
__device__ float g_w1[(size_t)CC * NQKV];
__device__ float g_w2[(size_t)CC * CC];

static __device__ __forceinline__ float warp_sum(float v) {
    #pragma unroll
    for (int o = 16; o; o >>= 1) v += __shfl_xor_sync(0xffffffffu, v, o);
    return v;
}
static __device__ __forceinline__ float warp_max(float v) {
    #pragma unroll
    for (int o = 16; o; o >>= 1) v = fmaxf(v, __shfl_xor_sync(0xffffffffu, v, o));
    return v;
}

static __device__ __forceinline__ uint32_t f2tf32(float x) {
    uint32_t r;
    asm("cvt.rna.tf32.f32 %0, %1;" : "=r"(r) : "f"(x));
    return r;
}

static __device__ __forceinline__ void mma_m16n8k8(
    float* c, const uint32_t* a, const uint32_t* b)
{
    asm volatile(
        "mma.sync.aligned.m16n8k8.row.col.f32.tf32.tf32.f32 "
        "{%0,%1,%2,%3}, {%4,%5,%6,%7}, {%8,%9}, {%0,%1,%2,%3};\n"
        : "+f"(c[0]), "+f"(c[1]), "+f"(c[2]), "+f"(c[3])
        : "r"(a[0]), "r"(a[1]), "r"(a[2]), "r"(a[3]),
          "r"(b[0]), "r"(b[1]));
}

static __device__ __forceinline__ void cp_async16(float* dst_smem, const float* src, bool pred) {
    uint32_t daddr = (uint32_t)__cvta_generic_to_shared(dst_smem);
    int sz = pred ? 16 : 0;
    asm volatile("cp.async.cg.shared.global [%0], [%1], 16, %2;\n"
                 :: "r"(daddr), "l"(src), "r"(sz));
}
#define CP_COMMIT() asm volatile("cp.async.commit_group;\n" ::: "memory")
#define CP_WAIT0()  asm volatile("cp.async.wait_group 0;\n" ::: "memory")
#define CP_WAIT1()  asm volatile("cp.async.wait_group 1;\n" ::: "memory")

// ============================================================================
// K0: elementwise tf32 rounding pre-pass
// ============================================================================
__global__ __launch_bounds__(256) void cvt_tf32_kernel(
    const float* __restrict__ src, float* __restrict__ dst, int n4)
{
    int i = blockIdx.x * 256 + threadIdx.x;
    int stride = gridDim.x * 256;
    for (; i < n4; i += stride) {
        float4 v = ((const float4*)src)[i];
        uint4 o;
        o.x = f2tf32(v.x); o.y = f2tf32(v.y);
        o.z = f2tf32(v.z); o.w = f2tf32(v.w);
        ((uint4*)dst)[i] = o;
    }
}

// ============================================================================
// K1/K4: tf32 tensor-core GEMM, cp.async double-buffered; pure LDS+MMA loop.
// SPLIT (K1): q/k cols (<1024) -> hi to C + lo residual to C2 (pitch 1024);
//             v cols -> tf32-rounded to C.   K4: plain fp32 + bias.
// ============================================================================
#define AP 20
#define BP 136

template <bool BIAS, bool SPLIT>
__global__ __launch_bounds__(256) void gemm_tf32(
    const float* __restrict__ A, const float* __restrict__ B,
    const float* __restrict__ bias, float* __restrict__ C,
    float* __restrict__ C2, int M, int N, int K)
{
    __shared__ float As[2][128 * AP];
    __shared__ float Bs[2][16 * BP];

    const int tid  = threadIdx.x;
    const int warp = tid >> 5, lane = tid & 31;
    const int g    = lane >> 2, tig = lane & 3;
    const int wm   = warp & 1,  wn  = warp >> 1;
    const int m0   = blockIdx.y * 128, n0 = blockIdx.x * 128;

    int ar[2], ac4[2], br[2], bc4[2];
    bool apred[2];
    #pragma unroll
    for (int l = 0; l < 2; l++) {
        int li = tid + l * 256;
        ar[l] = li >> 2; ac4[l] = (li & 3) * 4;
        apred[l] = (m0 + ar[l]) < M;
        br[l] = li >> 5; bc4[l] = (li & 31) * 4;
    }

    float c[4][4][4];
    #pragma unroll
    for (int i = 0; i < 4; i++)
        #pragma unroll
        for (int j = 0; j < 4; j++)
            #pragma unroll
            for (int f = 0; f < 4; f++) c[i][j][f] = 0.f;

    const int niter = K / 16;

    #pragma unroll
    for (int l = 0; l < 2; l++) {
        int garow = apred[l] ? (m0 + ar[l]) : (M - 1);
        cp_async16(&As[0][ar[l] * AP + ac4[l]], A + (size_t)garow * K + ac4[l], apred[l]);
        cp_async16(&Bs[0][br[l] * BP + bc4[l]], B + (size_t)br[l] * N + n0 + bc4[l], true);
    }
    CP_COMMIT();

    for (int it = 0; it < niter; it++) {
        int cur = it & 1, nxt = cur ^ 1;
        if (it + 1 < niter) {
            int k0n = (it + 1) * 16;
            #pragma unroll
            for (int l = 0; l < 2; l++) {
                int garow = apred[l] ? (m0 + ar[l]) : (M - 1);
                cp_async16(&As[nxt][ar[l] * AP + ac4[l]],
                           A + (size_t)garow * K + k0n + ac4[l], apred[l]);
                cp_async16(&Bs[nxt][br[l] * BP + bc4[l]],
                           B + (size_t)(k0n + br[l]) * N + n0 + bc4[l], true);
            }
            CP_COMMIT();
            CP_WAIT1();
        } else {
            CP_WAIT0();
        }
        __syncthreads();

        const float* as = As[cur];
        const float* bs = Bs[cur];
        #pragma unroll
        for (int kk = 0; kk < 16; kk += 8) {
            uint32_t af[4][4];
            #pragma unroll
            for (int mt = 0; mt < 4; mt++) {
                int base = wm * 64 + mt * 16;
                af[mt][0] = __float_as_uint(as[(base + g)     * AP + kk + tig]);
                af[mt][1] = __float_as_uint(as[(base + g + 8) * AP + kk + tig]);
                af[mt][2] = __float_as_uint(as[(base + g)     * AP + kk + tig + 4]);
                af[mt][3] = __float_as_uint(as[(base + g + 8) * AP + kk + tig + 4]);
            }
            uint32_t bf[4][2];
            #pragma unroll
            for (int nt = 0; nt < 4; nt++) {
                int n = wn * 32 + nt * 8 + g;
                bf[nt][0] = __float_as_uint(bs[(kk + tig)     * BP + n]);
                bf[nt][1] = __float_as_uint(bs[(kk + tig + 4) * BP + n]);
            }
            #pragma unroll
            for (int mt = 0; mt < 4; mt++)
                #pragma unroll
                for (int nt = 0; nt < 4; nt++)
                    mma_m16n8k8(c[mt][nt], af[mt], bf[nt]);
        }
        __syncthreads();
    }

    #pragma unroll
    for (int mt = 0; mt < 4; mt++) {
        int row0 = m0 + wm * 64 + mt * 16 + g;
        #pragma unroll
        for (int nt = 0; nt < 4; nt++) {
            int col = n0 + wn * 32 + nt * 8 + 2 * tig;
            float b0 = 0.f, b1 = 0.f;
            if (BIAS) { b0 = bias[col]; b1 = bias[col + 1]; }
            #pragma unroll
            for (int half = 0; half < 2; half++) {
                int r = row0 + half * 8;
                if (r >= M) continue;
                float v0 = c[mt][nt][half * 2 + 0] + b0;
                float v1 = c[mt][nt][half * 2 + 1] + b1;
                if (SPLIT) {
                    uint32_t h0 = f2tf32(v0), h1 = f2tf32(v1);
                    *(float2*)(C + (size_t)r * N + col) =
                        make_float2(__uint_as_float(h0), __uint_as_float(h1));
                    if (col < 1024) {
                        uint32_t l0 = f2tf32(v0 - __uint_as_float(h0));
                        uint32_t l1 = f2tf32(v1 - __uint_as_float(h1));
                        *(float2*)(C2 + (size_t)r * 1024 + col) =
                            make_float2(__uint_as_float(l0), __uint_as_float(l1));
                    }
                } else {
                    *(float2*)(C + (size_t)r * N + col) = make_float2(v0, v1);
                }
            }
        }
    }
}

// ============================================================================
// K2: gating (unchanged)
// ============================================================================
__global__ __launch_bounds__(256) void gate_kernel(
    const float* __restrict__ x, const float* __restrict__ tw,
    const float* __restrict__ tb, float* __restrict__ gate)
{
    int row = blockIdx.x * 8 + (threadIdx.x >> 5);
    if (row >= MROWS) return;
    int lane = threadIdx.x & 31;
    const float* xr = x + (size_t)row * CC;
    float s0 = 0.f, s1 = 0.f, s2 = 0.f, s3 = 0.f;
    for (int c = lane; c < CC; c += 32) {
        float xv = xr[c];
        float4 w = *(const float4*)(tw + c * 4);
        s0 += xv * w.x; s1 += xv * w.y; s2 += xv * w.z; s3 += xv * w.w;
    }
    s0 = warp_sum(s0); s1 = warp_sum(s1); s2 = warp_sum(s2); s3 = warp_sum(s3);
    float l0 = s0 + tb[0], l1 = s1 + tb[1], l2 = s2 + tb[2], l3 = s3 + tb[3];
    float m = fmaxf(fmaxf(l0, l1), fmaxf(l2, l3));
    float e0 = __expf(l0 - m), e1 = __expf(l1 - m);
    float e2 = __expf(l2 - m), e3 = __expf(l3 - m);
    float inv = 1.f / (e0 + e1 + e2 + e3);
    if (lane == 0) {
        float4 o = make_float4(e0 * inv, e1 * inv, e2 * inv, e3 * inv);
        *(float4*)(gate + (size_t)row * 4) = o;
    }
}

// ============================================================================
// K3: tensor-core attention, 32-row tiles, grid (544, 8), 256 thr,
// ~104 KB smem => 2 CTAs/SM. All staging via cp.async (operands pre-formatted
// by K1's split epilogue). Split-tf32 QK^T, fp32 nested-window softmax with
// gate fold (gate prefetched + shfl), tf32 PV with double-buffered V chunks.
// ============================================================================
#define QP2 68
#define KP2 68
#define VP2 72
#define PP2 260
#define K3_SMEM_BYTES ((32*QP2*2 + 64*KP2*2 + 2*32*VP2 + 32*PP2) * 4)  // 103936

__global__ __launch_bounds__(256, 2) void attn_tc2_kernel(
    const float* __restrict__ qkv, const float* __restrict__ qkvlo,
    const float* __restrict__ gate, float* __restrict__ eo)
{
    extern __shared__ float sm[];
    float* sQh = sm;                     // [32][QP2]
    float* sQl = sQh + 32 * QP2;
    float* sKh = sQl + 32 * QP2;         // [64][KP2]
    float* sKl = sKh + 64 * KP2;
    float* sV  = sKl + 64 * KP2;         // [2][32][VP2]
    float* sP  = sV  + 2 * 32 * VP2;     // [32][PP2]

    const int tid  = threadIdx.x;
    const int warp = tid >> 5, lane = tid & 31;
    const int g    = lane >> 2, tig = lane & 3;
    const int wm   = warp & 1,  wn  = warp >> 1;   // 2m x 4n
    const int bid  = blockIdx.x;
    const int b = bid / (HH * NJ);
    const int h = (bid / NJ) % HH;
    const int n = bid % NJ;
    const int t0 = blockIdx.y * 32;
    const float scale = 0.125f;

    // gate prefetch: lane rr<4 holds gate row t0+warp*4+rr; shfl at use
    float4 gv = make_float4(0.f, 0.f, 0.f, 0.f);
    {
        int tg = t0 + warp * 4 + lane;
        if (lane < 4 && tg < TT)
            gv = *(const float4*)(gate + ((size_t)((b * TT + tg) * NJ + n)) * 4);
    }

    #define QKV_ROW(s) (((size_t)(b * TT + (s))) * NJ + n)

    // ---- prologue: stage Q(hi/lo) + K chunk 0 (group 1); V chunk 0 (group 2)
    #pragma unroll
    for (int l = 0; l < 2; l++) {
        int li = tid + l * 256;
        int r = li >> 4, c4 = (li & 15) * 4;
        int t = t0 + r;
        bool pr = t < TT;
        int ts = pr ? t : TT - 1;
        cp_async16(&sQh[r * QP2 + c4], qkv   + QKV_ROW(ts) * NQKV + h * HD + c4, pr);
        cp_async16(&sQl[r * QP2 + c4], qkvlo + QKV_ROW(ts) * 1024 + h * HD + c4, pr);
    }
    #pragma unroll
    for (int l = 0; l < 4; l++) {
        int li = tid + l * 256;
        int sl = li >> 4, c4 = (li & 15) * 4;
        bool pr = sl < TT;   // chunk 0: s = sl
        int ss = pr ? sl : TT - 1;
        cp_async16(&sKh[sl * KP2 + c4], qkv   + QKV_ROW(ss) * NQKV + h * HD + 512 + c4, pr);
        cp_async16(&sKl[sl * KP2 + c4], qkvlo + QKV_ROW(ss) * 1024 + h * HD + 512 + c4, pr);
    }
    CP_COMMIT();
    #pragma unroll
    for (int l = 0; l < 2; l++) {
        int li = tid + l * 256;
        int r = li >> 4, c4 = (li & 15) * 4;
        bool pr = r < TT;
        int ss = pr ? r : TT - 1;
        cp_async16(&sV[r * VP2 + c4], qkv + QKV_ROW(ss) * NQKV + h * HD + 1024 + c4, pr);
    }
    CP_COMMIT();

    // ---- QK^T over 4 s-chunks of 64 ----
    for (int c = 0; c < 4; c++) {
        if (c == 0) { CP_WAIT1(); } else { CP_WAIT0(); }
        __syncthreads();

        float acc[2][4];
        #pragma unroll
        for (int j = 0; j < 2; j++)
            #pragma unroll
            for (int f = 0; f < 4; f++) acc[j][f] = 0.f;

        #pragma unroll
        for (int kk = 0; kk < 64; kk += 8) {
            uint32_t ah[4], al[4];
            int base = wm * 16;
            ah[0] = __float_as_uint(sQh[(base + g)     * QP2 + kk + tig]);
            ah[1] = __float_as_uint(sQh[(base + g + 8) * QP2 + kk + tig]);
            ah[2] = __float_as_uint(sQh[(base + g)     * QP2 + kk + tig + 4]);
            ah[3] = __float_as_uint(sQh[(base + g + 8) * QP2 + kk + tig + 4]);
            al[0] = __float_as_uint(sQl[(base + g)     * QP2 + kk + tig]);
            al[1] = __float_as_uint(sQl[(base + g + 8) * QP2 + kk + tig]);
            al[2] = __float_as_uint(sQl[(base + g)     * QP2 + kk + tig + 4]);
            al[3] = __float_as_uint(sQl[(base + g + 8) * QP2 + kk + tig + 4]);
            uint32_t bh[2][2], bl[2][2];
            #pragma unroll
            for (int nt = 0; nt < 2; nt++) {
                int nl = wn * 16 + nt * 8 + g;
                bh[nt][0] = __float_as_uint(sKh[nl * KP2 + kk + tig]);
                bh[nt][1] = __float_as_uint(sKh[nl * KP2 + kk + tig + 4]);
                bl[nt][0] = __float_as_uint(sKl[nl * KP2 + kk + tig]);
                bl[nt][1] = __float_as_uint(sKl[nl * KP2 + kk + tig + 4]);
            }
            #pragma unroll
            for (int nt = 0; nt < 2; nt++) {
                mma_m16n8k8(acc[nt], ah, bh[nt]);
                mma_m16n8k8(acc[nt], ah, bl[nt]);
                mma_m16n8k8(acc[nt], al, bh[nt]);
            }
        }

        int row = wm * 16 + g;
        #pragma unroll
        for (int nt = 0; nt < 2; nt++) {
            int col = c * 64 + wn * 16 + nt * 8 + 2 * tig;
            *(float2*)&sP[row * PP2 + col] =
                make_float2(acc[nt][0] * scale, acc[nt][1] * scale);
            *(float2*)&sP[(row + 8) * PP2 + col] =
                make_float2(acc[nt][2] * scale, acc[nt][3] * scale);
        }
        __syncthreads();

        if (c < 3) {
            int s0 = 64 * (c + 1);
            #pragma unroll
            for (int l = 0; l < 4; l++) {
                int li = tid + l * 256;
                int sl = li >> 4, c4 = (li & 15) * 4;
                int s = s0 + sl;
                bool pr = s < TT;
                int ss = pr ? s : TT - 1;
                cp_async16(&sKh[sl * KP2 + c4], qkv   + QKV_ROW(ss) * NQKV + h * HD + 512 + c4, pr);
                cp_async16(&sKl[sl * KP2 + c4], qkvlo + QKV_ROW(ss) * 1024 + h * HD + 512 + c4, pr);
            }
            CP_COMMIT();
        }
    }

    // ---- nested-window softmax + gate folding; write tf32 values ----
    for (int rr = 0; rr < 4; rr++) {
        int r = warp * 4 + rr;
        int t = t0 + r;
        if (t >= TT) break;
        float p[8];
        float m = -1e30f;
        #pragma unroll
        for (int i2 = 0; i2 < 8; i2++) {
            int s = lane + 32 * i2;
            float v = (s < TT) ? sP[r * PP2 + s] : -1e30f;
            p[i2] = v;
            m = fmaxf(m, v);
        }
        m = warp_max(m);
        int a9 = (t / 9) * 9, a27 = (t / 27) * 27, a81 = (t / 81) * 81;
        float z9 = 0.f, z27 = 0.f, z81 = 0.f, z243 = 0.f;
        #pragma unroll
        for (int i2 = 0; i2 < 8; i2++) {
            int s = lane + 32 * i2;
            float e = (s < TT) ? __expf(p[i2] - m) : 0.f;
            p[i2] = e;
            z243 += e;
            if (s >= a81 && s < a81 + 81) z81 += e;
            if (s >= a27 && s < a27 + 27) z27 += e;
            if (s >= a9  && s < a9  + 9)  z9  += e;
        }
        z9 = warp_sum(z9); z27 = warp_sum(z27);
        z81 = warp_sum(z81); z243 = warp_sum(z243);
        float w9   = __shfl_sync(0xffffffffu, gv.x, rr) / z9;
        float w27  = __shfl_sync(0xffffffffu, gv.y, rr) / z27;
        float w81  = __shfl_sync(0xffffffffu, gv.z, rr) / z81;
        float w243 = __shfl_sync(0xffffffffu, gv.w, rr) / z243;
        #pragma unroll
        for (int i2 = 0; i2 < 8; i2++) {
            int s = lane + 32 * i2;
            float val = 0.f;
            if (s < TT) {
                float cf = w243;
                if (s >= a81 && s < a81 + 81) cf += w81;
                if (s >= a27 && s < a27 + 27) cf += w27;
                if (s >= a9  && s < a9  + 9)  cf += w9;
                val = __uint_as_float(f2tf32(p[i2] * cf));
            }
            sP[r * PP2 + s] = val;   // s in [0,256): within PP2=260 pitch
        }
    }
    __syncthreads();

    // ---- O = P V with double-buffered 32-row V chunks ----
    float acc2[2][4];
    #pragma unroll
    for (int j = 0; j < 2; j++)
        #pragma unroll
        for (int f = 0; f < 4; f++) acc2[j][f] = 0.f;

    for (int c = 0; c < 8; c++) {
        if (c < 7) {
            int vc = 32 * (c + 1);
            float* vbn = sV + ((c + 1) & 1) * 32 * VP2;
            #pragma unroll
            for (int l = 0; l < 2; l++) {
                int li = tid + l * 256;
                int r = li >> 4, c4 = (li & 15) * 4;
                int s = vc + r;
                bool pr = s < TT;
                int ss = pr ? s : TT - 1;
                cp_async16(&vbn[r * VP2 + c4], qkv + QKV_ROW(ss) * NQKV + h * HD + 1024 + c4, pr);
            }
            CP_COMMIT();
            CP_WAIT1();
        } else {
            CP_WAIT0();
        }
        __syncthreads();

        const float* vb = sV + (c & 1) * 32 * VP2;
        int vc0 = c * 32;
        #pragma unroll
        for (int kk = 0; kk < 32; kk += 8) {
            uint32_t af[4];
            int base = wm * 16;
            af[0] = __float_as_uint(sP[(base + g)     * PP2 + vc0 + kk + tig]);
            af[1] = __float_as_uint(sP[(base + g + 8) * PP2 + vc0 + kk + tig]);
            af[2] = __float_as_uint(sP[(base + g)     * PP2 + vc0 + kk + tig + 4]);
            af[3] = __float_as_uint(sP[(base + g + 8) * PP2 + vc0 + kk + tig + 4]);
            uint32_t bf[2][2];
            #pragma unroll
            for (int nt = 0; nt < 2; nt++) {
                int nc = wn * 16 + nt * 8 + g;
                bf[nt][0] = __float_as_uint(vb[(kk + tig)     * VP2 + nc]);
                bf[nt][1] = __float_as_uint(vb[(kk + tig + 4) * VP2 + nc]);
            }
            #pragma unroll
            for (int nt = 0; nt < 2; nt++)
                mma_m16n8k8(acc2[nt], af, bf[nt]);
        }
        __syncthreads();
    }

    // ---- store O (tf32-rounded for K4) ----
    {
        int row = wm * 16 + g;
        #pragma unroll
        for (int nt = 0; nt < 2; nt++) {
            int col = wn * 16 + nt * 8 + 2 * tig;
            int t = t0 + row;
            if (t < TT) {
                *(float2*)(eo + QKV_ROW(t) * CC + h * HD + col) =
                    make_float2(__uint_as_float(f2tf32(acc2[nt][0])),
                                __uint_as_float(f2tf32(acc2[nt][1])));
            }
            if (t + 8 < TT) {
                *(float2*)(eo + QKV_ROW(t + 8) * CC + h * HD + col) =
                    make_float2(__uint_as_float(f2tf32(acc2[nt][2])),
                                __uint_as_float(f2tf32(acc2[nt][3])));
            }
        }
    }
    #undef QKV_ROW
}

// ============================================================================
extern "C" void kernel_launch(void* const* d_in, const int* in_sizes, int n_in,
                              void* d_out, int out_size)
{
    const float* x      = (const float*)d_in[0];
    const float* qkv_w  = (const float*)d_in[1];
    const float* proj_w = (const float*)d_in[2];
    const float* proj_b = (const float*)d_in[3];
    const float* te_w   = (const float*)d_in[4];
    const float* te_b   = (const float*)d_in[5];
    float* out = (float*)d_out;

    float *qkv_p, *qkvlo_p, *gate_p, *eo_p, *xtf_p, *w1_p, *w2_p;
    cudaGetSymbolAddress((void**)&qkv_p,   g_qkv);
    cudaGetSymbolAddress((void**)&qkvlo_p, g_qkvlo);
    cudaGetSymbolAddress((void**)&gate_p,  g_gate);
    cudaGetSymbolAddress((void**)&eo_p,    g_eo);
    cudaGetSymbolAddress((void**)&xtf_p,   g_xtf);
    cudaGetSymbolAddress((void**)&w1_p,    g_w1);
    cudaGetSymbolAddress((void**)&w2_p,    g_w2);

    cudaFuncSetAttribute(attn_tc2_kernel, cudaFuncAttributeMaxDynamicSharedMemorySize,
                         K3_SMEM_BYTES);

    // K0: round x, qkv_w, proj_w to tf32 once
    cvt_tf32_kernel<<<592, 256>>>(x, xtf_p, MROWS * CC / 4);
    cvt_tf32_kernel<<<148, 256>>>(qkv_w, w1_p, CC * NQKV / 4);
    cvt_tf32_kernel<<<148, 256>>>(proj_w, w2_p, CC * CC / 4);

    // K1: qkv = x @ qkv_w — split epilogue (q/k hi+lo, v tf32)
    gemm_tf32<false, true><<<dim3(NQKV / 128, (MROWS + 127) / 128), 256>>>(
        xtf_p, w1_p, nullptr, qkv_p, qkvlo_p, MROWS, NQKV, CC);

    // K2: gate = softmax(x @ te_w + te_b)
    gate_kernel<<<(MROWS + 7) / 8, 256>>>(x, te_w, te_b, gate_p);

    // K3: 2-CTA/SM tensor-core attention, 32-row tiles
    attn_tc2_kernel<<<dim3(BB * HH * NJ, 8), 256, K3_SMEM_BYTES>>>(
        qkv_p, qkvlo_p, gate_p, eo_p);

    // K4: out = eo @ proj_w + proj_b
    gemm_tf32<true, false><<<dim3(CC / 128, (MROWS + 127) / 128), 256>>>(
        eo_p, w2_p, proj_b, out, nullptr, MROWS, CC, CC);
}

// round 10
// speedup vs baseline: 1.6520x; 1.0642x over previous
#include <cuda_runtime.h>
#include <cstdint>
#include <cstddef>

#define TT    243
#define NJ    17
#define BB    4
#define HH    8
#define HD    64
#define CC    512
#define EE    4
#define MROWS (BB*TT*NJ)   // 16524
#define NQKV  1536

// ---- scratch (static device globals; no allocations allowed) ----
__device__ float g_qkv[(size_t)MROWS * NQKV];    // q/k raw fp32 ; v tf32-valued
__device__ float g_gate[(size_t)MROWS * EE];
__device__ float g_eo[(size_t)MROWS * CC];       // tf32-valued
__device__ float g_xtf[(size_t)MROWS * CC];
__device__ float g_w1[(size_t)CC * NQKV];
__device__ float g_w2[(size_t)CC * CC];

static __device__ __forceinline__ float warp_sum(float v) {
    #pragma unroll
    for (int o = 16; o; o >>= 1) v += __shfl_xor_sync(0xffffffffu, v, o);
    return v;
}
static __device__ __forceinline__ float warp_max(float v) {
    #pragma unroll
    for (int o = 16; o; o >>= 1) v = fmaxf(v, __shfl_xor_sync(0xffffffffu, v, o));
    return v;
}

static __device__ __forceinline__ uint32_t f2tf32(float x) {
    uint32_t r;
    asm("cvt.rna.tf32.f32 %0, %1;" : "=r"(r) : "f"(x));
    return r;
}

static __device__ __forceinline__ void mma_m16n8k8(
    float* c, const uint32_t* a, const uint32_t* b)
{
    asm volatile(
        "mma.sync.aligned.m16n8k8.row.col.f32.tf32.tf32.f32 "
        "{%0,%1,%2,%3}, {%4,%5,%6,%7}, {%8,%9}, {%0,%1,%2,%3};\n"
        : "+f"(c[0]), "+f"(c[1]), "+f"(c[2]), "+f"(c[3])
        : "r"(a[0]), "r"(a[1]), "r"(a[2]), "r"(a[3]),
          "r"(b[0]), "r"(b[1]));
}

static __device__ __forceinline__ void cp_async16(float* dst_smem, const float* src, bool pred) {
    uint32_t daddr = (uint32_t)__cvta_generic_to_shared(dst_smem);
    int sz = pred ? 16 : 0;
    asm volatile("cp.async.cg.shared.global [%0], [%1], 16, %2;\n"
                 :: "r"(daddr), "l"(src), "r"(sz));
}
#define CP_COMMIT() asm volatile("cp.async.commit_group;\n" ::: "memory")
#define CP_WAIT0()  asm volatile("cp.async.wait_group 0;\n" ::: "memory")
#define CP_WAIT1()  asm volatile("cp.async.wait_group 1;\n" ::: "memory")

// ============================================================================
// K0: elementwise tf32 rounding pre-pass
// ============================================================================
__global__ __launch_bounds__(256) void cvt_tf32_kernel(
    const float* __restrict__ src, float* __restrict__ dst, int n4)
{
    int i = blockIdx.x * 256 + threadIdx.x;
    int stride = gridDim.x * 256;
    for (; i < n4; i += stride) {
        float4 v = ((const float4*)src)[i];
        uint4 o;
        o.x = f2tf32(v.x); o.y = f2tf32(v.y);
        o.z = f2tf32(v.z); o.w = f2tf32(v.w);
        ((uint4*)dst)[i] = o;
    }
}

// ============================================================================
// K1/K4: tf32 tensor-core GEMM, cp.async double-buffered; pure LDS+MMA loop.
// SPLIT (K1): q/k cols (<1024) -> raw fp32; v cols -> tf32-rounded.
// K4: plain fp32 + bias.
// ============================================================================
#define AP 20
#define BP 136

template <bool BIAS, bool SPLIT>
__global__ __launch_bounds__(256) void gemm_tf32(
    const float* __restrict__ A, const float* __restrict__ B,
    const float* __restrict__ bias, float* __restrict__ C,
    int M, int N, int K)
{
    __shared__ float As[2][128 * AP];
    __shared__ float Bs[2][16 * BP];

    const int tid  = threadIdx.x;
    const int warp = tid >> 5, lane = tid & 31;
    const int g    = lane >> 2, tig = lane & 3;
    const int wm   = warp & 1,  wn  = warp >> 1;
    const int m0   = blockIdx.y * 128, n0 = blockIdx.x * 128;

    int ar[2], ac4[2], br[2], bc4[2];
    bool apred[2];
    #pragma unroll
    for (int l = 0; l < 2; l++) {
        int li = tid + l * 256;
        ar[l] = li >> 2; ac4[l] = (li & 3) * 4;
        apred[l] = (m0 + ar[l]) < M;
        br[l] = li >> 5; bc4[l] = (li & 31) * 4;
    }

    float c[4][4][4];
    #pragma unroll
    for (int i = 0; i < 4; i++)
        #pragma unroll
        for (int j = 0; j < 4; j++)
            #pragma unroll
            for (int f = 0; f < 4; f++) c[i][j][f] = 0.f;

    const int niter = K / 16;

    #pragma unroll
    for (int l = 0; l < 2; l++) {
        int garow = apred[l] ? (m0 + ar[l]) : (M - 1);
        cp_async16(&As[0][ar[l] * AP + ac4[l]], A + (size_t)garow * K + ac4[l], apred[l]);
        cp_async16(&Bs[0][br[l] * BP + bc4[l]], B + (size_t)br[l] * N + n0 + bc4[l], true);
    }
    CP_COMMIT();

    for (int it = 0; it < niter; it++) {
        int cur = it & 1, nxt = cur ^ 1;
        if (it + 1 < niter) {
            int k0n = (it + 1) * 16;
            #pragma unroll
            for (int l = 0; l < 2; l++) {
                int garow = apred[l] ? (m0 + ar[l]) : (M - 1);
                cp_async16(&As[nxt][ar[l] * AP + ac4[l]],
                           A + (size_t)garow * K + k0n + ac4[l], apred[l]);
                cp_async16(&Bs[nxt][br[l] * BP + bc4[l]],
                           B + (size_t)(k0n + br[l]) * N + n0 + bc4[l], true);
            }
            CP_COMMIT();
            CP_WAIT1();
        } else {
            CP_WAIT0();
        }
        __syncthreads();

        const float* as = As[cur];
        const float* bs = Bs[cur];
        #pragma unroll
        for (int kk = 0; kk < 16; kk += 8) {
            uint32_t af[4][4];
            #pragma unroll
            for (int mt = 0; mt < 4; mt++) {
                int base = wm * 64 + mt * 16;
                af[mt][0] = __float_as_uint(as[(base + g)     * AP + kk + tig]);
                af[mt][1] = __float_as_uint(as[(base + g + 8) * AP + kk + tig]);
                af[mt][2] = __float_as_uint(as[(base + g)     * AP + kk + tig + 4]);
                af[mt][3] = __float_as_uint(as[(base + g + 8) * AP + kk + tig + 4]);
            }
            uint32_t bf[4][2];
            #pragma unroll
            for (int nt = 0; nt < 4; nt++) {
                int n = wn * 32 + nt * 8 + g;
                bf[nt][0] = __float_as_uint(bs[(kk + tig)     * BP + n]);
                bf[nt][1] = __float_as_uint(bs[(kk + tig + 4) * BP + n]);
            }
            #pragma unroll
            for (int mt = 0; mt < 4; mt++)
                #pragma unroll
                for (int nt = 0; nt < 4; nt++)
                    mma_m16n8k8(c[mt][nt], af[mt], bf[nt]);
        }
        __syncthreads();
    }

    #pragma unroll
    for (int mt = 0; mt < 4; mt++) {
        int row0 = m0 + wm * 64 + mt * 16 + g;
        #pragma unroll
        for (int nt = 0; nt < 4; nt++) {
            int col = n0 + wn * 32 + nt * 8 + 2 * tig;
            float b0 = 0.f, b1 = 0.f;
            if (BIAS) { b0 = bias[col]; b1 = bias[col + 1]; }
            #pragma unroll
            for (int half = 0; half < 2; half++) {
                int r = row0 + half * 8;
                if (r >= M) continue;
                float v0 = c[mt][nt][half * 2 + 0] + b0;
                float v1 = c[mt][nt][half * 2 + 1] + b1;
                if (SPLIT && col >= 1024) {
                    // v columns: pre-round to tf32 for K3's PV mma
                    v0 = __uint_as_float(f2tf32(v0));
                    v1 = __uint_as_float(f2tf32(v1));
                }
                *(float2*)(C + (size_t)r * N + col) = make_float2(v0, v1);
            }
        }
    }
}

// ============================================================================
// K2: gating (unchanged)
// ============================================================================
__global__ __launch_bounds__(256) void gate_kernel(
    const float* __restrict__ x, const float* __restrict__ tw,
    const float* __restrict__ tb, float* __restrict__ gate)
{
    int row = blockIdx.x * 8 + (threadIdx.x >> 5);
    if (row >= MROWS) return;
    int lane = threadIdx.x & 31;
    const float* xr = x + (size_t)row * CC;
    float s0 = 0.f, s1 = 0.f, s2 = 0.f, s3 = 0.f;
    for (int c = lane; c < CC; c += 32) {
        float xv = xr[c];
        float4 w = *(const float4*)(tw + c * 4);
        s0 += xv * w.x; s1 += xv * w.y; s2 += xv * w.z; s3 += xv * w.w;
    }
    s0 = warp_sum(s0); s1 = warp_sum(s1); s2 = warp_sum(s2); s3 = warp_sum(s3);
    float l0 = s0 + tb[0], l1 = s1 + tb[1], l2 = s2 + tb[2], l3 = s3 + tb[3];
    float m = fmaxf(fmaxf(l0, l1), fmaxf(l2, l3));
    float e0 = __expf(l0 - m), e1 = __expf(l1 - m);
    float e2 = __expf(l2 - m), e3 = __expf(l3 - m);
    float inv = 1.f / (e0 + e1 + e2 + e3);
    if (lane == 0) {
        float4 o = make_float4(e0 * inv, e1 * inv, e2 * inv, e3 * inv);
        *(float4*)(gate + (size_t)row * 4) = o;
    }
}

// ============================================================================
// K3: tensor-core attention, 32-row tiles, grid (8, 544) — Q-tile FASTEST so
// consecutive CTAs share K/V in L2. 256 thr, ~104 KB smem => 2 CTAs/SM.
// Q/K loaded as raw fp32 and split hi/lo AT STAGING (same rounding points as
// before => bit-identical). K chunks prefetched into registers (LDG overlaps
// mma); V via cp.async double-buffer (tf32-valued in gmem).
// ============================================================================
#define QP2 68
#define KP2 68
#define VP2 72
#define PP2 260
#define K3_SMEM_BYTES ((32*QP2*2 + 64*KP2*2 + 2*32*VP2 + 32*PP2) * 4)  // 103936

__global__ __launch_bounds__(256, 2) void attn_tc2_kernel(
    const float* __restrict__ qkv, const float* __restrict__ gate,
    float* __restrict__ eo)
{
    extern __shared__ float sm[];
    float* sQh = sm;                     // [32][QP2]
    float* sQl = sQh + 32 * QP2;
    float* sKh = sQl + 32 * QP2;         // [64][KP2]
    float* sKl = sKh + 64 * KP2;
    float* sV  = sKl + 64 * KP2;         // [2][32][VP2]
    float* sP  = sV  + 2 * 32 * VP2;     // [32][PP2]

    const int tid  = threadIdx.x;
    const int warp = tid >> 5, lane = tid & 31;
    const int g    = lane >> 2, tig = lane & 3;
    const int wm   = warp & 1,  wn  = warp >> 1;   // 2m x 4n
    const int bid  = blockIdx.y;                   // (b,h,n) — slow axis
    const int b = bid / (HH * NJ);
    const int h = (bid / NJ) % HH;
    const int n = bid % NJ;
    const int t0 = blockIdx.x * 32;                // Q tile — fast axis
    const float scale = 0.125f;

    // gate prefetch: lane rr<4 holds gate row t0+warp*4+rr; shfl at use
    float4 gv = make_float4(0.f, 0.f, 0.f, 0.f);
    {
        int tg = t0 + warp * 4 + lane;
        if (lane < 4 && tg < TT)
            gv = *(const float4*)(gate + ((size_t)((b * TT + tg) * NJ + n)) * 4);
    }

    #define QKV_ROW(s) (((size_t)(b * TT + (s))) * NJ + n)

    // ---- V chunk 0 via cp.async (overlaps everything below) ----
    #pragma unroll
    for (int l = 0; l < 2; l++) {
        int li = tid + l * 256;
        int r = li >> 4, c4 = (li & 15) * 4;
        cp_async16(&sV[r * VP2 + c4], qkv + QKV_ROW(r) * NQKV + h * HD + 1024 + c4, true);
    }
    CP_COMMIT();

    // ---- stage Q (raw fp32 -> split hi/lo) ----
    #pragma unroll
    for (int l = 0; l < 2; l++) {
        int li = tid + l * 256;
        int r = li >> 4, c4 = (li & 15) * 4;
        int t = t0 + r;
        float4 qv = (t < TT)
            ? *(const float4*)(qkv + QKV_ROW(t) * NQKV + h * HD + c4)
            : make_float4(0.f, 0.f, 0.f, 0.f);
        uint4 hi, lo;
        hi.x = f2tf32(qv.x); lo.x = f2tf32(qv.x - __uint_as_float(hi.x));
        hi.y = f2tf32(qv.y); lo.y = f2tf32(qv.y - __uint_as_float(hi.y));
        hi.z = f2tf32(qv.z); lo.z = f2tf32(qv.z - __uint_as_float(hi.z));
        hi.w = f2tf32(qv.w); lo.w = f2tf32(qv.w - __uint_as_float(hi.w));
        *(uint4*)&sQh[r * QP2 + c4] = hi;
        *(uint4*)&sQl[r * QP2 + c4] = lo;
    }

    // ---- K chunk register prefetch (4 float4 / thread covers 64x64) ----
    float4 kreg[4];
    int ksl[4], kc4[4];
    #pragma unroll
    for (int l = 0; l < 4; l++) {
        int li = tid + l * 256;
        ksl[l] = li >> 4; kc4[l] = (li & 15) * 4;
    }
    #pragma unroll
    for (int l = 0; l < 4; l++) {
        int s = ksl[l];   // chunk 0
        kreg[l] = (s < TT)
            ? *(const float4*)(qkv + QKV_ROW(s) * NQKV + h * HD + 512 + kc4[l])
            : make_float4(0.f, 0.f, 0.f, 0.f);
    }

    // ---- QK^T over 4 s-chunks of 64 ----
    for (int c = 0; c < 4; c++) {
        __syncthreads();   // prev chunk's mma done; (c==0) Q/K regs ready
        #pragma unroll
        for (int l = 0; l < 4; l++) {
            float4 kv = kreg[l];
            uint4 hi, lo;
            hi.x = f2tf32(kv.x); lo.x = f2tf32(kv.x - __uint_as_float(hi.x));
            hi.y = f2tf32(kv.y); lo.y = f2tf32(kv.y - __uint_as_float(hi.y));
            hi.z = f2tf32(kv.z); lo.z = f2tf32(kv.z - __uint_as_float(hi.z));
            hi.w = f2tf32(kv.w); lo.w = f2tf32(kv.w - __uint_as_float(hi.w));
            *(uint4*)&sKh[ksl[l] * KP2 + kc4[l]] = hi;
            *(uint4*)&sKl[ksl[l] * KP2 + kc4[l]] = lo;
        }
        __syncthreads();

        if (c < 3) {       // prefetch next chunk; LDGs overlap the mma below
            int s0 = 64 * (c + 1);
            #pragma unroll
            for (int l = 0; l < 4; l++) {
                int s = s0 + ksl[l];
                kreg[l] = (s < TT)
                    ? *(const float4*)(qkv + QKV_ROW(s) * NQKV + h * HD + 512 + kc4[l])
                    : make_float4(0.f, 0.f, 0.f, 0.f);
            }
        }

        float acc[2][4];
        #pragma unroll
        for (int j = 0; j < 2; j++)
            #pragma unroll
            for (int f = 0; f < 4; f++) acc[j][f] = 0.f;

        #pragma unroll
        for (int kk = 0; kk < 64; kk += 8) {
            uint32_t ah[4], al[4];
            int base = wm * 16;
            ah[0] = __float_as_uint(sQh[(base + g)     * QP2 + kk + tig]);
            ah[1] = __float_as_uint(sQh[(base + g + 8) * QP2 + kk + tig]);
            ah[2] = __float_as_uint(sQh[(base + g)     * QP2 + kk + tig + 4]);
            ah[3] = __float_as_uint(sQh[(base + g + 8) * QP2 + kk + tig + 4]);
            al[0] = __float_as_uint(sQl[(base + g)     * QP2 + kk + tig]);
            al[1] = __float_as_uint(sQl[(base + g + 8) * QP2 + kk + tig]);
            al[2] = __float_as_uint(sQl[(base + g)     * QP2 + kk + tig + 4]);
            al[3] = __float_as_uint(sQl[(base + g + 8) * QP2 + kk + tig + 4]);
            uint32_t bh[2][2], bl[2][2];
            #pragma unroll
            for (int nt = 0; nt < 2; nt++) {
                int nl = wn * 16 + nt * 8 + g;
                bh[nt][0] = __float_as_uint(sKh[nl * KP2 + kk + tig]);
                bh[nt][1] = __float_as_uint(sKh[nl * KP2 + kk + tig + 4]);
                bl[nt][0] = __float_as_uint(sKl[nl * KP2 + kk + tig]);
                bl[nt][1] = __float_as_uint(sKl[nl * KP2 + kk + tig + 4]);
            }
            #pragma unroll
            for (int nt = 0; nt < 2; nt++) {
                mma_m16n8k8(acc[nt], ah, bh[nt]);
                mma_m16n8k8(acc[nt], ah, bl[nt]);
                mma_m16n8k8(acc[nt], al, bh[nt]);
            }
        }

        int row = wm * 16 + g;
        #pragma unroll
        for (int nt = 0; nt < 2; nt++) {
            int col = c * 64 + wn * 16 + nt * 8 + 2 * tig;
            *(float2*)&sP[row * PP2 + col] =
                make_float2(acc[nt][0] * scale, acc[nt][1] * scale);
            *(float2*)&sP[(row + 8) * PP2 + col] =
                make_float2(acc[nt][2] * scale, acc[nt][3] * scale);
        }
    }
    __syncthreads();

    // ---- nested-window softmax + gate folding; write tf32 values ----
    for (int rr = 0; rr < 4; rr++) {
        int r = warp * 4 + rr;
        int t = t0 + r;
        if (t >= TT) break;
        float p[8];
        float m = -1e30f;
        #pragma unroll
        for (int i2 = 0; i2 < 8; i2++) {
            int s = lane + 32 * i2;
            float v = (s < TT) ? sP[r * PP2 + s] : -1e30f;
            p[i2] = v;
            m = fmaxf(m, v);
        }
        m = warp_max(m);
        int a9 = (t / 9) * 9, a27 = (t / 27) * 27, a81 = (t / 81) * 81;
        float z9 = 0.f, z27 = 0.f, z81 = 0.f, z243 = 0.f;
        #pragma unroll
        for (int i2 = 0; i2 < 8; i2++) {
            int s = lane + 32 * i2;
            float e = (s < TT) ? __expf(p[i2] - m) : 0.f;
            p[i2] = e;
            z243 += e;
            if (s >= a81 && s < a81 + 81) z81 += e;
            if (s >= a27 && s < a27 + 27) z27 += e;
            if (s >= a9  && s < a9  + 9)  z9  += e;
        }
        z9 = warp_sum(z9); z27 = warp_sum(z27);
        z81 = warp_sum(z81); z243 = warp_sum(z243);
        float w9   = __shfl_sync(0xffffffffu, gv.x, rr) / z9;
        float w27  = __shfl_sync(0xffffffffu, gv.y, rr) / z27;
        float w81  = __shfl_sync(0xffffffffu, gv.z, rr) / z81;
        float w243 = __shfl_sync(0xffffffffu, gv.w, rr) / z243;
        #pragma unroll
        for (int i2 = 0; i2 < 8; i2++) {
            int s = lane + 32 * i2;
            float val = 0.f;
            if (s < TT) {
                float cf = w243;
                if (s >= a81 && s < a81 + 81) cf += w81;
                if (s >= a27 && s < a27 + 27) cf += w27;
                if (s >= a9  && s < a9  + 9)  cf += w9;
                val = __uint_as_float(f2tf32(p[i2] * cf));
            }
            sP[r * PP2 + s] = val;
        }
    }
    __syncthreads();

    // ---- O = P V with double-buffered 32-row V chunks ----
    float acc2[2][4];
    #pragma unroll
    for (int j = 0; j < 2; j++)
        #pragma unroll
        for (int f = 0; f < 4; f++) acc2[j][f] = 0.f;

    for (int c = 0; c < 8; c++) {
        if (c < 7) {
            int vc = 32 * (c + 1);
            float* vbn = sV + ((c + 1) & 1) * 32 * VP2;
            #pragma unroll
            for (int l = 0; l < 2; l++) {
                int li = tid + l * 256;
                int r = li >> 4, c4 = (li & 15) * 4;
                int s = vc + r;
                bool pr = s < TT;
                int ss = pr ? s : TT - 1;
                cp_async16(&vbn[r * VP2 + c4], qkv + QKV_ROW(ss) * NQKV + h * HD + 1024 + c4, pr);
            }
            CP_COMMIT();
            CP_WAIT1();
        } else {
            CP_WAIT0();
        }
        __syncthreads();

        const float* vb = sV + (c & 1) * 32 * VP2;
        int vc0 = c * 32;
        #pragma unroll
        for (int kk = 0; kk < 32; kk += 8) {
            uint32_t af[4];
            int base = wm * 16;
            af[0] = __float_as_uint(sP[(base + g)     * PP2 + vc0 + kk + tig]);
            af[1] = __float_as_uint(sP[(base + g + 8) * PP2 + vc0 + kk + tig]);
            af[2] = __float_as_uint(sP[(base + g)     * PP2 + vc0 + kk + tig + 4]);
            af[3] = __float_as_uint(sP[(base + g + 8) * PP2 + vc0 + kk + tig + 4]);
            uint32_t bf[2][2];
            #pragma unroll
            for (int nt = 0; nt < 2; nt++) {
                int nc = wn * 16 + nt * 8 + g;
                bf[nt][0] = __float_as_uint(vb[(kk + tig)     * VP2 + nc]);
                bf[nt][1] = __float_as_uint(vb[(kk + tig + 4) * VP2 + nc]);
            }
            #pragma unroll
            for (int nt = 0; nt < 2; nt++)
                mma_m16n8k8(acc2[nt], af, bf[nt]);
        }
        __syncthreads();
    }

    // ---- store O (tf32-rounded for K4) ----
    {
        int row = wm * 16 + g;
        #pragma unroll
        for (int nt = 0; nt < 2; nt++) {
            int col = wn * 16 + nt * 8 + 2 * tig;
            int t = t0 + row;
            if (t < TT) {
                *(float2*)(eo + QKV_ROW(t) * CC + h * HD + col) =
                    make_float2(__uint_as_float(f2tf32(acc2[nt][0])),
                                __uint_as_float(f2tf32(acc2[nt][1])));
            }
            if (t + 8 < TT) {
                *(float2*)(eo + QKV_ROW(t + 8) * CC + h * HD + col) =
                    make_float2(__uint_as_float(f2tf32(acc2[nt][2])),
                                __uint_as_float(f2tf32(acc2[nt][3])));
            }
        }
    }
    #undef QKV_ROW
}

// ============================================================================
extern "C" void kernel_launch(void* const* d_in, const int* in_sizes, int n_in,
                              void* d_out, int out_size)
{
    const float* x      = (const float*)d_in[0];
    const float* qkv_w  = (const float*)d_in[1];
    const float* proj_w = (const float*)d_in[2];
    const float* proj_b = (const float*)d_in[3];
    const float* te_w   = (const float*)d_in[4];
    const float* te_b   = (const float*)d_in[5];
    float* out = (float*)d_out;

    float *qkv_p, *gate_p, *eo_p, *xtf_p, *w1_p, *w2_p;
    cudaGetSymbolAddress((void**)&qkv_p,  g_qkv);
    cudaGetSymbolAddress((void**)&gate_p, g_gate);
    cudaGetSymbolAddress((void**)&eo_p,   g_eo);
    cudaGetSymbolAddress((void**)&xtf_p,  g_xtf);
    cudaGetSymbolAddress((void**)&w1_p,   g_w1);
    cudaGetSymbolAddress((void**)&w2_p,   g_w2);

    cudaFuncSetAttribute(attn_tc2_kernel, cudaFuncAttributeMaxDynamicSharedMemorySize,
                         K3_SMEM_BYTES);

    // K0: round x, qkv_w, proj_w to tf32 once
    cvt_tf32_kernel<<<592, 256>>>(x, xtf_p, MROWS * CC / 4);
    cvt_tf32_kernel<<<148, 256>>>(qkv_w, w1_p, CC * NQKV / 4);
    cvt_tf32_kernel<<<148, 256>>>(proj_w, w2_p, CC * CC / 4);

    // K1: qkv = x @ qkv_w — q/k raw fp32, v tf32-rounded
    gemm_tf32<false, true><<<dim3(NQKV / 128, (MROWS + 127) / 128), 256>>>(
        xtf_p, w1_p, nullptr, qkv_p, MROWS, NQKV, CC);

    // K2: gate = softmax(x @ te_w + te_b)
    gate_kernel<<<(MROWS + 7) / 8, 256>>>(x, te_w, te_b, gate_p);

    // K3: 2-CTA/SM tensor-core attention; Q-tile fastest grid axis for L2 reuse
    attn_tc2_kernel<<<dim3(8, BB * HH * NJ), 256, K3_SMEM_BYTES>>>(
        qkv_p, gate_p, eo_p);

    // K4: out = eo @ proj_w + proj_b
    gemm_tf32<true, false><<<dim3(CC / 128, (MROWS + 127) / 128), 256>>>(
        eo_p, w2_p, proj_b, out, MROWS, CC, CC);
}

// round 11
// speedup vs baseline: 1.6612x; 1.0056x over previous
#include <cuda_runtime.h>
#include <cstdint>
#include <cstddef>

#define TT    243
#define NJ    17
#define BB    4
#define HH    8
#define HD    64
#define CC    512
#define EE    4
#define MROWS (BB*TT*NJ)   // 16524
#define NQKV  1536

// ---- scratch (static device globals; no allocations allowed) ----
__device__ float g_qkv[(size_t)MROWS * NQKV];    // q/k raw fp32 ; v tf32-valued
__device__ float g_gate[(size_t)MROWS * EE];
__device__ float g_eo[(size_t)MROWS * CC];       // tf32-valued
__device__ float g_xtf[(size_t)MROWS * CC];
__device__ float g_w1[(size_t)CC * NQKV];
__device__ float g_w2[(size_t)CC * CC];

static __device__ __forceinline__ float warp_sum(float v) {
    #pragma unroll
    for (int o = 16; o; o >>= 1) v += __shfl_xor_sync(0xffffffffu, v, o);
    return v;
}
static __device__ __forceinline__ float warp_max(float v) {
    #pragma unroll
    for (int o = 16; o; o >>= 1) v = fmaxf(v, __shfl_xor_sync(0xffffffffu, v, o));
    return v;
}

static __device__ __forceinline__ uint32_t f2tf32(float x) {
    uint32_t r;
    asm("cvt.rna.tf32.f32 %0, %1;" : "=r"(r) : "f"(x));
    return r;
}

static __device__ __forceinline__ void mma_m16n8k8(
    float* c, const uint32_t* a, const uint32_t* b)
{
    asm volatile(
        "mma.sync.aligned.m16n8k8.row.col.f32.tf32.tf32.f32 "
        "{%0,%1,%2,%3}, {%4,%5,%6,%7}, {%8,%9}, {%0,%1,%2,%3};\n"
        : "+f"(c[0]), "+f"(c[1]), "+f"(c[2]), "+f"(c[3])
        : "r"(a[0]), "r"(a[1]), "r"(a[2]), "r"(a[3]),
          "r"(b[0]), "r"(b[1]));
}

static __device__ __forceinline__ void cp_async16(float* dst_smem, const float* src, bool pred) {
    uint32_t daddr = (uint32_t)__cvta_generic_to_shared(dst_smem);
    int sz = pred ? 16 : 0;
    asm volatile("cp.async.cg.shared.global [%0], [%1], 16, %2;\n"
                 :: "r"(daddr), "l"(src), "r"(sz));
}
#define CP_COMMIT() asm volatile("cp.async.commit_group;\n" ::: "memory")
#define CP_WAIT0()  asm volatile("cp.async.wait_group 0;\n" ::: "memory")

// ============================================================================
// K0: elementwise tf32 rounding pre-pass
// ============================================================================
__global__ __launch_bounds__(256) void cvt_tf32_kernel(
    const float* __restrict__ src, float* __restrict__ dst, int n4)
{
    int i = blockIdx.x * 256 + threadIdx.x;
    int stride = gridDim.x * 256;
    for (; i < n4; i += stride) {
        float4 v = ((const float4*)src)[i];
        uint4 o;
        o.x = f2tf32(v.x); o.y = f2tf32(v.y);
        o.z = f2tf32(v.z); o.w = f2tf32(v.w);
        ((uint4*)dst)[i] = o;
    }
}

// ============================================================================
// K1/K4: tf32 tensor-core GEMM. BK=32, single-sync software pipeline:
//   wait0 -> sync -> issue(it+1) -> 4x(kk) mma
// Accumulation order over k8-blocks identical to BK=16 version => bit-identical.
// BM=BN=128, 256 threads, 8 warps (2m x 4n), warptile 64x32. Dynamic smem.
// ============================================================================
#define AP 36    // 36 mod 32 = 4 -> conflict-free A fragment loads
#define BP 136   // 136 mod 32 = 8 -> conflict-free B fragment loads
#define GEMM_SMEM_BYTES ((2*128*AP + 2*32*BP) * 4)   // 71680

template <bool BIAS, bool SPLIT>
__global__ __launch_bounds__(256, 2) void gemm_tf32(
    const float* __restrict__ A, const float* __restrict__ B,
    const float* __restrict__ bias, float* __restrict__ C,
    int M, int N, int K)
{
    extern __shared__ float smg[];
    float* As = smg;                  // [2][128*AP]
    float* Bs = smg + 2 * 128 * AP;   // [2][32*BP]

    const int tid  = threadIdx.x;
    const int warp = tid >> 5, lane = tid & 31;
    const int g    = lane >> 2, tig = lane & 3;
    const int wm   = warp & 1,  wn  = warp >> 1;
    const int m0   = blockIdx.y * 128, n0 = blockIdx.x * 128;

    float c[4][4][4];
    #pragma unroll
    for (int i = 0; i < 4; i++)
        #pragma unroll
        for (int j = 0; j < 4; j++)
            #pragma unroll
            for (int f = 0; f < 4; f++) c[i][j][f] = 0.f;

    const int niter = K / 32;

    // ---- stage helper: A 128x32, B 32x128 (4 cp16/thread each) ----
    #define GEMM_STAGE(IT, BUF) do {                                          \
        int k0s = (IT) * 32;                                                  \
        float* ab = As + (BUF) * 128 * AP;                                    \
        float* bb = Bs + (BUF) * 32 * BP;                                     \
        _Pragma("unroll")                                                     \
        for (int l = 0; l < 4; l++) {                                         \
            int li = tid + l * 256;                                           \
            int r = li >> 3, c4 = (li & 7) * 4;                               \
            bool pr = (m0 + r) < M;                                           \
            int gr = pr ? (m0 + r) : (M - 1);                                 \
            cp_async16(&ab[r * AP + c4], A + (size_t)gr * K + k0s + c4, pr);  \
            int br = li >> 5, bc4 = (li & 31) * 4;                            \
            cp_async16(&bb[br * BP + bc4],                                    \
                       B + (size_t)(k0s + br) * N + n0 + bc4, true);          \
        }                                                                     \
        CP_COMMIT();                                                          \
    } while (0)

    GEMM_STAGE(0, 0);

    for (int it = 0; it < niter; it++) {
        int cur = it & 1;
        CP_WAIT0();
        __syncthreads();
        if (it + 1 < niter) GEMM_STAGE(it + 1, cur ^ 1);

        const float* as = As + cur * 128 * AP;
        const float* bs = Bs + cur * 32 * BP;
        #pragma unroll
        for (int kk = 0; kk < 32; kk += 8) {
            uint32_t af[4][4];
            #pragma unroll
            for (int mt = 0; mt < 4; mt++) {
                int base = wm * 64 + mt * 16;
                af[mt][0] = __float_as_uint(as[(base + g)     * AP + kk + tig]);
                af[mt][1] = __float_as_uint(as[(base + g + 8) * AP + kk + tig]);
                af[mt][2] = __float_as_uint(as[(base + g)     * AP + kk + tig + 4]);
                af[mt][3] = __float_as_uint(as[(base + g + 8) * AP + kk + tig + 4]);
            }
            uint32_t bf[4][2];
            #pragma unroll
            for (int nt = 0; nt < 4; nt++) {
                int n = wn * 32 + nt * 8 + g;
                bf[nt][0] = __float_as_uint(bs[(kk + tig)     * BP + n]);
                bf[nt][1] = __float_as_uint(bs[(kk + tig + 4) * BP + n]);
            }
            #pragma unroll
            for (int mt = 0; mt < 4; mt++)
                #pragma unroll
                for (int nt = 0; nt < 4; nt++)
                    mma_m16n8k8(c[mt][nt], af[mt], bf[nt]);
        }
    }
    #undef GEMM_STAGE

    #pragma unroll
    for (int mt = 0; mt < 4; mt++) {
        int row0 = m0 + wm * 64 + mt * 16 + g;
        #pragma unroll
        for (int nt = 0; nt < 4; nt++) {
            int col = n0 + wn * 32 + nt * 8 + 2 * tig;
            float b0 = 0.f, b1 = 0.f;
            if (BIAS) { b0 = bias[col]; b1 = bias[col + 1]; }
            #pragma unroll
            for (int half = 0; half < 2; half++) {
                int r = row0 + half * 8;
                if (r >= M) continue;
                float v0 = c[mt][nt][half * 2 + 0] + b0;
                float v1 = c[mt][nt][half * 2 + 1] + b1;
                if (SPLIT && col >= 1024) {
                    v0 = __uint_as_float(f2tf32(v0));
                    v1 = __uint_as_float(f2tf32(v1));
                }
                *(float2*)(C + (size_t)r * N + col) = make_float2(v0, v1);
            }
        }
    }
}

// ============================================================================
// K2: gating (unchanged)
// ============================================================================
__global__ __launch_bounds__(256) void gate_kernel(
    const float* __restrict__ x, const float* __restrict__ tw,
    const float* __restrict__ tb, float* __restrict__ gate)
{
    int row = blockIdx.x * 8 + (threadIdx.x >> 5);
    if (row >= MROWS) return;
    int lane = threadIdx.x & 31;
    const float* xr = x + (size_t)row * CC;
    float s0 = 0.f, s1 = 0.f, s2 = 0.f, s3 = 0.f;
    for (int c = lane; c < CC; c += 32) {
        float xv = xr[c];
        float4 w = *(const float4*)(tw + c * 4);
        s0 += xv * w.x; s1 += xv * w.y; s2 += xv * w.z; s3 += xv * w.w;
    }
    s0 = warp_sum(s0); s1 = warp_sum(s1); s2 = warp_sum(s2); s3 = warp_sum(s3);
    float l0 = s0 + tb[0], l1 = s1 + tb[1], l2 = s2 + tb[2], l3 = s3 + tb[3];
    float m = fmaxf(fmaxf(l0, l1), fmaxf(l2, l3));
    float e0 = __expf(l0 - m), e1 = __expf(l1 - m);
    float e2 = __expf(l2 - m), e3 = __expf(l3 - m);
    float inv = 1.f / (e0 + e1 + e2 + e3);
    if (lane == 0) {
        float4 o = make_float4(e0 * inv, e1 * inv, e2 * inv, e3 * inv);
        *(float4*)(gate + (size_t)row * 4) = o;
    }
}

// ============================================================================
// K3: tensor-core attention, 32-row tiles, grid (8, 544), 2 CTAs/SM.
// Same math as R9 (bit-identical); PV loop now single-sync per chunk.
// ============================================================================
#define QP2 68
#define KP2 68
#define VP2 72
#define PP2 260
#define K3_SMEM_BYTES ((32*QP2*2 + 64*KP2*2 + 2*32*VP2 + 32*PP2) * 4)  // 103936

__global__ __launch_bounds__(256, 2) void attn_tc2_kernel(
    const float* __restrict__ qkv, const float* __restrict__ gate,
    float* __restrict__ eo)
{
    extern __shared__ float sm[];
    float* sQh = sm;                     // [32][QP2]
    float* sQl = sQh + 32 * QP2;
    float* sKh = sQl + 32 * QP2;         // [64][KP2]
    float* sKl = sKh + 64 * KP2;
    float* sV  = sKl + 64 * KP2;         // [2][32][VP2]
    float* sP  = sV  + 2 * 32 * VP2;     // [32][PP2]

    const int tid  = threadIdx.x;
    const int warp = tid >> 5, lane = tid & 31;
    const int g    = lane >> 2, tig = lane & 3;
    const int wm   = warp & 1,  wn  = warp >> 1;   // 2m x 4n
    const int bid  = blockIdx.y;
    const int b = bid / (HH * NJ);
    const int h = (bid / NJ) % HH;
    const int n = bid % NJ;
    const int t0 = blockIdx.x * 32;
    const float scale = 0.125f;

    float4 gv = make_float4(0.f, 0.f, 0.f, 0.f);
    {
        int tg = t0 + warp * 4 + lane;
        if (lane < 4 && tg < TT)
            gv = *(const float4*)(gate + ((size_t)((b * TT + tg) * NJ + n)) * 4);
    }

    #define QKV_ROW(s) (((size_t)(b * TT + (s))) * NJ + n)

    // ---- V chunk 0 via cp.async ----
    #pragma unroll
    for (int l = 0; l < 2; l++) {
        int li = tid + l * 256;
        int r = li >> 4, c4 = (li & 15) * 4;
        cp_async16(&sV[r * VP2 + c4], qkv + QKV_ROW(r) * NQKV + h * HD + 1024 + c4, true);
    }
    CP_COMMIT();

    // ---- stage Q (raw fp32 -> split hi/lo) ----
    #pragma unroll
    for (int l = 0; l < 2; l++) {
        int li = tid + l * 256;
        int r = li >> 4, c4 = (li & 15) * 4;
        int t = t0 + r;
        float4 qv = (t < TT)
            ? *(const float4*)(qkv + QKV_ROW(t) * NQKV + h * HD + c4)
            : make_float4(0.f, 0.f, 0.f, 0.f);
        uint4 hi, lo;
        hi.x = f2tf32(qv.x); lo.x = f2tf32(qv.x - __uint_as_float(hi.x));
        hi.y = f2tf32(qv.y); lo.y = f2tf32(qv.y - __uint_as_float(hi.y));
        hi.z = f2tf32(qv.z); lo.z = f2tf32(qv.z - __uint_as_float(hi.z));
        hi.w = f2tf32(qv.w); lo.w = f2tf32(qv.w - __uint_as_float(hi.w));
        *(uint4*)&sQh[r * QP2 + c4] = hi;
        *(uint4*)&sQl[r * QP2 + c4] = lo;
    }

    // ---- K chunk register prefetch ----
    float4 kreg[4];
    int ksl[4], kc4[4];
    #pragma unroll
    for (int l = 0; l < 4; l++) {
        int li = tid + l * 256;
        ksl[l] = li >> 4; kc4[l] = (li & 15) * 4;
    }
    #pragma unroll
    for (int l = 0; l < 4; l++) {
        int s = ksl[l];
        kreg[l] = (s < TT)
            ? *(const float4*)(qkv + QKV_ROW(s) * NQKV + h * HD + 512 + kc4[l])
            : make_float4(0.f, 0.f, 0.f, 0.f);
    }

    // ---- QK^T over 4 s-chunks of 64 ----
    for (int c = 0; c < 4; c++) {
        __syncthreads();
        #pragma unroll
        for (int l = 0; l < 4; l++) {
            float4 kv = kreg[l];
            uint4 hi, lo;
            hi.x = f2tf32(kv.x); lo.x = f2tf32(kv.x - __uint_as_float(hi.x));
            hi.y = f2tf32(kv.y); lo.y = f2tf32(kv.y - __uint_as_float(hi.y));
            hi.z = f2tf32(kv.z); lo.z = f2tf32(kv.z - __uint_as_float(hi.z));
            hi.w = f2tf32(kv.w); lo.w = f2tf32(kv.w - __uint_as_float(hi.w));
            *(uint4*)&sKh[ksl[l] * KP2 + kc4[l]] = hi;
            *(uint4*)&sKl[ksl[l] * KP2 + kc4[l]] = lo;
        }
        __syncthreads();

        if (c < 3) {
            int s0 = 64 * (c + 1);
            #pragma unroll
            for (int l = 0; l < 4; l++) {
                int s = s0 + ksl[l];
                kreg[l] = (s < TT)
                    ? *(const float4*)(qkv + QKV_ROW(s) * NQKV + h * HD + 512 + kc4[l])
                    : make_float4(0.f, 0.f, 0.f, 0.f);
            }
        }

        float acc[2][4];
        #pragma unroll
        for (int j = 0; j < 2; j++)
            #pragma unroll
            for (int f = 0; f < 4; f++) acc[j][f] = 0.f;

        #pragma unroll
        for (int kk = 0; kk < 64; kk += 8) {
            uint32_t ah[4], al[4];
            int base = wm * 16;
            ah[0] = __float_as_uint(sQh[(base + g)     * QP2 + kk + tig]);
            ah[1] = __float_as_uint(sQh[(base + g + 8) * QP2 + kk + tig]);
            ah[2] = __float_as_uint(sQh[(base + g)     * QP2 + kk + tig + 4]);
            ah[3] = __float_as_uint(sQh[(base + g + 8) * QP2 + kk + tig + 4]);
            al[0] = __float_as_uint(sQl[(base + g)     * QP2 + kk + tig]);
            al[1] = __float_as_uint(sQl[(base + g + 8) * QP2 + kk + tig]);
            al[2] = __float_as_uint(sQl[(base + g)     * QP2 + kk + tig + 4]);
            al[3] = __float_as_uint(sQl[(base + g + 8) * QP2 + kk + tig + 4]);
            uint32_t bh[2][2], bl[2][2];
            #pragma unroll
            for (int nt = 0; nt < 2; nt++) {
                int nl = wn * 16 + nt * 8 + g;
                bh[nt][0] = __float_as_uint(sKh[nl * KP2 + kk + tig]);
                bh[nt][1] = __float_as_uint(sKh[nl * KP2 + kk + tig + 4]);
                bl[nt][0] = __float_as_uint(sKl[nl * KP2 + kk + tig]);
                bl[nt][1] = __float_as_uint(sKl[nl * KP2 + kk + tig + 4]);
            }
            #pragma unroll
            for (int nt = 0; nt < 2; nt++) {
                mma_m16n8k8(acc[nt], ah, bh[nt]);
                mma_m16n8k8(acc[nt], ah, bl[nt]);
                mma_m16n8k8(acc[nt], al, bh[nt]);
            }
        }

        int row = wm * 16 + g;
        #pragma unroll
        for (int nt = 0; nt < 2; nt++) {
            int col = c * 64 + wn * 16 + nt * 8 + 2 * tig;
            *(float2*)&sP[row * PP2 + col] =
                make_float2(acc[nt][0] * scale, acc[nt][1] * scale);
            *(float2*)&sP[(row + 8) * PP2 + col] =
                make_float2(acc[nt][2] * scale, acc[nt][3] * scale);
        }
    }
    __syncthreads();

    // ---- nested-window softmax + gate folding; write tf32 values ----
    for (int rr = 0; rr < 4; rr++) {
        int r = warp * 4 + rr;
        int t = t0 + r;
        if (t >= TT) break;
        float p[8];
        float m = -1e30f;
        #pragma unroll
        for (int i2 = 0; i2 < 8; i2++) {
            int s = lane + 32 * i2;
            float v = (s < TT) ? sP[r * PP2 + s] : -1e30f;
            p[i2] = v;
            m = fmaxf(m, v);
        }
        m = warp_max(m);
        int a9 = (t / 9) * 9, a27 = (t / 27) * 27, a81 = (t / 81) * 81;
        float z9 = 0.f, z27 = 0.f, z81 = 0.f, z243 = 0.f;
        #pragma unroll
        for (int i2 = 0; i2 < 8; i2++) {
            int s = lane + 32 * i2;
            float e = (s < TT) ? __expf(p[i2] - m) : 0.f;
            p[i2] = e;
            z243 += e;
            if (s >= a81 && s < a81 + 81) z81 += e;
            if (s >= a27 && s < a27 + 27) z27 += e;
            if (s >= a9  && s < a9  + 9)  z9  += e;
        }
        z9 = warp_sum(z9); z27 = warp_sum(z27);
        z81 = warp_sum(z81); z243 = warp_sum(z243);
        float w9   = __shfl_sync(0xffffffffu, gv.x, rr) / z9;
        float w27  = __shfl_sync(0xffffffffu, gv.y, rr) / z27;
        float w81  = __shfl_sync(0xffffffffu, gv.z, rr) / z81;
        float w243 = __shfl_sync(0xffffffffu, gv.w, rr) / z243;
        #pragma unroll
        for (int i2 = 0; i2 < 8; i2++) {
            int s = lane + 32 * i2;
            float val = 0.f;
            if (s < TT) {
                float cf = w243;
                if (s >= a81 && s < a81 + 81) cf += w81;
                if (s >= a27 && s < a27 + 27) cf += w27;
                if (s >= a9  && s < a9  + 9)  cf += w9;
                val = __uint_as_float(f2tf32(p[i2] * cf));
            }
            sP[r * PP2 + s] = val;
        }
    }
    // (PV loop's first wait0+sync provides the barrier before reading sP/sV)

    // ---- O = P V, single-sync-per-chunk double-buffered pipeline ----
    float acc2[2][4];
    #pragma unroll
    for (int j = 0; j < 2; j++)
        #pragma unroll
        for (int f = 0; f < 4; f++) acc2[j][f] = 0.f;

    for (int c = 0; c < 8; c++) {
        CP_WAIT0();
        __syncthreads();
        if (c < 7) {
            int vc = 32 * (c + 1);
            float* vbn = sV + ((c + 1) & 1) * 32 * VP2;
            #pragma unroll
            for (int l = 0; l < 2; l++) {
                int li = tid + l * 256;
                int r = li >> 4, c4 = (li & 15) * 4;
                int s = vc + r;
                bool pr = s < TT;
                int ss = pr ? s : TT - 1;
                cp_async16(&vbn[r * VP2 + c4], qkv + QKV_ROW(ss) * NQKV + h * HD + 1024 + c4, pr);
            }
            CP_COMMIT();
        }

        const float* vb = sV + (c & 1) * 32 * VP2;
        int vc0 = c * 32;
        #pragma unroll
        for (int kk = 0; kk < 32; kk += 8) {
            uint32_t af[4];
            int base = wm * 16;
            af[0] = __float_as_uint(sP[(base + g)     * PP2 + vc0 + kk + tig]);
            af[1] = __float_as_uint(sP[(base + g + 8) * PP2 + vc0 + kk + tig]);
            af[2] = __float_as_uint(sP[(base + g)     * PP2 + vc0 + kk + tig + 4]);
            af[3] = __float_as_uint(sP[(base + g + 8) * PP2 + vc0 + kk + tig + 4]);
            uint32_t bf[2][2];
            #pragma unroll
            for (int nt = 0; nt < 2; nt++) {
                int nc = wn * 16 + nt * 8 + g;
                bf[nt][0] = __float_as_uint(vb[(kk + tig)     * VP2 + nc]);
                bf[nt][1] = __float_as_uint(vb[(kk + tig + 4) * VP2 + nc]);
            }
            #pragma unroll
            for (int nt = 0; nt < 2; nt++)
                mma_m16n8k8(acc2[nt], af, bf[nt]);
        }
    }

    // ---- store O (tf32-rounded for K4) ----
    {
        int row = wm * 16 + g;
        #pragma unroll
        for (int nt = 0; nt < 2; nt++) {
            int col = wn * 16 + nt * 8 + 2 * tig;
            int t = t0 + row;
            if (t < TT) {
                *(float2*)(eo + QKV_ROW(t) * CC + h * HD + col) =
                    make_float2(__uint_as_float(f2tf32(acc2[nt][0])),
                                __uint_as_float(f2tf32(acc2[nt][1])));
            }
            if (t + 8 < TT) {
                *(float2*)(eo + QKV_ROW(t + 8) * CC + h * HD + col) =
                    make_float2(__uint_as_float(f2tf32(acc2[nt][2])),
                                __uint_as_float(f2tf32(acc2[nt][3])));
            }
        }
    }
    #undef QKV_ROW
}

// ============================================================================
extern "C" void kernel_launch(void* const* d_in, const int* in_sizes, int n_in,
                              void* d_out, int out_size)
{
    const float* x      = (const float*)d_in[0];
    const float* qkv_w  = (const float*)d_in[1];
    const float* proj_w = (const float*)d_in[2];
    const float* proj_b = (const float*)d_in[3];
    const float* te_w   = (const float*)d_in[4];
    const float* te_b   = (const float*)d_in[5];
    float* out = (float*)d_out;

    float *qkv_p, *gate_p, *eo_p, *xtf_p, *w1_p, *w2_p;
    cudaGetSymbolAddress((void**)&qkv_p,  g_qkv);
    cudaGetSymbolAddress((void**)&gate_p, g_gate);
    cudaGetSymbolAddress((void**)&eo_p,   g_eo);
    cudaGetSymbolAddress((void**)&xtf_p,  g_xtf);
    cudaGetSymbolAddress((void**)&w1_p,   g_w1);
    cudaGetSymbolAddress((void**)&w2_p,   g_w2);

    cudaFuncSetAttribute(attn_tc2_kernel, cudaFuncAttributeMaxDynamicSharedMemorySize,
                         K3_SMEM_BYTES);
    cudaFuncSetAttribute(gemm_tf32<false, true>,
                         cudaFuncAttributeMaxDynamicSharedMemorySize, GEMM_SMEM_BYTES);
    cudaFuncSetAttribute(gemm_tf32<true, false>,
                         cudaFuncAttributeMaxDynamicSharedMemorySize, GEMM_SMEM_BYTES);

    // K0: round x, qkv_w, proj_w to tf32 once
    cvt_tf32_kernel<<<592, 256>>>(x, xtf_p, MROWS * CC / 4);
    cvt_tf32_kernel<<<148, 256>>>(qkv_w, w1_p, CC * NQKV / 4);
    cvt_tf32_kernel<<<148, 256>>>(proj_w, w2_p, CC * CC / 4);

    // K1: qkv = x @ qkv_w — q/k raw fp32, v tf32-rounded
    gemm_tf32<false, true><<<dim3(NQKV / 128, (MROWS + 127) / 128), 256, GEMM_SMEM_BYTES>>>(
        xtf_p, w1_p, nullptr, qkv_p, MROWS, NQKV, CC);

    // K2: gate = softmax(x @ te_w + te_b)
    gate_kernel<<<(MROWS + 7) / 8, 256>>>(x, te_w, te_b, gate_p);

    // K3: 2-CTA/SM tensor-core attention; Q-tile fastest grid axis for L2 reuse
    attn_tc2_kernel<<<dim3(8, BB * HH * NJ), 256, K3_SMEM_BYTES>>>(
        qkv_p, gate_p, eo_p);

    // K4: out = eo @ proj_w + proj_b
    gemm_tf32<true, false><<<dim3(CC / 128, (MROWS + 127) / 128), 256, GEMM_SMEM_BYTES>>>(
        eo_p, w2_p, proj_b, out, MROWS, CC, CC);
}

// round 13
// speedup vs baseline: 1.8164x; 1.0934x over previous
#include <cuda_runtime.h>
#include <cuda_bf16.h>
#include <cstdint>
#include <cstddef>

#define TT    243
#define NJ    17
#define BB    4
#define HH    8
#define HD    64
#define CC    512
#define EE    4
#define MROWS (BB*TT*NJ)   // 16524
#define NQKV  1536

// ---- scratch (static device globals; no allocations allowed) ----
__device__ __nv_bfloat16 g_qkh[(size_t)MROWS * 1024];  // q|k hi (bf16)
__device__ __nv_bfloat16 g_qkl[(size_t)MROWS * 1024];  // q|k lo (bf16)
__device__ float g_v[(size_t)MROWS * 512];             // v (tf32-valued fp32)
__device__ float g_gate[(size_t)MROWS * EE];
__device__ float g_eo[(size_t)MROWS * CC];             // tf32-valued
__device__ float g_xtf[(size_t)MROWS * CC];
__device__ float g_w1[(size_t)CC * NQKV];
__device__ float g_w2[(size_t)CC * CC];

static __device__ __forceinline__ float warp_sum(float v) {
    #pragma unroll
    for (int o = 16; o; o >>= 1) v += __shfl_xor_sync(0xffffffffu, v, o);
    return v;
}
static __device__ __forceinline__ float warp_max(float v) {
    #pragma unroll
    for (int o = 16; o; o >>= 1) v = fmaxf(v, __shfl_xor_sync(0xffffffffu, v, o));
    return v;
}

static __device__ __forceinline__ uint32_t f2tf32(float x) {
    uint32_t r;
    asm("cvt.rna.tf32.f32 %0, %1;" : "=r"(r) : "f"(x));
    return r;
}

static __device__ __forceinline__ void mma_m16n8k8(
    float* c, const uint32_t* a, const uint32_t* b)
{
    asm volatile(
        "mma.sync.aligned.m16n8k8.row.col.f32.tf32.tf32.f32 "
        "{%0,%1,%2,%3}, {%4,%5,%6,%7}, {%8,%9}, {%0,%1,%2,%3};\n"
        : "+f"(c[0]), "+f"(c[1]), "+f"(c[2]), "+f"(c[3])
        : "r"(a[0]), "r"(a[1]), "r"(a[2]), "r"(a[3]),
          "r"(b[0]), "r"(b[1]));
}

static __device__ __forceinline__ void mma_m16n8k16_bf16(
    float* c, const uint32_t* a, const uint32_t* b)
{
    asm volatile(
        "mma.sync.aligned.m16n8k16.row.col.f32.bf16.bf16.f32 "
        "{%0,%1,%2,%3}, {%4,%5,%6,%7}, {%8,%9}, {%0,%1,%2,%3};\n"
        : "+f"(c[0]), "+f"(c[1]), "+f"(c[2]), "+f"(c[3])
        : "r"(a[0]), "r"(a[1]), "r"(a[2]), "r"(a[3]),
          "r"(b[0]), "r"(b[1]));
}

static __device__ __forceinline__ void cp_async16(void* dst_smem, const void* src, bool pred) {
    uint32_t daddr = (uint32_t)__cvta_generic_to_shared(dst_smem);
    int sz = pred ? 16 : 0;
    asm volatile("cp.async.cg.shared.global [%0], [%1], 16, %2;\n"
                 :: "r"(daddr), "l"(src), "r"(sz));
}
#define CP_COMMIT() asm volatile("cp.async.commit_group;\n" ::: "memory")
#define CP_WAIT0()  asm volatile("cp.async.wait_group 0;\n" ::: "memory")
#define CP_WAIT1()  asm volatile("cp.async.wait_group 1;\n" ::: "memory")

// ============================================================================
// K0: elementwise tf32 rounding pre-pass
// ============================================================================
__global__ __launch_bounds__(256) void cvt_tf32_kernel(
    const float* __restrict__ src, float* __restrict__ dst, int n4)
{
    int i = blockIdx.x * 256 + threadIdx.x;
    int stride = gridDim.x * 256;
    for (; i < n4; i += stride) {
        float4 v = ((const float4*)src)[i];
        uint4 o;
        o.x = f2tf32(v.x); o.y = f2tf32(v.y);
        o.z = f2tf32(v.z); o.w = f2tf32(v.w);
        ((uint4*)dst)[i] = o;
    }
}

// ============================================================================
// K1/K4: tf32 tensor-core GEMM, BK=32, single-sync cp.async pipeline.
// SPLIT (K1): q/k cols (<1024) -> bf16 hi/lo planes; v cols -> tf32 fp32.
// K4: plain fp32 + bias.
// ============================================================================
#define AP 36
#define BP 136
#define GEMM_SMEM_BYTES ((2*128*AP + 2*32*BP) * 4)   // 71680

template <bool BIAS, bool SPLIT>
__global__ __launch_bounds__(256, 2) void gemm_tf32(
    const float* __restrict__ A, const float* __restrict__ B,
    const float* __restrict__ bias, float* __restrict__ C,
    __nv_bfloat16* __restrict__ qkh, __nv_bfloat16* __restrict__ qkl,
    float* __restrict__ vout, int M, int N, int K)
{
    extern __shared__ float smg[];
    float* As = smg;
    float* Bs = smg + 2 * 128 * AP;

    const int tid  = threadIdx.x;
    const int warp = tid >> 5, lane = tid & 31;
    const int g    = lane >> 2, tig = lane & 3;
    const int wm   = warp & 1,  wn  = warp >> 1;
    const int m0   = blockIdx.y * 128, n0 = blockIdx.x * 128;

    float c[4][4][4];
    #pragma unroll
    for (int i = 0; i < 4; i++)
        #pragma unroll
        for (int j = 0; j < 4; j++)
            #pragma unroll
            for (int f = 0; f < 4; f++) c[i][j][f] = 0.f;

    const int niter = K / 32;

    #define GEMM_STAGE(IT, BUF) do {                                          \
        int k0s = (IT) * 32;                                                  \
        float* ab = As + (BUF) * 128 * AP;                                    \
        float* bb = Bs + (BUF) * 32 * BP;                                     \
        _Pragma("unroll")                                                     \
        for (int l = 0; l < 4; l++) {                                         \
            int li = tid + l * 256;                                           \
            int r = li >> 3, c4 = (li & 7) * 4;                               \
            bool pr = (m0 + r) < M;                                           \
            int gr = pr ? (m0 + r) : (M - 1);                                 \
            cp_async16(&ab[r * AP + c4], A + (size_t)gr * K + k0s + c4, pr);  \
            int br = li >> 5, bc4 = (li & 31) * 4;                            \
            cp_async16(&bb[br * BP + bc4],                                    \
                       B + (size_t)(k0s + br) * N + n0 + bc4, true);          \
        }                                                                     \
        CP_COMMIT();                                                          \
    } while (0)

    GEMM_STAGE(0, 0);

    for (int it = 0; it < niter; it++) {
        int cur = it & 1;
        CP_WAIT0();
        __syncthreads();
        if (it + 1 < niter) GEMM_STAGE(it + 1, cur ^ 1);

        const float* as = As + cur * 128 * AP;
        const float* bs = Bs + cur * 32 * BP;
        #pragma unroll
        for (int kk = 0; kk < 32; kk += 8) {
            uint32_t af[4][4];
            #pragma unroll
            for (int mt = 0; mt < 4; mt++) {
                int base = wm * 64 + mt * 16;
                af[mt][0] = __float_as_uint(as[(base + g)     * AP + kk + tig]);
                af[mt][1] = __float_as_uint(as[(base + g + 8) * AP + kk + tig]);
                af[mt][2] = __float_as_uint(as[(base + g)     * AP + kk + tig + 4]);
                af[mt][3] = __float_as_uint(as[(base + g + 8) * AP + kk + tig + 4]);
            }
            uint32_t bf[4][2];
            #pragma unroll
            for (int nt = 0; nt < 4; nt++) {
                int n = wn * 32 + nt * 8 + g;
                bf[nt][0] = __float_as_uint(bs[(kk + tig)     * BP + n]);
                bf[nt][1] = __float_as_uint(bs[(kk + tig + 4) * BP + n]);
            }
            #pragma unroll
            for (int mt = 0; mt < 4; mt++)
                #pragma unroll
                for (int nt = 0; nt < 4; nt++)
                    mma_m16n8k8(c[mt][nt], af[mt], bf[nt]);
        }
    }
    #undef GEMM_STAGE

    #pragma unroll
    for (int mt = 0; mt < 4; mt++) {
        int row0 = m0 + wm * 64 + mt * 16 + g;
        #pragma unroll
        for (int nt = 0; nt < 4; nt++) {
            int col = n0 + wn * 32 + nt * 8 + 2 * tig;
            float b0 = 0.f, b1 = 0.f;
            if (BIAS) { b0 = bias[col]; b1 = bias[col + 1]; }
            #pragma unroll
            for (int half = 0; half < 2; half++) {
                int r = row0 + half * 8;
                if (r >= M) continue;
                float v0 = c[mt][nt][half * 2 + 0] + b0;
                float v1 = c[mt][nt][half * 2 + 1] + b1;
                if (SPLIT) {
                    if (col < 1024) {
                        __nv_bfloat16 h0 = __float2bfloat16(v0);
                        __nv_bfloat16 h1 = __float2bfloat16(v1);
                        __nv_bfloat16 l0 = __float2bfloat16(v0 - __bfloat162float(h0));
                        __nv_bfloat16 l1 = __float2bfloat16(v1 - __bfloat162float(h1));
                        *(__nv_bfloat162*)(qkh + (size_t)r * 1024 + col) =
                            __halves2bfloat162(h0, h1);
                        *(__nv_bfloat162*)(qkl + (size_t)r * 1024 + col) =
                            __halves2bfloat162(l0, l1);
                    } else {
                        float2 o = make_float2(__uint_as_float(f2tf32(v0)),
                                               __uint_as_float(f2tf32(v1)));
                        *(float2*)(vout + (size_t)r * 512 + (col - 1024)) = o;
                    }
                } else {
                    *(float2*)(C + (size_t)r * N + col) = make_float2(v0, v1);
                }
            }
        }
    }
}

// ============================================================================
// K2: gating (unchanged)
// ============================================================================
__global__ __launch_bounds__(256) void gate_kernel(
    const float* __restrict__ x, const float* __restrict__ tw,
    const float* __restrict__ tb, float* __restrict__ gate)
{
    int row = blockIdx.x * 8 + (threadIdx.x >> 5);
    if (row >= MROWS) return;
    int lane = threadIdx.x & 31;
    const float* xr = x + (size_t)row * CC;
    float s0 = 0.f, s1 = 0.f, s2 = 0.f, s3 = 0.f;
    for (int c = lane; c < CC; c += 32) {
        float xv = xr[c];
        float4 w = *(const float4*)(tw + c * 4);
        s0 += xv * w.x; s1 += xv * w.y; s2 += xv * w.z; s3 += xv * w.w;
    }
    s0 = warp_sum(s0); s1 = warp_sum(s1); s2 = warp_sum(s2); s3 = warp_sum(s3);
    float l0 = s0 + tb[0], l1 = s1 + tb[1], l2 = s2 + tb[2], l3 = s3 + tb[3];
    float m = fmaxf(fmaxf(l0, l1), fmaxf(l2, l3));
    float e0 = __expf(l0 - m), e1 = __expf(l1 - m);
    float e2 = __expf(l2 - m), e3 = __expf(l3 - m);
    float inv = 1.f / (e0 + e1 + e2 + e3);
    if (lane == 0) {
        float4 o = make_float4(e0 * inv, e1 * inv, e2 * inv, e3 * inv);
        *(float4*)(gate + (size_t)row * 4) = o;
    }
}

// ============================================================================
// K3: attention. QK^T = bf16x3 (hh+hl+lh) on pre-split planes, pure cp.async
// staging, double-buffered K chunks. fp32 nested-window softmax + gate fold.
// PV = tf32. 32-row tiles, grid (8, 544), 256 thr, ~98 KB smem -> 2 CTAs/SM.
// ============================================================================
#define QW  36    // Q/K pitch in bf16x2 WORDS (64 bf16 = 32 words + pad 4)
#define VP2 72
#define PP2 260
#define K3_SMEM_WORDS (2*32*QW + 2*2*64*QW + 2*32*VP2 + 32*PP2)
#define K3_SMEM_BYTES (K3_SMEM_WORDS * 4)   // 97792

__global__ __launch_bounds__(256, 2) void attn_tc2_kernel(
    const __nv_bfloat16* __restrict__ qkh, const __nv_bfloat16* __restrict__ qkl,
    const float* __restrict__ vsrc, const float* __restrict__ gate,
    float* __restrict__ eo)
{
    extern __shared__ float smf[];
    uint32_t* sQh = (uint32_t*)smf;            // [32][QW]
    uint32_t* sQl = sQh + 32 * QW;
    uint32_t* sKh = sQl + 32 * QW;             // [2][64][QW]
    uint32_t* sKl = sKh + 2 * 64 * QW;
    float*    sV  = (float*)(sKl + 2 * 64 * QW);   // [2][32][VP2]
    float*    sP  = sV + 2 * 32 * VP2;             // [32][PP2]

    const int tid  = threadIdx.x;
    const int warp = tid >> 5, lane = tid & 31;
    const int g    = lane >> 2, tig = lane & 3;
    const int wm   = warp & 1,  wn  = warp >> 1;   // 2m x 4n
    const int bid  = blockIdx.y;
    const int b = bid / (HH * NJ);
    const int h = (bid / NJ) % HH;
    const int n = bid % NJ;
    const int t0 = blockIdx.x * 32;
    const float scale = 0.125f;

    float4 gv = make_float4(0.f, 0.f, 0.f, 0.f);
    {
        int tg = t0 + warp * 4 + lane;
        if (lane < 4 && tg < TT)
            gv = *(const float4*)(gate + ((size_t)((b * TT + tg) * NJ + n)) * 4);
    }

    #define QKV_ROW(s) (((size_t)(b * TT + (s))) * NJ + n)

    // ---- group G0: Q hi/lo + K chunk 0 hi/lo ----
    {
        // Q: 32 rows x 8 segs per plane; 256 transfers/plane
        int r = tid >> 3, seg = tid & 7;
        int t = t0 + r;
        bool pr = t < TT;
        size_t qrow = QKV_ROW(pr ? t : 0);
        cp_async16(sQh + r * QW + seg * 4, qkh + qrow * 1024 + h * HD + seg * 8, pr);
        cp_async16(sQl + r * QW + seg * 4, qkl + qrow * 1024 + h * HD + seg * 8, pr);
        // K chunk 0: 64 rows x 8 segs per plane; 512 transfers/plane
        #pragma unroll
        for (int l = 0; l < 2; l++) {
            int li = tid + l * 256;
            int kr = li >> 3, ks = li & 7;
            bool kp = kr < TT;
            size_t krow = QKV_ROW(kp ? kr : 0);
            cp_async16(sKh + kr * QW + ks * 4, qkh + krow * 1024 + 512 + h * HD + ks * 8, kp);
            cp_async16(sKl + kr * QW + ks * 4, qkl + krow * 1024 + 512 + h * HD + ks * 8, kp);
        }
    }
    CP_COMMIT();
    // ---- group G1: V chunk 0 ----
    #pragma unroll
    for (int l = 0; l < 2; l++) {
        int li = tid + l * 256;
        int r = li >> 4, c4 = (li & 15) * 4;
        cp_async16(sV + r * VP2 + c4, vsrc + QKV_ROW(r) * 512 + h * HD + c4, true);
    }
    CP_COMMIT();

    // ---- QK^T over 4 s-chunks of 64, bf16x3, double-buffered K ----
    for (int c = 0; c < 4; c++) {
        if (c == 0) { CP_WAIT1(); } else { CP_WAIT0(); }
        __syncthreads();
        if (c < 3) {
            int s0 = 64 * (c + 1);
            uint32_t* khn = sKh + ((c + 1) & 1) * 64 * QW;
            uint32_t* kln = sKl + ((c + 1) & 1) * 64 * QW;
            #pragma unroll
            for (int l = 0; l < 2; l++) {
                int li = tid + l * 256;
                int kr = li >> 3, ks = li & 7;
                int s = s0 + kr;
                bool kp = s < TT;
                size_t krow = QKV_ROW(kp ? s : 0);
                cp_async16(khn + kr * QW + ks * 4, qkh + krow * 1024 + 512 + h * HD + ks * 8, kp);
                cp_async16(kln + kr * QW + ks * 4, qkl + krow * 1024 + 512 + h * HD + ks * 8, kp);
            }
            CP_COMMIT();
        }

        const uint32_t* kh = sKh + (c & 1) * 64 * QW;
        const uint32_t* kl = sKl + (c & 1) * 64 * QW;

        float acc[2][4];
        #pragma unroll
        for (int j = 0; j < 2; j++)
            #pragma unroll
            for (int f = 0; f < 4; f++) acc[j][f] = 0.f;

        #pragma unroll
        for (int ks = 0; ks < 32; ks += 8) {   // word units; k16 per step
            uint32_t ah[4], al[4];
            int base = wm * 16;
            ah[0] = sQh[(base + g)     * QW + ks + tig];
            ah[1] = sQh[(base + g + 8) * QW + ks + tig];
            ah[2] = sQh[(base + g)     * QW + ks + tig + 4];
            ah[3] = sQh[(base + g + 8) * QW + ks + tig + 4];
            al[0] = sQl[(base + g)     * QW + ks + tig];
            al[1] = sQl[(base + g + 8) * QW + ks + tig];
            al[2] = sQl[(base + g)     * QW + ks + tig + 4];
            al[3] = sQl[(base + g + 8) * QW + ks + tig + 4];
            uint32_t bh[2][2], bl[2][2];
            #pragma unroll
            for (int nt = 0; nt < 2; nt++) {
                int nl = wn * 16 + nt * 8 + g;
                bh[nt][0] = kh[nl * QW + ks + tig];
                bh[nt][1] = kh[nl * QW + ks + tig + 4];
                bl[nt][0] = kl[nl * QW + ks + tig];
                bl[nt][1] = kl[nl * QW + ks + tig + 4];
            }
            #pragma unroll
            for (int nt = 0; nt < 2; nt++) {
                mma_m16n8k16_bf16(acc[nt], ah, bh[nt]);
                mma_m16n8k16_bf16(acc[nt], ah, bl[nt]);
                mma_m16n8k16_bf16(acc[nt], al, bh[nt]);
            }
        }

        int row = wm * 16 + g;
        #pragma unroll
        for (int nt = 0; nt < 2; nt++) {
            int col = c * 64 + wn * 16 + nt * 8 + 2 * tig;
            *(float2*)&sP[row * PP2 + col] =
                make_float2(acc[nt][0] * scale, acc[nt][1] * scale);
            *(float2*)&sP[(row + 8) * PP2 + col] =
                make_float2(acc[nt][2] * scale, acc[nt][3] * scale);
        }
    }
    __syncthreads();

    // ---- nested-window softmax + gate folding; write tf32 values ----
    for (int rr = 0; rr < 4; rr++) {
        int r = warp * 4 + rr;
        int t = t0 + r;
        if (t >= TT) break;
        float p[8];
        float m = -1e30f;
        #pragma unroll
        for (int i2 = 0; i2 < 8; i2++) {
            int s = lane + 32 * i2;
            float v = (s < TT) ? sP[r * PP2 + s] : -1e30f;
            p[i2] = v;
            m = fmaxf(m, v);
        }
        m = warp_max(m);
        int a9 = (t / 9) * 9, a27 = (t / 27) * 27, a81 = (t / 81) * 81;
        float z9 = 0.f, z27 = 0.f, z81 = 0.f, z243 = 0.f;
        #pragma unroll
        for (int i2 = 0; i2 < 8; i2++) {
            int s = lane + 32 * i2;
            float e = (s < TT) ? __expf(p[i2] - m) : 0.f;
            p[i2] = e;
            z243 += e;
            if (s >= a81 && s < a81 + 81) z81 += e;
            if (s >= a27 && s < a27 + 27) z27 += e;
            if (s >= a9  && s < a9  + 9)  z9  += e;
        }
        z9 = warp_sum(z9); z27 = warp_sum(z27);
        z81 = warp_sum(z81); z243 = warp_sum(z243);
        float w9   = __shfl_sync(0xffffffffu, gv.x, rr) / z9;
        float w27  = __shfl_sync(0xffffffffu, gv.y, rr) / z27;
        float w81  = __shfl_sync(0xffffffffu, gv.z, rr) / z81;
        float w243 = __shfl_sync(0xffffffffu, gv.w, rr) / z243;
        #pragma unroll
        for (int i2 = 0; i2 < 8; i2++) {
            int s = lane + 32 * i2;
            float val = 0.f;
            if (s < TT) {
                float cf = w243;
                if (s >= a81 && s < a81 + 81) cf += w81;
                if (s >= a27 && s < a27 + 27) cf += w27;
                if (s >= a9  && s < a9  + 9)  cf += w9;
                val = __uint_as_float(f2tf32(p[i2] * cf));
            }
            sP[r * PP2 + s] = val;
        }
    }
    // (PV loop's first wait+sync is the barrier before reading sP/sV)

    // ---- O = P V (tf32), single-sync-per-chunk double-buffered V ----
    float acc2[2][4];
    #pragma unroll
    for (int j = 0; j < 2; j++)
        #pragma unroll
        for (int f = 0; f < 4; f++) acc2[j][f] = 0.f;

    for (int c = 0; c < 8; c++) {
        CP_WAIT0();
        __syncthreads();
        if (c < 7) {
            int vc = 32 * (c + 1);
            float* vbn = sV + ((c + 1) & 1) * 32 * VP2;
            #pragma unroll
            for (int l = 0; l < 2; l++) {
                int li = tid + l * 256;
                int r = li >> 4, c4 = (li & 15) * 4;
                int s = vc + r;
                bool pr = s < TT;
                int ss = pr ? s : TT - 1;
                cp_async16(vbn + r * VP2 + c4, vsrc + QKV_ROW(ss) * 512 + h * HD + c4, pr);
            }
            CP_COMMIT();
        }

        const float* vb = sV + (c & 1) * 32 * VP2;
        int vc0 = c * 32;
        #pragma unroll
        for (int kk = 0; kk < 32; kk += 8) {
            uint32_t af[4];
            int base = wm * 16;
            af[0] = __float_as_uint(sP[(base + g)     * PP2 + vc0 + kk + tig]);
            af[1] = __float_as_uint(sP[(base + g + 8) * PP2 + vc0 + kk + tig]);
            af[2] = __float_as_uint(sP[(base + g)     * PP2 + vc0 + kk + tig + 4]);
            af[3] = __float_as_uint(sP[(base + g + 8) * PP2 + vc0 + kk + tig + 4]);
            uint32_t bf[2][2];
            #pragma unroll
            for (int nt = 0; nt < 2; nt++) {
                int nc = wn * 16 + nt * 8 + g;
                bf[nt][0] = __float_as_uint(vb[(kk + tig)     * VP2 + nc]);
                bf[nt][1] = __float_as_uint(vb[(kk + tig + 4) * VP2 + nc]);
            }
            #pragma unroll
            for (int nt = 0; nt < 2; nt++)
                mma_m16n8k8(acc2[nt], af, bf[nt]);
        }
    }

    // ---- store O (tf32-rounded for K4) ----
    {
        int row = wm * 16 + g;
        #pragma unroll
        for (int nt = 0; nt < 2; nt++) {
            int col = wn * 16 + nt * 8 + 2 * tig;
            int t = t0 + row;
            if (t < TT) {
                *(float2*)(eo + QKV_ROW(t) * CC + h * HD + col) =
                    make_float2(__uint_as_float(f2tf32(acc2[nt][0])),
                                __uint_as_float(f2tf32(acc2[nt][1])));
            }
            if (t + 8 < TT) {
                *(float2*)(eo + QKV_ROW(t + 8) * CC + h * HD + col) =
                    make_float2(__uint_as_float(f2tf32(acc2[nt][2])),
                                __uint_as_float(f2tf32(acc2[nt][3])));
            }
        }
    }
    #undef QKV_ROW
}

// ============================================================================
extern "C" void kernel_launch(void* const* d_in, const int* in_sizes, int n_in,
                              void* d_out, int out_size)
{
    const float* x      = (const float*)d_in[0];
    const float* qkv_w  = (const float*)d_in[1];
    const float* proj_w = (const float*)d_in[2];
    const float* proj_b = (const float*)d_in[3];
    const float* te_w   = (const float*)d_in[4];
    const float* te_b   = (const float*)d_in[5];
    float* out = (float*)d_out;

    float *gate_p, *eo_p, *xtf_p, *w1_p, *w2_p, *v_p;
    __nv_bfloat16 *qkh_p, *qkl_p;
    cudaGetSymbolAddress((void**)&qkh_p,  g_qkh);
    cudaGetSymbolAddress((void**)&qkl_p,  g_qkl);
    cudaGetSymbolAddress((void**)&v_p,    g_v);
    cudaGetSymbolAddress((void**)&gate_p, g_gate);
    cudaGetSymbolAddress((void**)&eo_p,   g_eo);
    cudaGetSymbolAddress((void**)&xtf_p,  g_xtf);
    cudaGetSymbolAddress((void**)&w1_p,   g_w1);
    cudaGetSymbolAddress((void**)&w2_p,   g_w2);

    cudaFuncSetAttribute(attn_tc2_kernel, cudaFuncAttributeMaxDynamicSharedMemorySize,
                         K3_SMEM_BYTES);
    cudaFuncSetAttribute(gemm_tf32<false, true>,
                         cudaFuncAttributeMaxDynamicSharedMemorySize, GEMM_SMEM_BYTES);
    cudaFuncSetAttribute(gemm_tf32<true, false>,
                         cudaFuncAttributeMaxDynamicSharedMemorySize, GEMM_SMEM_BYTES);

    // K0: round x, qkv_w, proj_w to tf32 once
    cvt_tf32_kernel<<<592, 256>>>(x, xtf_p, MROWS * CC / 4);
    cvt_tf32_kernel<<<148, 256>>>(qkv_w, w1_p, CC * NQKV / 4);
    cvt_tf32_kernel<<<148, 256>>>(proj_w, w2_p, CC * CC / 4);

    // K1: qkv = x @ qkv_w — q/k bf16 hi/lo planes, v tf32 plane
    gemm_tf32<false, true><<<dim3(NQKV / 128, (MROWS + 127) / 128), 256, GEMM_SMEM_BYTES>>>(
        xtf_p, w1_p, nullptr, nullptr, qkh_p, qkl_p, v_p, MROWS, NQKV, CC);

    // K2: gate = softmax(x @ te_w + te_b)
    gate_kernel<<<(MROWS + 7) / 8, 256>>>(x, te_w, te_b, gate_p);

    // K3: 2-CTA/SM attention, bf16x3 QK^T, pure cp.async staging
    attn_tc2_kernel<<<dim3(8, BB * HH * NJ), 256, K3_SMEM_BYTES>>>(
        qkh_p, qkl_p, v_p, gate_p, eo_p);

    // K4: out = eo @ proj_w + proj_b
    gemm_tf32<true, false><<<dim3(CC / 128, (MROWS + 127) / 128), 256, GEMM_SMEM_BYTES>>>(
        eo_p, w2_p, proj_b, out, nullptr, nullptr, nullptr, MROWS, CC, CC);
}

// round 14
// speedup vs baseline: 1.9023x; 1.0473x over previous
#include <cuda_runtime.h>
#include <cuda_bf16.h>
#include <cstdint>
#include <cstddef>

#define TT    243
#define NJ    17
#define BB    4
#define HH    8
#define HD    64
#define CC    512
#define EE    4
#define MROWS (BB*TT*NJ)   // 16524
#define NQKV  1536

// ---- scratch (static device globals; no allocations allowed) ----
__device__ __nv_bfloat16 g_qkh[(size_t)MROWS * 1024];  // q|k hi (bf16)
__device__ __nv_bfloat16 g_qkl[(size_t)MROWS * 1024];  // q|k lo (bf16)
__device__ float g_v[(size_t)MROWS * 512];             // v (tf32-valued fp32)
__device__ float g_gate[(size_t)MROWS * EE];
__device__ float g_eo[(size_t)MROWS * CC];             // tf32-valued
__device__ float g_xtf[(size_t)MROWS * CC];
__device__ float g_w1[(size_t)CC * NQKV];
__device__ float g_w2[(size_t)CC * CC];

static __device__ __forceinline__ float warp_sum(float v) {
    #pragma unroll
    for (int o = 16; o; o >>= 1) v += __shfl_xor_sync(0xffffffffu, v, o);
    return v;
}
static __device__ __forceinline__ float warp_max(float v) {
    #pragma unroll
    for (int o = 16; o; o >>= 1) v = fmaxf(v, __shfl_xor_sync(0xffffffffu, v, o));
    return v;
}

static __device__ __forceinline__ uint32_t f2tf32(float x) {
    uint32_t r;
    asm("cvt.rna.tf32.f32 %0, %1;" : "=r"(r) : "f"(x));
    return r;
}

static __device__ __forceinline__ void mma_m16n8k8(
    float* c, const uint32_t* a, const uint32_t* b)
{
    asm volatile(
        "mma.sync.aligned.m16n8k8.row.col.f32.tf32.tf32.f32 "
        "{%0,%1,%2,%3}, {%4,%5,%6,%7}, {%8,%9}, {%0,%1,%2,%3};\n"
        : "+f"(c[0]), "+f"(c[1]), "+f"(c[2]), "+f"(c[3])
        : "r"(a[0]), "r"(a[1]), "r"(a[2]), "r"(a[3]),
          "r"(b[0]), "r"(b[1]));
}

static __device__ __forceinline__ void mma_m16n8k16_bf16(
    float* c, const uint32_t* a, const uint32_t* b)
{
    asm volatile(
        "mma.sync.aligned.m16n8k16.row.col.f32.bf16.bf16.f32 "
        "{%0,%1,%2,%3}, {%4,%5,%6,%7}, {%8,%9}, {%0,%1,%2,%3};\n"
        : "+f"(c[0]), "+f"(c[1]), "+f"(c[2]), "+f"(c[3])
        : "r"(a[0]), "r"(a[1]), "r"(a[2]), "r"(a[3]),
          "r"(b[0]), "r"(b[1]));
}

// ldmatrix.x4: one instruction loads 4 fragment registers (layout matches
// mma A-fragments for 32-bit-element and bf16 operands; values identical
// to the 4 scalar LDS it replaces).
static __device__ __forceinline__ void ldsm4(uint32_t* r, uint32_t addr) {
    asm volatile("ldmatrix.sync.aligned.m8n8.x4.shared.b16 {%0,%1,%2,%3}, [%4];"
                 : "=r"(r[0]), "=r"(r[1]), "=r"(r[2]), "=r"(r[3]) : "r"(addr));
}

static __device__ __forceinline__ void cp_async16(void* dst_smem, const void* src, bool pred) {
    uint32_t daddr = (uint32_t)__cvta_generic_to_shared(dst_smem);
    int sz = pred ? 16 : 0;
    asm volatile("cp.async.cg.shared.global [%0], [%1], 16, %2;\n"
                 :: "r"(daddr), "l"(src), "r"(sz));
}
#define CP_COMMIT() asm volatile("cp.async.commit_group;\n" ::: "memory")
#define CP_WAIT0()  asm volatile("cp.async.wait_group 0;\n" ::: "memory")
#define CP_WAIT1()  asm volatile("cp.async.wait_group 1;\n" ::: "memory")

// ============================================================================
// K0: elementwise tf32 rounding pre-pass
// ============================================================================
__global__ __launch_bounds__(256) void cvt_tf32_kernel(
    const float* __restrict__ src, float* __restrict__ dst, int n4)
{
    int i = blockIdx.x * 256 + threadIdx.x;
    int stride = gridDim.x * 256;
    for (; i < n4; i += stride) {
        float4 v = ((const float4*)src)[i];
        uint4 o;
        o.x = f2tf32(v.x); o.y = f2tf32(v.y);
        o.z = f2tf32(v.z); o.w = f2tf32(v.w);
        ((uint4*)dst)[i] = o;
    }
}

// ============================================================================
// K1/K4: tf32 tensor-core GEMM, BK=32, single-sync cp.async pipeline.
// A-fragments via ldmatrix.x4 (4 LDS -> 1 LDSM, identical values).
// SPLIT (K1): q/k cols -> bf16 hi/lo planes; v cols -> tf32 fp32.
// ============================================================================
#define AP 36
#define BP 136
#define GEMM_SMEM_BYTES ((2*128*AP + 2*32*BP) * 4)   // 71680

template <bool BIAS, bool SPLIT>
__global__ __launch_bounds__(256, 2) void gemm_tf32(
    const float* __restrict__ A, const float* __restrict__ B,
    const float* __restrict__ bias, float* __restrict__ C,
    __nv_bfloat16* __restrict__ qkh, __nv_bfloat16* __restrict__ qkl,
    float* __restrict__ vout, int M, int N, int K)
{
    extern __shared__ float smg[];
    float* As = smg;
    float* Bs = smg + 2 * 128 * AP;

    const int tid  = threadIdx.x;
    const int warp = tid >> 5, lane = tid & 31;
    const int g    = lane >> 2, tig = lane & 3;
    const int wm   = warp & 1,  wn  = warp >> 1;
    const int m0   = blockIdx.y * 128, n0 = blockIdx.x * 128;

    const uint32_t sA0 = (uint32_t)__cvta_generic_to_shared(As);
    // per-lane LDSM offset within an A buffer (float units):
    // row = wm*64 + (lane&15), col-word = (lane>>4)*4
    const uint32_t a_off = (uint32_t)((wm * 64 + (lane & 15)) * AP + ((lane >> 4) * 4));

    float c[4][4][4];
    #pragma unroll
    for (int i = 0; i < 4; i++)
        #pragma unroll
        for (int j = 0; j < 4; j++)
            #pragma unroll
            for (int f = 0; f < 4; f++) c[i][j][f] = 0.f;

    const int niter = K / 32;

    #define GEMM_STAGE(IT, BUF) do {                                          \
        int k0s = (IT) * 32;                                                  \
        float* ab = As + (BUF) * 128 * AP;                                    \
        float* bb = Bs + (BUF) * 32 * BP;                                     \
        _Pragma("unroll")                                                     \
        for (int l = 0; l < 4; l++) {                                         \
            int li = tid + l * 256;                                           \
            int r = li >> 3, c4 = (li & 7) * 4;                               \
            bool pr = (m0 + r) < M;                                           \
            int gr = pr ? (m0 + r) : (M - 1);                                 \
            cp_async16(&ab[r * AP + c4], A + (size_t)gr * K + k0s + c4, pr);  \
            int br = li >> 5, bc4 = (li & 31) * 4;                            \
            cp_async16(&bb[br * BP + bc4],                                    \
                       B + (size_t)(k0s + br) * N + n0 + bc4, true);          \
        }                                                                     \
        CP_COMMIT();                                                          \
    } while (0)

    GEMM_STAGE(0, 0);

    for (int it = 0; it < niter; it++) {
        int cur = it & 1;
        CP_WAIT0();
        __syncthreads();
        if (it + 1 < niter) GEMM_STAGE(it + 1, cur ^ 1);

        const float* bs = Bs + cur * 32 * BP;
        const uint32_t sAcur = sA0 + (uint32_t)(cur * 128 * AP) * 4u;
        #pragma unroll
        for (int kk = 0; kk < 32; kk += 8) {
            uint32_t af[4][4];
            #pragma unroll
            for (int mt = 0; mt < 4; mt++)
                ldsm4(af[mt], sAcur + 4u * (a_off + (uint32_t)(mt * 16 * AP + kk)));
            uint32_t bf[4][2];
            #pragma unroll
            for (int nt = 0; nt < 4; nt++) {
                int n = wn * 32 + nt * 8 + g;
                bf[nt][0] = __float_as_uint(bs[(kk + tig)     * BP + n]);
                bf[nt][1] = __float_as_uint(bs[(kk + tig + 4) * BP + n]);
            }
            #pragma unroll
            for (int mt = 0; mt < 4; mt++)
                #pragma unroll
                for (int nt = 0; nt < 4; nt++)
                    mma_m16n8k8(c[mt][nt], af[mt], bf[nt]);
        }
    }
    #undef GEMM_STAGE

    #pragma unroll
    for (int mt = 0; mt < 4; mt++) {
        int row0 = m0 + wm * 64 + mt * 16 + g;
        #pragma unroll
        for (int nt = 0; nt < 4; nt++) {
            int col = n0 + wn * 32 + nt * 8 + 2 * tig;
            float b0 = 0.f, b1 = 0.f;
            if (BIAS) { b0 = bias[col]; b1 = bias[col + 1]; }
            #pragma unroll
            for (int half = 0; half < 2; half++) {
                int r = row0 + half * 8;
                if (r >= M) continue;
                float v0 = c[mt][nt][half * 2 + 0] + b0;
                float v1 = c[mt][nt][half * 2 + 1] + b1;
                if (SPLIT) {
                    if (col < 1024) {
                        __nv_bfloat16 h0 = __float2bfloat16(v0);
                        __nv_bfloat16 h1 = __float2bfloat16(v1);
                        __nv_bfloat16 l0 = __float2bfloat16(v0 - __bfloat162float(h0));
                        __nv_bfloat16 l1 = __float2bfloat16(v1 - __bfloat162float(h1));
                        *(__nv_bfloat162*)(qkh + (size_t)r * 1024 + col) =
                            __halves2bfloat162(h0, h1);
                        *(__nv_bfloat162*)(qkl + (size_t)r * 1024 + col) =
                            __halves2bfloat162(l0, l1);
                    } else {
                        float2 o = make_float2(__uint_as_float(f2tf32(v0)),
                                               __uint_as_float(f2tf32(v1)));
                        *(float2*)(vout + (size_t)r * 512 + (col - 1024)) = o;
                    }
                } else {
                    *(float2*)(C + (size_t)r * N + col) = make_float2(v0, v1);
                }
            }
        }
    }
}

// ============================================================================
// K2: gating (unchanged)
// ============================================================================
__global__ __launch_bounds__(256) void gate_kernel(
    const float* __restrict__ x, const float* __restrict__ tw,
    const float* __restrict__ tb, float* __restrict__ gate)
{
    int row = blockIdx.x * 8 + (threadIdx.x >> 5);
    if (row >= MROWS) return;
    int lane = threadIdx.x & 31;
    const float* xr = x + (size_t)row * CC;
    float s0 = 0.f, s1 = 0.f, s2 = 0.f, s3 = 0.f;
    for (int c = lane; c < CC; c += 32) {
        float xv = xr[c];
        float4 w = *(const float4*)(tw + c * 4);
        s0 += xv * w.x; s1 += xv * w.y; s2 += xv * w.z; s3 += xv * w.w;
    }
    s0 = warp_sum(s0); s1 = warp_sum(s1); s2 = warp_sum(s2); s3 = warp_sum(s3);
    float l0 = s0 + tb[0], l1 = s1 + tb[1], l2 = s2 + tb[2], l3 = s3 + tb[3];
    float m = fmaxf(fmaxf(l0, l1), fmaxf(l2, l3));
    float e0 = __expf(l0 - m), e1 = __expf(l1 - m);
    float e2 = __expf(l2 - m), e3 = __expf(l3 - m);
    float inv = 1.f / (e0 + e1 + e2 + e3);
    if (lane == 0) {
        float4 o = make_float4(e0 * inv, e1 * inv, e2 * inv, e3 * inv);
        *(float4*)(gate + (size_t)row * 4) = o;
    }
}

// ============================================================================
// K3: attention. QK^T = bf16x3 on pre-split planes; all QK fragments via
// ldmatrix.x4. fp32 nested-window softmax + gate fold. PV = tf32 with
// LDSM A-fragments. 32-row tiles, grid (8, 544), 256 thr, 2 CTAs/SM.
// ============================================================================
#define QW  36    // Q/K pitch in bf16x2 WORDS
#define VP2 72
#define PP2 260
#define K3_SMEM_WORDS (2*32*QW + 2*2*64*QW + 2*32*VP2 + 32*PP2)
#define K3_SMEM_BYTES (K3_SMEM_WORDS * 4)   // 97792

__global__ __launch_bounds__(256, 2) void attn_tc2_kernel(
    const __nv_bfloat16* __restrict__ qkh, const __nv_bfloat16* __restrict__ qkl,
    const float* __restrict__ vsrc, const float* __restrict__ gate,
    float* __restrict__ eo)
{
    extern __shared__ float smf[];
    uint32_t* sQh = (uint32_t*)smf;            // [32][QW]
    uint32_t* sQl = sQh + 32 * QW;
    uint32_t* sKh = sQl + 32 * QW;             // [2][64][QW]
    uint32_t* sKl = sKh + 2 * 64 * QW;
    float*    sV  = (float*)(sKl + 2 * 64 * QW);   // [2][32][VP2]
    float*    sP  = sV + 2 * 32 * VP2;             // [32][PP2]

    const int tid  = threadIdx.x;
    const int warp = tid >> 5, lane = tid & 31;
    const int g    = lane >> 2, tig = lane & 3;
    const int wm   = warp & 1,  wn  = warp >> 1;   // 2m x 4n
    const int bid  = blockIdx.y;
    const int b = bid / (HH * NJ);
    const int h = (bid / NJ) % HH;
    const int n = bid % NJ;
    const int t0 = blockIdx.x * 32;
    const float scale = 0.125f;

    const uint32_t uQh = (uint32_t)__cvta_generic_to_shared(sQh);
    const uint32_t uQl = (uint32_t)__cvta_generic_to_shared(sQl);
    const uint32_t uKh = (uint32_t)__cvta_generic_to_shared(sKh);
    const uint32_t uKl = (uint32_t)__cvta_generic_to_shared(sKl);
    const uint32_t uP  = (uint32_t)__cvta_generic_to_shared(sP);

    // LDSM lane offsets (word units):
    // A-side (Q / P): row = wm*16 + (lane&15), col-word = (lane>>4)*4
    const uint32_t qa_off = (uint32_t)((wm * 16 + (lane & 15)) * QW + ((lane >> 4) * 4));
    const uint32_t pa_off = (uint32_t)((wm * 16 + (lane & 15)) * PP2 + ((lane >> 4) * 4));
    // B-side (K): row = wn*16 + ((lane>>4)<<3) + (lane&7), col-word = ((lane>>3)&1)*4
    // -> regs: r0=bh[0][0], r1=bh[0][1], r2=bh[1][0], r3=bh[1][1]
    const uint32_t kb_off = (uint32_t)((wn * 16 + ((lane >> 4) << 3) + (lane & 7)) * QW
                                       + (((lane >> 3) & 1) * 4));

    float4 gv = make_float4(0.f, 0.f, 0.f, 0.f);
    {
        int tg = t0 + warp * 4 + lane;
        if (lane < 4 && tg < TT)
            gv = *(const float4*)(gate + ((size_t)((b * TT + tg) * NJ + n)) * 4);
    }

    #define QKV_ROW(s) (((size_t)(b * TT + (s))) * NJ + n)

    // ---- group G0: Q hi/lo + K chunk 0 hi/lo ----
    {
        int r = tid >> 3, seg = tid & 7;
        int t = t0 + r;
        bool pr = t < TT;
        size_t qrow = QKV_ROW(pr ? t : 0);
        cp_async16(sQh + r * QW + seg * 4, qkh + qrow * 1024 + h * HD + seg * 8, pr);
        cp_async16(sQl + r * QW + seg * 4, qkl + qrow * 1024 + h * HD + seg * 8, pr);
        #pragma unroll
        for (int l = 0; l < 2; l++) {
            int li = tid + l * 256;
            int kr = li >> 3, ks = li & 7;
            bool kp = kr < TT;
            size_t krow = QKV_ROW(kp ? kr : 0);
            cp_async16(sKh + kr * QW + ks * 4, qkh + krow * 1024 + 512 + h * HD + ks * 8, kp);
            cp_async16(sKl + kr * QW + ks * 4, qkl + krow * 1024 + 512 + h * HD + ks * 8, kp);
        }
    }
    CP_COMMIT();
    // ---- group G1: V chunk 0 ----
    #pragma unroll
    for (int l = 0; l < 2; l++) {
        int li = tid + l * 256;
        int r = li >> 4, c4 = (li & 15) * 4;
        cp_async16(sV + r * VP2 + c4, vsrc + QKV_ROW(r) * 512 + h * HD + c4, true);
    }
    CP_COMMIT();

    // ---- QK^T over 4 s-chunks of 64, bf16x3, double-buffered K ----
    for (int c = 0; c < 4; c++) {
        if (c == 0) { CP_WAIT1(); } else { CP_WAIT0(); }
        __syncthreads();
        if (c < 3) {
            int s0 = 64 * (c + 1);
            uint32_t* khn = sKh + ((c + 1) & 1) * 64 * QW;
            uint32_t* kln = sKl + ((c + 1) & 1) * 64 * QW;
            #pragma unroll
            for (int l = 0; l < 2; l++) {
                int li = tid + l * 256;
                int kr = li >> 3, ks = li & 7;
                int s = s0 + kr;
                bool kp = s < TT;
                size_t krow = QKV_ROW(kp ? s : 0);
                cp_async16(khn + kr * QW + ks * 4, qkh + krow * 1024 + 512 + h * HD + ks * 8, kp);
                cp_async16(kln + kr * QW + ks * 4, qkl + krow * 1024 + 512 + h * HD + ks * 8, kp);
            }
            CP_COMMIT();
        }

        const uint32_t uKhc = uKh + (uint32_t)((c & 1) * 64 * QW) * 4u;
        const uint32_t uKlc = uKl + (uint32_t)((c & 1) * 64 * QW) * 4u;

        float acc[2][4];
        #pragma unroll
        for (int j = 0; j < 2; j++)
            #pragma unroll
            for (int f = 0; f < 4; f++) acc[j][f] = 0.f;

        #pragma unroll
        for (int ks = 0; ks < 32; ks += 8) {
            uint32_t ah[4], al[4], th[4], tl[4];
            ldsm4(ah, uQh + 4u * (qa_off + (uint32_t)ks));
            ldsm4(al, uQl + 4u * (qa_off + (uint32_t)ks));
            ldsm4(th, uKhc + 4u * (kb_off + (uint32_t)ks));
            ldsm4(tl, uKlc + 4u * (kb_off + (uint32_t)ks));
            uint32_t bh[2][2] = {{th[0], th[1]}, {th[2], th[3]}};
            uint32_t bl[2][2] = {{tl[0], tl[1]}, {tl[2], tl[3]}};
            #pragma unroll
            for (int nt = 0; nt < 2; nt++) {
                mma_m16n8k16_bf16(acc[nt], ah, bh[nt]);
                mma_m16n8k16_bf16(acc[nt], ah, bl[nt]);
                mma_m16n8k16_bf16(acc[nt], al, bh[nt]);
            }
        }

        int row = wm * 16 + g;
        #pragma unroll
        for (int nt = 0; nt < 2; nt++) {
            int col = c * 64 + wn * 16 + nt * 8 + 2 * tig;
            *(float2*)&sP[row * PP2 + col] =
                make_float2(acc[nt][0] * scale, acc[nt][1] * scale);
            *(float2*)&sP[(row + 8) * PP2 + col] =
                make_float2(acc[nt][2] * scale, acc[nt][3] * scale);
        }
    }
    __syncthreads();

    // ---- nested-window softmax + gate folding; write tf32 values ----
    for (int rr = 0; rr < 4; rr++) {
        int r = warp * 4 + rr;
        int t = t0 + r;
        if (t >= TT) break;
        float p[8];
        float m = -1e30f;
        #pragma unroll
        for (int i2 = 0; i2 < 8; i2++) {
            int s = lane + 32 * i2;
            float v = (s < TT) ? sP[r * PP2 + s] : -1e30f;
            p[i2] = v;
            m = fmaxf(m, v);
        }
        m = warp_max(m);
        int a9 = (t / 9) * 9, a27 = (t / 27) * 27, a81 = (t / 81) * 81;
        float z9 = 0.f, z27 = 0.f, z81 = 0.f, z243 = 0.f;
        #pragma unroll
        for (int i2 = 0; i2 < 8; i2++) {
            int s = lane + 32 * i2;
            float e = (s < TT) ? __expf(p[i2] - m) : 0.f;
            p[i2] = e;
            z243 += e;
            if (s >= a81 && s < a81 + 81) z81 += e;
            if (s >= a27 && s < a27 + 27) z27 += e;
            if (s >= a9  && s < a9  + 9)  z9  += e;
        }
        z9 = warp_sum(z9); z27 = warp_sum(z27);
        z81 = warp_sum(z81); z243 = warp_sum(z243);
        float w9   = __shfl_sync(0xffffffffu, gv.x, rr) / z9;
        float w27  = __shfl_sync(0xffffffffu, gv.y, rr) / z27;
        float w81  = __shfl_sync(0xffffffffu, gv.z, rr) / z81;
        float w243 = __shfl_sync(0xffffffffu, gv.w, rr) / z243;
        #pragma unroll
        for (int i2 = 0; i2 < 8; i2++) {
            int s = lane + 32 * i2;
            float val = 0.f;
            if (s < TT) {
                float cf = w243;
                if (s >= a81 && s < a81 + 81) cf += w81;
                if (s >= a27 && s < a27 + 27) cf += w27;
                if (s >= a9  && s < a9  + 9)  cf += w9;
                val = __uint_as_float(f2tf32(p[i2] * cf));
            }
            sP[r * PP2 + s] = val;
        }
    }
    // (PV loop's first wait+sync is the barrier before reading sP/sV)

    // ---- O = P V (tf32), LDSM A-fragments, double-buffered V ----
    float acc2[2][4];
    #pragma unroll
    for (int j = 0; j < 2; j++)
        #pragma unroll
        for (int f = 0; f < 4; f++) acc2[j][f] = 0.f;

    for (int c = 0; c < 8; c++) {
        CP_WAIT0();
        __syncthreads();
        if (c < 7) {
            int vc = 32 * (c + 1);
            float* vbn = sV + ((c + 1) & 1) * 32 * VP2;
            #pragma unroll
            for (int l = 0; l < 2; l++) {
                int li = tid + l * 256;
                int r = li >> 4, c4 = (li & 15) * 4;
                int s = vc + r;
                bool pr = s < TT;
                int ss = pr ? s : TT - 1;
                cp_async16(vbn + r * VP2 + c4, vsrc + QKV_ROW(ss) * 512 + h * HD + c4, pr);
            }
            CP_COMMIT();
        }

        const float* vb = sV + (c & 1) * 32 * VP2;
        int vc0 = c * 32;
        #pragma unroll
        for (int kk = 0; kk < 32; kk += 8) {
            uint32_t af[4];
            ldsm4(af, uP + 4u * (pa_off + (uint32_t)(vc0 + kk)));
            uint32_t bf[2][2];
            #pragma unroll
            for (int nt = 0; nt < 2; nt++) {
                int nc = wn * 16 + nt * 8 + g;
                bf[nt][0] = __float_as_uint(vb[(kk + tig)     * VP2 + nc]);
                bf[nt][1] = __float_as_uint(vb[(kk + tig + 4) * VP2 + nc]);
            }
            #pragma unroll
            for (int nt = 0; nt < 2; nt++)
                mma_m16n8k8(acc2[nt], af, bf[nt]);
        }
    }

    // ---- store O (tf32-rounded for K4) ----
    {
        int row = wm * 16 + g;
        #pragma unroll
        for (int nt = 0; nt < 2; nt++) {
            int col = wn * 16 + nt * 8 + 2 * tig;
            int t = t0 + row;
            if (t < TT) {
                *(float2*)(eo + QKV_ROW(t) * CC + h * HD + col) =
                    make_float2(__uint_as_float(f2tf32(acc2[nt][0])),
                                __uint_as_float(f2tf32(acc2[nt][1])));
            }
            if (t + 8 < TT) {
                *(float2*)(eo + QKV_ROW(t + 8) * CC + h * HD + col) =
                    make_float2(__uint_as_float(f2tf32(acc2[nt][2])),
                                __uint_as_float(f2tf32(acc2[nt][3])));
            }
        }
    }
    #undef QKV_ROW
}

// ============================================================================
extern "C" void kernel_launch(void* const* d_in, const int* in_sizes, int n_in,
                              void* d_out, int out_size)
{
    const float* x      = (const float*)d_in[0];
    const float* qkv_w  = (const float*)d_in[1];
    const float* proj_w = (const float*)d_in[2];
    const float* proj_b = (const float*)d_in[3];
    const float* te_w   = (const float*)d_in[4];
    const float* te_b   = (const float*)d_in[5];
    float* out = (float*)d_out;

    float *gate_p, *eo_p, *xtf_p, *w1_p, *w2_p, *v_p;
    __nv_bfloat16 *qkh_p, *qkl_p;
    cudaGetSymbolAddress((void**)&qkh_p,  g_qkh);
    cudaGetSymbolAddress((void**)&qkl_p,  g_qkl);
    cudaGetSymbolAddress((void**)&v_p,    g_v);
    cudaGetSymbolAddress((void**)&gate_p, g_gate);
    cudaGetSymbolAddress((void**)&eo_p,   g_eo);
    cudaGetSymbolAddress((void**)&xtf_p,  g_xtf);
    cudaGetSymbolAddress((void**)&w1_p,   g_w1);
    cudaGetSymbolAddress((void**)&w2_p,   g_w2);

    cudaFuncSetAttribute(attn_tc2_kernel, cudaFuncAttributeMaxDynamicSharedMemorySize,
                         K3_SMEM_BYTES);
    cudaFuncSetAttribute(gemm_tf32<false, true>,
                         cudaFuncAttributeMaxDynamicSharedMemorySize, GEMM_SMEM_BYTES);
    cudaFuncSetAttribute(gemm_tf32<true, false>,
                         cudaFuncAttributeMaxDynamicSharedMemorySize, GEMM_SMEM_BYTES);

    // K0: round x, qkv_w, proj_w to tf32 once
    cvt_tf32_kernel<<<592, 256>>>(x, xtf_p, MROWS * CC / 4);
    cvt_tf32_kernel<<<148, 256>>>(qkv_w, w1_p, CC * NQKV / 4);
    cvt_tf32_kernel<<<148, 256>>>(proj_w, w2_p, CC * CC / 4);

    // K1: qkv = x @ qkv_w — q/k bf16 hi/lo planes, v tf32 plane
    gemm_tf32<false, true><<<dim3(NQKV / 128, (MROWS + 127) / 128), 256, GEMM_SMEM_BYTES>>>(
        xtf_p, w1_p, nullptr, nullptr, qkh_p, qkl_p, v_p, MROWS, NQKV, CC);

    // K2: gate = softmax(x @ te_w + te_b)
    gate_kernel<<<(MROWS + 7) / 8, 256>>>(x, te_w, te_b, gate_p);

    // K3: 2-CTA/SM attention, bf16x3 QK^T, LDSM fragments
    attn_tc2_kernel<<<dim3(8, BB * HH * NJ), 256, K3_SMEM_BYTES>>>(
        qkh_p, qkl_p, v_p, gate_p, eo_p);

    // K4: out = eo @ proj_w + proj_b
    gemm_tf32<true, false><<<dim3(CC / 128, (MROWS + 127) / 128), 256, GEMM_SMEM_BYTES>>>(
        eo_p, w2_p, proj_b, out, nullptr, nullptr, nullptr, MROWS, CC, CC);
}

// round 15
// speedup vs baseline: 1.9127x; 1.0055x over previous
#include <cuda_runtime.h>
#include <cuda_bf16.h>
#include <cstdint>
#include <cstddef>

#define TT    243
#define NJ    17
#define BB    4
#define HH    8
#define HD    64
#define CC    512
#define EE    4
#define MROWS (BB*TT*NJ)   // 16524
#define NQKV  1536

// ---- scratch (static device globals; no allocations allowed) ----
__device__ __nv_bfloat16 g_qkh[(size_t)MROWS * 1024];  // q|k hi (bf16)
__device__ __nv_bfloat16 g_qkl[(size_t)MROWS * 1024];  // q|k lo (bf16)
__device__ float g_v[(size_t)MROWS * 512];             // v (tf32-valued fp32)
__device__ float g_gate[(size_t)MROWS * EE];
__device__ float g_eo[(size_t)MROWS * CC];             // tf32-valued
__device__ float g_xtf[(size_t)MROWS * CC];
__device__ float g_w1t[(size_t)NQKV * CC];             // w1^T, tf32-valued
__device__ float g_w2t[(size_t)CC * CC];               // w2^T, tf32-valued

static __device__ __forceinline__ float warp_sum(float v) {
    #pragma unroll
    for (int o = 16; o; o >>= 1) v += __shfl_xor_sync(0xffffffffu, v, o);
    return v;
}
static __device__ __forceinline__ float warp_max(float v) {
    #pragma unroll
    for (int o = 16; o; o >>= 1) v = fmaxf(v, __shfl_xor_sync(0xffffffffu, v, o));
    return v;
}

static __device__ __forceinline__ uint32_t f2tf32(float x) {
    uint32_t r;
    asm("cvt.rna.tf32.f32 %0, %1;" : "=r"(r) : "f"(x));
    return r;
}

static __device__ __forceinline__ void mma_m16n8k8(
    float* c, const uint32_t* a, const uint32_t* b)
{
    asm volatile(
        "mma.sync.aligned.m16n8k8.row.col.f32.tf32.tf32.f32 "
        "{%0,%1,%2,%3}, {%4,%5,%6,%7}, {%8,%9}, {%0,%1,%2,%3};\n"
        : "+f"(c[0]), "+f"(c[1]), "+f"(c[2]), "+f"(c[3])
        : "r"(a[0]), "r"(a[1]), "r"(a[2]), "r"(a[3]),
          "r"(b[0]), "r"(b[1]));
}

static __device__ __forceinline__ void mma_m16n8k16_bf16(
    float* c, const uint32_t* a, const uint32_t* b)
{
    asm volatile(
        "mma.sync.aligned.m16n8k16.row.col.f32.bf16.bf16.f32 "
        "{%0,%1,%2,%3}, {%4,%5,%6,%7}, {%8,%9}, {%0,%1,%2,%3};\n"
        : "+f"(c[0]), "+f"(c[1]), "+f"(c[2]), "+f"(c[3])
        : "r"(a[0]), "r"(a[1]), "r"(a[2]), "r"(a[3]),
          "r"(b[0]), "r"(b[1]));
}

static __device__ __forceinline__ void ldsm4(uint32_t* r, uint32_t addr) {
    asm volatile("ldmatrix.sync.aligned.m8n8.x4.shared.b16 {%0,%1,%2,%3}, [%4];"
                 : "=r"(r[0]), "=r"(r[1]), "=r"(r[2]), "=r"(r[3]) : "r"(addr));
}

static __device__ __forceinline__ void cp_async16(void* dst_smem, const void* src, bool pred) {
    uint32_t daddr = (uint32_t)__cvta_generic_to_shared(dst_smem);
    int sz = pred ? 16 : 0;
    asm volatile("cp.async.cg.shared.global [%0], [%1], 16, %2;\n"
                 :: "r"(daddr), "l"(src), "r"(sz));
}
#define CP_COMMIT() asm volatile("cp.async.commit_group;\n" ::: "memory")
#define CP_WAIT0()  asm volatile("cp.async.wait_group 0;\n" ::: "memory")
#define CP_WAIT1()  asm volatile("cp.async.wait_group 1;\n" ::: "memory")

// ============================================================================
// K0a: elementwise tf32 rounding (x)
// ============================================================================
__global__ __launch_bounds__(256) void cvt_tf32_kernel(
    const float* __restrict__ src, float* __restrict__ dst, int n4)
{
    int i = blockIdx.x * 256 + threadIdx.x;
    int stride = gridDim.x * 256;
    for (; i < n4; i += stride) {
        float4 v = ((const float4*)src)[i];
        uint4 o;
        o.x = f2tf32(v.x); o.y = f2tf32(v.y);
        o.z = f2tf32(v.z); o.w = f2tf32(v.w);
        ((uint4*)dst)[i] = o;
    }
}

// ============================================================================
// K0b: cvt+transpose — src[R][C] -> dst[C][R], tf32-rounded. R,C % 32 == 0.
// ============================================================================
__global__ __launch_bounds__(256) void cvt_transpose_kernel(
    const float* __restrict__ src, float* __restrict__ dst, int R, int C)
{
    __shared__ float tile[32][33];
    int c0 = blockIdx.x * 32, r0 = blockIdx.y * 32;
    int tx = threadIdx.x & 31, ty = threadIdx.x >> 5;   // 32 x 8
    #pragma unroll
    for (int i = 0; i < 32; i += 8)
        tile[ty + i][tx] = src[(size_t)(r0 + ty + i) * C + c0 + tx];
    __syncthreads();
    #pragma unroll
    for (int i = 0; i < 32; i += 8)
        dst[(size_t)(c0 + ty + i) * R + r0 + tx] =
            __uint_as_float(f2tf32(tile[tx][ty + i]));
}

// ============================================================================
// K1/K4: tf32 tensor-core GEMM, BK=32, single-sync cp.async pipeline.
// B pre-transposed (Bt[N][K], tf32-valued): ALL fragments via ldmatrix.x4.
// Per iter/warp: 24 LDSM + 64 mma, zero scalar LDS.
// SPLIT (K1): q/k cols -> bf16 hi/lo planes; v cols -> tf32 fp32.
// ============================================================================
#define AP 36
#define GEMM_SMEM_BYTES (4 * 128 * AP * 4)   // 73728 (2 bufs A + 2 bufs Bt)

template <bool BIAS, bool SPLIT>
__global__ __launch_bounds__(256, 2) void gemm_tf32(
    const float* __restrict__ A, const float* __restrict__ Bt,
    const float* __restrict__ bias, float* __restrict__ C,
    __nv_bfloat16* __restrict__ qkh, __nv_bfloat16* __restrict__ qkl,
    float* __restrict__ vout, int M, int N, int K)
{
    extern __shared__ float smg[];
    float* As = smg;                   // [2][128*AP]
    float* Bs = smg + 2 * 128 * AP;    // [2][128*AP]  (Bt tiles)

    const int tid  = threadIdx.x;
    const int warp = tid >> 5, lane = tid & 31;
    const int g    = lane >> 2, tig = lane & 3;
    const int wm   = warp & 1,  wn  = warp >> 1;
    const int m0   = blockIdx.y * 128, n0 = blockIdx.x * 128;

    const uint32_t sA0 = (uint32_t)__cvta_generic_to_shared(As);
    const uint32_t sB0 = (uint32_t)__cvta_generic_to_shared(Bs);
    // A-side LDSM offset: row = wm*64 + (lane&15), col-word = (lane>>4)*4
    const uint32_t a_off = (uint32_t)((wm * 64 + (lane & 15)) * AP + ((lane >> 4) * 4));
    // B-side LDSM offset (pair p adds p*16*AP):
    // row = wn*32 + ((lane>>4)&1)*8 + (lane&7), col-word = ((lane>>3)&1)*4
    const uint32_t b_off = (uint32_t)((wn * 32 + ((lane >> 4) & 1) * 8 + (lane & 7)) * AP
                                      + (((lane >> 3) & 1) * 4));

    float c[4][4][4];
    #pragma unroll
    for (int i = 0; i < 4; i++)
        #pragma unroll
        for (int j = 0; j < 4; j++)
            #pragma unroll
            for (int f = 0; f < 4; f++) c[i][j][f] = 0.f;

    const int niter = K / 32;

    #define GEMM_STAGE(IT, BUF) do {                                          \
        int k0s = (IT) * 32;                                                  \
        float* ab = As + (BUF) * 128 * AP;                                    \
        float* bb = Bs + (BUF) * 128 * AP;                                    \
        _Pragma("unroll")                                                     \
        for (int l = 0; l < 4; l++) {                                         \
            int li = tid + l * 256;                                           \
            int r = li >> 3, c4 = (li & 7) * 4;                               \
            bool pr = (m0 + r) < M;                                           \
            int gr = pr ? (m0 + r) : (M - 1);                                 \
            cp_async16(&ab[r * AP + c4], A + (size_t)gr * K + k0s + c4, pr);  \
            cp_async16(&bb[r * AP + c4],                                      \
                       Bt + (size_t)(n0 + r) * K + k0s + c4, true);           \
        }                                                                     \
        CP_COMMIT();                                                          \
    } while (0)

    GEMM_STAGE(0, 0);

    for (int it = 0; it < niter; it++) {
        int cur = it & 1;
        CP_WAIT0();
        __syncthreads();
        if (it + 1 < niter) GEMM_STAGE(it + 1, cur ^ 1);

        const uint32_t sAcur = sA0 + (uint32_t)(cur * 128 * AP) * 4u;
        const uint32_t sBcur = sB0 + (uint32_t)(cur * 128 * AP) * 4u;
        #pragma unroll
        for (int kk = 0; kk < 32; kk += 8) {
            uint32_t af[4][4];
            #pragma unroll
            for (int mt = 0; mt < 4; mt++)
                ldsm4(af[mt], sAcur + 4u * (a_off + (uint32_t)(mt * 16 * AP + kk)));
            uint32_t bf[4][2];
            #pragma unroll
            for (int p = 0; p < 2; p++) {
                uint32_t t[4];
                ldsm4(t, sBcur + 4u * (b_off + (uint32_t)(p * 16 * AP + kk)));
                bf[2 * p][0]     = t[0]; bf[2 * p][1]     = t[1];
                bf[2 * p + 1][0] = t[2]; bf[2 * p + 1][1] = t[3];
            }
            #pragma unroll
            for (int mt = 0; mt < 4; mt++)
                #pragma unroll
                for (int nt = 0; nt < 4; nt++)
                    mma_m16n8k8(c[mt][nt], af[mt], bf[nt]);
        }
    }
    #undef GEMM_STAGE

    #pragma unroll
    for (int mt = 0; mt < 4; mt++) {
        int row0 = m0 + wm * 64 + mt * 16 + g;
        #pragma unroll
        for (int nt = 0; nt < 4; nt++) {
            int col = n0 + wn * 32 + nt * 8 + 2 * tig;
            float b0 = 0.f, b1 = 0.f;
            if (BIAS) { b0 = bias[col]; b1 = bias[col + 1]; }
            #pragma unroll
            for (int half = 0; half < 2; half++) {
                int r = row0 + half * 8;
                if (r >= M) continue;
                float v0 = c[mt][nt][half * 2 + 0] + b0;
                float v1 = c[mt][nt][half * 2 + 1] + b1;
                if (SPLIT) {
                    if (col < 1024) {
                        __nv_bfloat16 h0 = __float2bfloat16(v0);
                        __nv_bfloat16 h1 = __float2bfloat16(v1);
                        __nv_bfloat16 l0 = __float2bfloat16(v0 - __bfloat162float(h0));
                        __nv_bfloat16 l1 = __float2bfloat16(v1 - __bfloat162float(h1));
                        *(__nv_bfloat162*)(qkh + (size_t)r * 1024 + col) =
                            __halves2bfloat162(h0, h1);
                        *(__nv_bfloat162*)(qkl + (size_t)r * 1024 + col) =
                            __halves2bfloat162(l0, l1);
                    } else {
                        float2 o = make_float2(__uint_as_float(f2tf32(v0)),
                                               __uint_as_float(f2tf32(v1)));
                        *(float2*)(vout + (size_t)r * 512 + (col - 1024)) = o;
                    }
                } else {
                    *(float2*)(C + (size_t)r * N + col) = make_float2(v0, v1);
                }
            }
        }
    }
}

// ============================================================================
// K2: gating (unchanged)
// ============================================================================
__global__ __launch_bounds__(256) void gate_kernel(
    const float* __restrict__ x, const float* __restrict__ tw,
    const float* __restrict__ tb, float* __restrict__ gate)
{
    int row = blockIdx.x * 8 + (threadIdx.x >> 5);
    if (row >= MROWS) return;
    int lane = threadIdx.x & 31;
    const float* xr = x + (size_t)row * CC;
    float s0 = 0.f, s1 = 0.f, s2 = 0.f, s3 = 0.f;
    for (int c = lane; c < CC; c += 32) {
        float xv = xr[c];
        float4 w = *(const float4*)(tw + c * 4);
        s0 += xv * w.x; s1 += xv * w.y; s2 += xv * w.z; s3 += xv * w.w;
    }
    s0 = warp_sum(s0); s1 = warp_sum(s1); s2 = warp_sum(s2); s3 = warp_sum(s3);
    float l0 = s0 + tb[0], l1 = s1 + tb[1], l2 = s2 + tb[2], l3 = s3 + tb[3];
    float m = fmaxf(fmaxf(l0, l1), fmaxf(l2, l3));
    float e0 = __expf(l0 - m), e1 = __expf(l1 - m);
    float e2 = __expf(l2 - m), e3 = __expf(l3 - m);
    float inv = 1.f / (e0 + e1 + e2 + e3);
    if (lane == 0) {
        float4 o = make_float4(e0 * inv, e1 * inv, e2 * inv, e3 * inv);
        *(float4*)(gate + (size_t)row * 4) = o;
    }
}

// ============================================================================
// K3: attention (unchanged from R13). bf16x3 QK^T + LDSM, tf32 PV.
// ============================================================================
#define QW  36
#define VP2 72
#define PP2 260
#define K3_SMEM_WORDS (2*32*QW + 2*2*64*QW + 2*32*VP2 + 32*PP2)
#define K3_SMEM_BYTES (K3_SMEM_WORDS * 4)   // 97792

__global__ __launch_bounds__(256, 2) void attn_tc2_kernel(
    const __nv_bfloat16* __restrict__ qkh, const __nv_bfloat16* __restrict__ qkl,
    const float* __restrict__ vsrc, const float* __restrict__ gate,
    float* __restrict__ eo)
{
    extern __shared__ float smf[];
    uint32_t* sQh = (uint32_t*)smf;
    uint32_t* sQl = sQh + 32 * QW;
    uint32_t* sKh = sQl + 32 * QW;
    uint32_t* sKl = sKh + 2 * 64 * QW;
    float*    sV  = (float*)(sKl + 2 * 64 * QW);
    float*    sP  = sV + 2 * 32 * VP2;

    const int tid  = threadIdx.x;
    const int warp = tid >> 5, lane = tid & 31;
    const int g    = lane >> 2, tig = lane & 3;
    const int wm   = warp & 1,  wn  = warp >> 1;
    const int bid  = blockIdx.y;
    const int b = bid / (HH * NJ);
    const int h = (bid / NJ) % HH;
    const int n = bid % NJ;
    const int t0 = blockIdx.x * 32;
    const float scale = 0.125f;

    const uint32_t uQh = (uint32_t)__cvta_generic_to_shared(sQh);
    const uint32_t uQl = (uint32_t)__cvta_generic_to_shared(sQl);
    const uint32_t uKh = (uint32_t)__cvta_generic_to_shared(sKh);
    const uint32_t uKl = (uint32_t)__cvta_generic_to_shared(sKl);
    const uint32_t uP  = (uint32_t)__cvta_generic_to_shared(sP);

    const uint32_t qa_off = (uint32_t)((wm * 16 + (lane & 15)) * QW + ((lane >> 4) * 4));
    const uint32_t pa_off = (uint32_t)((wm * 16 + (lane & 15)) * PP2 + ((lane >> 4) * 4));
    const uint32_t kb_off = (uint32_t)((wn * 16 + ((lane >> 4) << 3) + (lane & 7)) * QW
                                       + (((lane >> 3) & 1) * 4));

    float4 gv = make_float4(0.f, 0.f, 0.f, 0.f);
    {
        int tg = t0 + warp * 4 + lane;
        if (lane < 4 && tg < TT)
            gv = *(const float4*)(gate + ((size_t)((b * TT + tg) * NJ + n)) * 4);
    }

    #define QKV_ROW(s) (((size_t)(b * TT + (s))) * NJ + n)

    {
        int r = tid >> 3, seg = tid & 7;
        int t = t0 + r;
        bool pr = t < TT;
        size_t qrow = QKV_ROW(pr ? t : 0);
        cp_async16(sQh + r * QW + seg * 4, qkh + qrow * 1024 + h * HD + seg * 8, pr);
        cp_async16(sQl + r * QW + seg * 4, qkl + qrow * 1024 + h * HD + seg * 8, pr);
        #pragma unroll
        for (int l = 0; l < 2; l++) {
            int li = tid + l * 256;
            int kr = li >> 3, ks = li & 7;
            bool kp = kr < TT;
            size_t krow = QKV_ROW(kp ? kr : 0);
            cp_async16(sKh + kr * QW + ks * 4, qkh + krow * 1024 + 512 + h * HD + ks * 8, kp);
            cp_async16(sKl + kr * QW + ks * 4, qkl + krow * 1024 + 512 + h * HD + ks * 8, kp);
        }
    }
    CP_COMMIT();
    #pragma unroll
    for (int l = 0; l < 2; l++) {
        int li = tid + l * 256;
        int r = li >> 4, c4 = (li & 15) * 4;
        cp_async16(sV + r * VP2 + c4, vsrc + QKV_ROW(r) * 512 + h * HD + c4, true);
    }
    CP_COMMIT();

    for (int c = 0; c < 4; c++) {
        if (c == 0) { CP_WAIT1(); } else { CP_WAIT0(); }
        __syncthreads();
        if (c < 3) {
            int s0 = 64 * (c + 1);
            uint32_t* khn = sKh + ((c + 1) & 1) * 64 * QW;
            uint32_t* kln = sKl + ((c + 1) & 1) * 64 * QW;
            #pragma unroll
            for (int l = 0; l < 2; l++) {
                int li = tid + l * 256;
                int kr = li >> 3, ks = li & 7;
                int s = s0 + kr;
                bool kp = s < TT;
                size_t krow = QKV_ROW(kp ? s : 0);
                cp_async16(khn + kr * QW + ks * 4, qkh + krow * 1024 + 512 + h * HD + ks * 8, kp);
                cp_async16(kln + kr * QW + ks * 4, qkl + krow * 1024 + 512 + h * HD + ks * 8, kp);
            }
            CP_COMMIT();
        }

        const uint32_t uKhc = uKh + (uint32_t)((c & 1) * 64 * QW) * 4u;
        const uint32_t uKlc = uKl + (uint32_t)((c & 1) * 64 * QW) * 4u;

        float acc[2][4];
        #pragma unroll
        for (int j = 0; j < 2; j++)
            #pragma unroll
            for (int f = 0; f < 4; f++) acc[j][f] = 0.f;

        #pragma unroll
        for (int ks = 0; ks < 32; ks += 8) {
            uint32_t ah[4], al[4], th[4], tl[4];
            ldsm4(ah, uQh + 4u * (qa_off + (uint32_t)ks));
            ldsm4(al, uQl + 4u * (qa_off + (uint32_t)ks));
            ldsm4(th, uKhc + 4u * (kb_off + (uint32_t)ks));
            ldsm4(tl, uKlc + 4u * (kb_off + (uint32_t)ks));
            uint32_t bh[2][2] = {{th[0], th[1]}, {th[2], th[3]}};
            uint32_t bl[2][2] = {{tl[0], tl[1]}, {tl[2], tl[3]}};
            #pragma unroll
            for (int nt = 0; nt < 2; nt++) {
                mma_m16n8k16_bf16(acc[nt], ah, bh[nt]);
                mma_m16n8k16_bf16(acc[nt], ah, bl[nt]);
                mma_m16n8k16_bf16(acc[nt], al, bh[nt]);
            }
        }

        int row = wm * 16 + g;
        #pragma unroll
        for (int nt = 0; nt < 2; nt++) {
            int col = c * 64 + wn * 16 + nt * 8 + 2 * tig;
            *(float2*)&sP[row * PP2 + col] =
                make_float2(acc[nt][0] * scale, acc[nt][1] * scale);
            *(float2*)&sP[(row + 8) * PP2 + col] =
                make_float2(acc[nt][2] * scale, acc[nt][3] * scale);
        }
    }
    __syncthreads();

    for (int rr = 0; rr < 4; rr++) {
        int r = warp * 4 + rr;
        int t = t0 + r;
        if (t >= TT) break;
        float p[8];
        float m = -1e30f;
        #pragma unroll
        for (int i2 = 0; i2 < 8; i2++) {
            int s = lane + 32 * i2;
            float v = (s < TT) ? sP[r * PP2 + s] : -1e30f;
            p[i2] = v;
            m = fmaxf(m, v);
        }
        m = warp_max(m);
        int a9 = (t / 9) * 9, a27 = (t / 27) * 27, a81 = (t / 81) * 81;
        float z9 = 0.f, z27 = 0.f, z81 = 0.f, z243 = 0.f;
        #pragma unroll
        for (int i2 = 0; i2 < 8; i2++) {
            int s = lane + 32 * i2;
            float e = (s < TT) ? __expf(p[i2] - m) : 0.f;
            p[i2] = e;
            z243 += e;
            if (s >= a81 && s < a81 + 81) z81 += e;
            if (s >= a27 && s < a27 + 27) z27 += e;
            if (s >= a9  && s < a9  + 9)  z9  += e;
        }
        z9 = warp_sum(z9); z27 = warp_sum(z27);
        z81 = warp_sum(z81); z243 = warp_sum(z243);
        float w9   = __shfl_sync(0xffffffffu, gv.x, rr) / z9;
        float w27  = __shfl_sync(0xffffffffu, gv.y, rr) / z27;
        float w81  = __shfl_sync(0xffffffffu, gv.z, rr) / z81;
        float w243 = __shfl_sync(0xffffffffu, gv.w, rr) / z243;
        #pragma unroll
        for (int i2 = 0; i2 < 8; i2++) {
            int s = lane + 32 * i2;
            float val = 0.f;
            if (s < TT) {
                float cf = w243;
                if (s >= a81 && s < a81 + 81) cf += w81;
                if (s >= a27 && s < a27 + 27) cf += w27;
                if (s >= a9  && s < a9  + 9)  cf += w9;
                val = __uint_as_float(f2tf32(p[i2] * cf));
            }
            sP[r * PP2 + s] = val;
        }
    }

    float acc2[2][4];
    #pragma unroll
    for (int j = 0; j < 2; j++)
        #pragma unroll
        for (int f = 0; f < 4; f++) acc2[j][f] = 0.f;

    for (int c = 0; c < 8; c++) {
        CP_WAIT0();
        __syncthreads();
        if (c < 7) {
            int vc = 32 * (c + 1);
            float* vbn = sV + ((c + 1) & 1) * 32 * VP2;
            #pragma unroll
            for (int l = 0; l < 2; l++) {
                int li = tid + l * 256;
                int r = li >> 4, c4 = (li & 15) * 4;
                int s = vc + r;
                bool pr = s < TT;
                int ss = pr ? s : TT - 1;
                cp_async16(vbn + r * VP2 + c4, vsrc + QKV_ROW(ss) * 512 + h * HD + c4, pr);
            }
            CP_COMMIT();
        }

        const float* vb = sV + (c & 1) * 32 * VP2;
        int vc0 = c * 32;
        #pragma unroll
        for (int kk = 0; kk < 32; kk += 8) {
            uint32_t af[4];
            ldsm4(af, uP + 4u * (pa_off + (uint32_t)(vc0 + kk)));
            uint32_t bf[2][2];
            #pragma unroll
            for (int nt = 0; nt < 2; nt++) {
                int nc = wn * 16 + nt * 8 + g;
                bf[nt][0] = __float_as_uint(vb[(kk + tig)     * VP2 + nc]);
                bf[nt][1] = __float_as_uint(vb[(kk + tig + 4) * VP2 + nc]);
            }
            #pragma unroll
            for (int nt = 0; nt < 2; nt++)
                mma_m16n8k8(acc2[nt], af, bf[nt]);
        }
    }

    {
        int row = wm * 16 + g;
        #pragma unroll
        for (int nt = 0; nt < 2; nt++) {
            int col = wn * 16 + nt * 8 + 2 * tig;
            int t = t0 + row;
            if (t < TT) {
                *(float2*)(eo + QKV_ROW(t) * CC + h * HD + col) =
                    make_float2(__uint_as_float(f2tf32(acc2[nt][0])),
                                __uint_as_float(f2tf32(acc2[nt][1])));
            }
            if (t + 8 < TT) {
                *(float2*)(eo + QKV_ROW(t + 8) * CC + h * HD + col) =
                    make_float2(__uint_as_float(f2tf32(acc2[nt][2])),
                                __uint_as_float(f2tf32(acc2[nt][3])));
            }
        }
    }
    #undef QKV_ROW
}

// ============================================================================
extern "C" void kernel_launch(void* const* d_in, const int* in_sizes, int n_in,
                              void* d_out, int out_size)
{
    const float* x      = (const float*)d_in[0];
    const float* qkv_w  = (const float*)d_in[1];
    const float* proj_w = (const float*)d_in[2];
    const float* proj_b = (const float*)d_in[3];
    const float* te_w   = (const float*)d_in[4];
    const float* te_b   = (const float*)d_in[5];
    float* out = (float*)d_out;

    float *gate_p, *eo_p, *xtf_p, *w1t_p, *w2t_p, *v_p;
    __nv_bfloat16 *qkh_p, *qkl_p;
    cudaGetSymbolAddress((void**)&qkh_p,  g_qkh);
    cudaGetSymbolAddress((void**)&qkl_p,  g_qkl);
    cudaGetSymbolAddress((void**)&v_p,    g_v);
    cudaGetSymbolAddress((void**)&gate_p, g_gate);
    cudaGetSymbolAddress((void**)&eo_p,   g_eo);
    cudaGetSymbolAddress((void**)&xtf_p,  g_xtf);
    cudaGetSymbolAddress((void**)&w1t_p,  g_w1t);
    cudaGetSymbolAddress((void**)&w2t_p,  g_w2t);

    cudaFuncSetAttribute(attn_tc2_kernel, cudaFuncAttributeMaxDynamicSharedMemorySize,
                         K3_SMEM_BYTES);
    cudaFuncSetAttribute(gemm_tf32<false, true>,
                         cudaFuncAttributeMaxDynamicSharedMemorySize, GEMM_SMEM_BYTES);
    cudaFuncSetAttribute(gemm_tf32<true, false>,
                         cudaFuncAttributeMaxDynamicSharedMemorySize, GEMM_SMEM_BYTES);

    // K0: round x; round+transpose w1, w2 (n-major for LDSM B-fragments)
    cvt_tf32_kernel<<<592, 256>>>(x, xtf_p, MROWS * CC / 4);
    cvt_transpose_kernel<<<dim3(NQKV / 32, CC / 32), 256>>>(qkv_w, w1t_p, CC, NQKV);
    cvt_transpose_kernel<<<dim3(CC / 32, CC / 32), 256>>>(proj_w, w2t_p, CC, CC);

    // K1: qkv = x @ qkv_w — q/k bf16 hi/lo planes, v tf32 plane
    gemm_tf32<false, true><<<dim3(NQKV / 128, (MROWS + 127) / 128), 256, GEMM_SMEM_BYTES>>>(
        xtf_p, w1t_p, nullptr, nullptr, qkh_p, qkl_p, v_p, MROWS, NQKV, CC);

    // K2: gate = softmax(x @ te_w + te_b)
    gate_kernel<<<(MROWS + 7) / 8, 256>>>(x, te_w, te_b, gate_p);

    // K3: 2-CTA/SM attention, bf16x3 QK^T, LDSM fragments
    attn_tc2_kernel<<<dim3(8, BB * HH * NJ), 256, K3_SMEM_BYTES>>>(
        qkh_p, qkl_p, v_p, gate_p, eo_p);

    // K4: out = eo @ proj_w + proj_b
    gemm_tf32<true, false><<<dim3(CC / 128, (MROWS + 127) / 128), 256, GEMM_SMEM_BYTES>>>(
        eo_p, w2t_p, proj_b, out, nullptr, nullptr, nullptr, MROWS, CC, CC);
}

// round 16
// speedup vs baseline: 1.9186x; 1.0031x over previous
#include <cuda_runtime.h>
#include <cuda_bf16.h>
#include <cstdint>
#include <cstddef>

#define TT    243
#define NJ    17
#define BB    4
#define HH    8
#define HD    64
#define CC    512
#define EE    4
#define MROWS (BB*TT*NJ)   // 16524
#define NQKV  1536

// ---- scratch (static device globals; no allocations allowed) ----
__device__ __nv_bfloat16 g_qkh[(size_t)MROWS * 1024];  // q|k hi (bf16)
__device__ __nv_bfloat16 g_qkl[(size_t)MROWS * 1024];  // q|k lo (bf16)
__device__ float g_v[(size_t)MROWS * 512];             // v (tf32-valued fp32)
__device__ float g_gate[(size_t)MROWS * EE];
__device__ float g_eo[(size_t)MROWS * CC];             // tf32-valued
__device__ float g_xtf[(size_t)MROWS * CC];
__device__ float g_w1t[(size_t)NQKV * CC];             // w1^T, tf32-valued
__device__ float g_w2t[(size_t)CC * CC];               // w2^T, tf32-valued

static __device__ __forceinline__ float warp_sum(float v) {
    #pragma unroll
    for (int o = 16; o; o >>= 1) v += __shfl_xor_sync(0xffffffffu, v, o);
    return v;
}
static __device__ __forceinline__ float warp_max(float v) {
    #pragma unroll
    for (int o = 16; o; o >>= 1) v = fmaxf(v, __shfl_xor_sync(0xffffffffu, v, o));
    return v;
}

static __device__ __forceinline__ uint32_t f2tf32(float x) {
    uint32_t r;
    asm("cvt.rna.tf32.f32 %0, %1;" : "=r"(r) : "f"(x));
    return r;
}

static __device__ __forceinline__ void mma_m16n8k8(
    float* c, const uint32_t* a, const uint32_t* b)
{
    asm volatile(
        "mma.sync.aligned.m16n8k8.row.col.f32.tf32.tf32.f32 "
        "{%0,%1,%2,%3}, {%4,%5,%6,%7}, {%8,%9}, {%0,%1,%2,%3};\n"
        : "+f"(c[0]), "+f"(c[1]), "+f"(c[2]), "+f"(c[3])
        : "r"(a[0]), "r"(a[1]), "r"(a[2]), "r"(a[3]),
          "r"(b[0]), "r"(b[1]));
}

static __device__ __forceinline__ void mma_m16n8k16_bf16(
    float* c, const uint32_t* a, const uint32_t* b)
{
    asm volatile(
        "mma.sync.aligned.m16n8k16.row.col.f32.bf16.bf16.f32 "
        "{%0,%1,%2,%3}, {%4,%5,%6,%7}, {%8,%9}, {%0,%1,%2,%3};\n"
        : "+f"(c[0]), "+f"(c[1]), "+f"(c[2]), "+f"(c[3])
        : "r"(a[0]), "r"(a[1]), "r"(a[2]), "r"(a[3]),
          "r"(b[0]), "r"(b[1]));
}

static __device__ __forceinline__ void ldsm4(uint32_t* r, uint32_t addr) {
    asm volatile("ldmatrix.sync.aligned.m8n8.x4.shared.b16 {%0,%1,%2,%3}, [%4];"
                 : "=r"(r[0]), "=r"(r[1]), "=r"(r[2]), "=r"(r[3]) : "r"(addr));
}

static __device__ __forceinline__ void cp_async16(void* dst_smem, const void* src, bool pred) {
    uint32_t daddr = (uint32_t)__cvta_generic_to_shared(dst_smem);
    int sz = pred ? 16 : 0;
    asm volatile("cp.async.cg.shared.global [%0], [%1], 16, %2;\n"
                 :: "r"(daddr), "l"(src), "r"(sz));
}
#define CP_COMMIT() asm volatile("cp.async.commit_group;\n" ::: "memory")
#define CP_WAIT0()  asm volatile("cp.async.wait_group 0;\n" ::: "memory")
#define CP_WAIT1()  asm volatile("cp.async.wait_group 1;\n" ::: "memory")

// ============================================================================
// K0a: elementwise tf32 rounding (x)
// ============================================================================
__global__ __launch_bounds__(256) void cvt_tf32_kernel(
    const float* __restrict__ src, float* __restrict__ dst, int n4)
{
    int i = blockIdx.x * 256 + threadIdx.x;
    int stride = gridDim.x * 256;
    for (; i < n4; i += stride) {
        float4 v = ((const float4*)src)[i];
        uint4 o;
        o.x = f2tf32(v.x); o.y = f2tf32(v.y);
        o.z = f2tf32(v.z); o.w = f2tf32(v.w);
        ((uint4*)dst)[i] = o;
    }
}

// ============================================================================
// K0b: cvt+transpose — src[R][C] -> dst[C][R], tf32-rounded. R,C % 32 == 0.
// ============================================================================
__global__ __launch_bounds__(256) void cvt_transpose_kernel(
    const float* __restrict__ src, float* __restrict__ dst, int R, int C)
{
    __shared__ float tile[32][33];
    int c0 = blockIdx.x * 32, r0 = blockIdx.y * 32;
    int tx = threadIdx.x & 31, ty = threadIdx.x >> 5;   // 32 x 8
    #pragma unroll
    for (int i = 0; i < 32; i += 8)
        tile[ty + i][tx] = src[(size_t)(r0 + ty + i) * C + c0 + tx];
    __syncthreads();
    #pragma unroll
    for (int i = 0; i < 32; i += 8)
        dst[(size_t)(c0 + ty + i) * R + r0 + tx] =
            __uint_as_float(f2tf32(tile[tx][ty + i]));
}

// ============================================================================
// K1/K4: tf32 tensor-core GEMM, BK=32, single-sync cp.async pipeline.
// B pre-transposed (Bt[N][K], tf32-valued): ALL fragments via ldmatrix.x4.
// Per iter/warp: 24 LDSM + 64 mma, zero scalar LDS.
// SPLIT (K1): q/k cols -> bf16 hi/lo planes; v cols -> tf32 fp32.
// ============================================================================
#define AP 36
#define GEMM_SMEM_BYTES (4 * 128 * AP * 4)   // 73728 (2 bufs A + 2 bufs Bt)

template <bool BIAS, bool SPLIT>
__global__ __launch_bounds__(256, 2) void gemm_tf32(
    const float* __restrict__ A, const float* __restrict__ Bt,
    const float* __restrict__ bias, float* __restrict__ C,
    __nv_bfloat16* __restrict__ qkh, __nv_bfloat16* __restrict__ qkl,
    float* __restrict__ vout, int M, int N, int K)
{
    extern __shared__ float smg[];
    float* As = smg;                   // [2][128*AP]
    float* Bs = smg + 2 * 128 * AP;    // [2][128*AP]  (Bt tiles)

    const int tid  = threadIdx.x;
    const int warp = tid >> 5, lane = tid & 31;
    const int g    = lane >> 2, tig = lane & 3;
    const int wm   = warp & 1,  wn  = warp >> 1;
    const int m0   = blockIdx.y * 128, n0 = blockIdx.x * 128;

    const uint32_t sA0 = (uint32_t)__cvta_generic_to_shared(As);
    const uint32_t sB0 = (uint32_t)__cvta_generic_to_shared(Bs);
    // A-side LDSM offset: row = wm*64 + (lane&15), col-word = (lane>>4)*4
    const uint32_t a_off = (uint32_t)((wm * 64 + (lane & 15)) * AP + ((lane >> 4) * 4));
    // B-side LDSM offset (pair p adds p*16*AP):
    // row = wn*32 + ((lane>>4)&1)*8 + (lane&7), col-word = ((lane>>3)&1)*4
    const uint32_t b_off = (uint32_t)((wn * 32 + ((lane >> 4) & 1) * 8 + (lane & 7)) * AP
                                      + (((lane >> 3) & 1) * 4));

    float c[4][4][4];
    #pragma unroll
    for (int i = 0; i < 4; i++)
        #pragma unroll
        for (int j = 0; j < 4; j++)
            #pragma unroll
            for (int f = 0; f < 4; f++) c[i][j][f] = 0.f;

    const int niter = K / 32;

    #define GEMM_STAGE(IT, BUF) do {                                          \
        int k0s = (IT) * 32;                                                  \
        float* ab = As + (BUF) * 128 * AP;                                    \
        float* bb = Bs + (BUF) * 128 * AP;                                    \
        _Pragma("unroll")                                                     \
        for (int l = 0; l < 4; l++) {                                         \
            int li = tid + l * 256;                                           \
            int r = li >> 3, c4 = (li & 7) * 4;                               \
            bool pr = (m0 + r) < M;                                           \
            int gr = pr ? (m0 + r) : (M - 1);                                 \
            cp_async16(&ab[r * AP + c4], A + (size_t)gr * K + k0s + c4, pr);  \
            cp_async16(&bb[r * AP + c4],                                      \
                       Bt + (size_t)(n0 + r) * K + k0s + c4, true);           \
        }                                                                     \
        CP_COMMIT();                                                          \
    } while (0)

    GEMM_STAGE(0, 0);

    for (int it = 0; it < niter; it++) {
        int cur = it & 1;
        CP_WAIT0();
        __syncthreads();
        if (it + 1 < niter) GEMM_STAGE(it + 1, cur ^ 1);

        const uint32_t sAcur = sA0 + (uint32_t)(cur * 128 * AP) * 4u;
        const uint32_t sBcur = sB0 + (uint32_t)(cur * 128 * AP) * 4u;
        #pragma unroll
        for (int kk = 0; kk < 32; kk += 8) {
            uint32_t af[4][4];
            #pragma unroll
            for (int mt = 0; mt < 4; mt++)
                ldsm4(af[mt], sAcur + 4u * (a_off + (uint32_t)(mt * 16 * AP + kk)));
            uint32_t bf[4][2];
            #pragma unroll
            for (int p = 0; p < 2; p++) {
                uint32_t t[4];
                ldsm4(t, sBcur + 4u * (b_off + (uint32_t)(p * 16 * AP + kk)));
                bf[2 * p][0]     = t[0]; bf[2 * p][1]     = t[1];
                bf[2 * p + 1][0] = t[2]; bf[2 * p + 1][1] = t[3];
            }
            #pragma unroll
            for (int mt = 0; mt < 4; mt++)
                #pragma unroll
                for (int nt = 0; nt < 4; nt++)
                    mma_m16n8k8(c[mt][nt], af[mt], bf[nt]);
        }
    }
    #undef GEMM_STAGE

    #pragma unroll
    for (int mt = 0; mt < 4; mt++) {
        int row0 = m0 + wm * 64 + mt * 16 + g;
        #pragma unroll
        for (int nt = 0; nt < 4; nt++) {
            int col = n0 + wn * 32 + nt * 8 + 2 * tig;
            float b0 = 0.f, b1 = 0.f;
            if (BIAS) { b0 = bias[col]; b1 = bias[col + 1]; }
            #pragma unroll
            for (int half = 0; half < 2; half++) {
                int r = row0 + half * 8;
                if (r >= M) continue;
                float v0 = c[mt][nt][half * 2 + 0] + b0;
                float v1 = c[mt][nt][half * 2 + 1] + b1;
                if (SPLIT) {
                    if (col < 1024) {
                        __nv_bfloat16 h0 = __float2bfloat16(v0);
                        __nv_bfloat16 h1 = __float2bfloat16(v1);
                        __nv_bfloat16 l0 = __float2bfloat16(v0 - __bfloat162float(h0));
                        __nv_bfloat16 l1 = __float2bfloat16(v1 - __bfloat162float(h1));
                        *(__nv_bfloat162*)(qkh + (size_t)r * 1024 + col) =
                            __halves2bfloat162(h0, h1);
                        *(__nv_bfloat162*)(qkl + (size_t)r * 1024 + col) =
                            __halves2bfloat162(l0, l1);
                    } else {
                        float2 o = make_float2(__uint_as_float(f2tf32(v0)),
                                               __uint_as_float(f2tf32(v1)));
                        *(float2*)(vout + (size_t)r * 512 + (col - 1024)) = o;
                    }
                } else {
                    *(float2*)(C + (size_t)r * N + col) = make_float2(v0, v1);
                }
            }
        }
    }
}

// ============================================================================
// K2: gating (unchanged)
// ============================================================================
__global__ __launch_bounds__(256) void gate_kernel(
    const float* __restrict__ x, const float* __restrict__ tw,
    const float* __restrict__ tb, float* __restrict__ gate)
{
    int row = blockIdx.x * 8 + (threadIdx.x >> 5);
    if (row >= MROWS) return;
    int lane = threadIdx.x & 31;
    const float* xr = x + (size_t)row * CC;
    float s0 = 0.f, s1 = 0.f, s2 = 0.f, s3 = 0.f;
    for (int c = lane; c < CC; c += 32) {
        float xv = xr[c];
        float4 w = *(const float4*)(tw + c * 4);
        s0 += xv * w.x; s1 += xv * w.y; s2 += xv * w.z; s3 += xv * w.w;
    }
    s0 = warp_sum(s0); s1 = warp_sum(s1); s2 = warp_sum(s2); s3 = warp_sum(s3);
    float l0 = s0 + tb[0], l1 = s1 + tb[1], l2 = s2 + tb[2], l3 = s3 + tb[3];
    float m = fmaxf(fmaxf(l0, l1), fmaxf(l2, l3));
    float e0 = __expf(l0 - m), e1 = __expf(l1 - m);
    float e2 = __expf(l2 - m), e3 = __expf(l3 - m);
    float inv = 1.f / (e0 + e1 + e2 + e3);
    if (lane == 0) {
        float4 o = make_float4(e0 * inv, e1 * inv, e2 * inv, e3 * inv);
        *(float4*)(gate + (size_t)row * 4) = o;
    }
}

// ============================================================================
// K3: attention (unchanged from R13). bf16x3 QK^T + LDSM, tf32 PV.
// ============================================================================
#define QW  36
#define VP2 72
#define PP2 260
#define K3_SMEM_WORDS (2*32*QW + 2*2*64*QW + 2*32*VP2 + 32*PP2)
#define K3_SMEM_BYTES (K3_SMEM_WORDS * 4)   // 97792

__global__ __launch_bounds__(256, 2) void attn_tc2_kernel(
    const __nv_bfloat16* __restrict__ qkh, const __nv_bfloat16* __restrict__ qkl,
    const float* __restrict__ vsrc, const float* __restrict__ gate,
    float* __restrict__ eo)
{
    extern __shared__ float smf[];
    uint32_t* sQh = (uint32_t*)smf;
    uint32_t* sQl = sQh + 32 * QW;
    uint32_t* sKh = sQl + 32 * QW;
    uint32_t* sKl = sKh + 2 * 64 * QW;
    float*    sV  = (float*)(sKl + 2 * 64 * QW);
    float*    sP  = sV + 2 * 32 * VP2;

    const int tid  = threadIdx.x;
    const int warp = tid >> 5, lane = tid & 31;
    const int g    = lane >> 2, tig = lane & 3;
    const int wm   = warp & 1,  wn  = warp >> 1;
    const int bid  = blockIdx.y;
    const int b = bid / (HH * NJ);
    const int h = (bid / NJ) % HH;
    const int n = bid % NJ;
    const int t0 = blockIdx.x * 32;
    const float scale = 0.125f;

    const uint32_t uQh = (uint32_t)__cvta_generic_to_shared(sQh);
    const uint32_t uQl = (uint32_t)__cvta_generic_to_shared(sQl);
    const uint32_t uKh = (uint32_t)__cvta_generic_to_shared(sKh);
    const uint32_t uKl = (uint32_t)__cvta_generic_to_shared(sKl);
    const uint32_t uP  = (uint32_t)__cvta_generic_to_shared(sP);

    const uint32_t qa_off = (uint32_t)((wm * 16 + (lane & 15)) * QW + ((lane >> 4) * 4));
    const uint32_t pa_off = (uint32_t)((wm * 16 + (lane & 15)) * PP2 + ((lane >> 4) * 4));
    const uint32_t kb_off = (uint32_t)((wn * 16 + ((lane >> 4) << 3) + (lane & 7)) * QW
                                       + (((lane >> 3) & 1) * 4));

    float4 gv = make_float4(0.f, 0.f, 0.f, 0.f);
    {
        int tg = t0 + warp * 4 + lane;
        if (lane < 4 && tg < TT)
            gv = *(const float4*)(gate + ((size_t)((b * TT + tg) * NJ + n)) * 4);
    }

    #define QKV_ROW(s) (((size_t)(b * TT + (s))) * NJ + n)

    {
        int r = tid >> 3, seg = tid & 7;
        int t = t0 + r;
        bool pr = t < TT;
        size_t qrow = QKV_ROW(pr ? t : 0);
        cp_async16(sQh + r * QW + seg * 4, qkh + qrow * 1024 + h * HD + seg * 8, pr);
        cp_async16(sQl + r * QW + seg * 4, qkl + qrow * 1024 + h * HD + seg * 8, pr);
        #pragma unroll
        for (int l = 0; l < 2; l++) {
            int li = tid + l * 256;
            int kr = li >> 3, ks = li & 7;
            bool kp = kr < TT;
            size_t krow = QKV_ROW(kp ? kr : 0);
            cp_async16(sKh + kr * QW + ks * 4, qkh + krow * 1024 + 512 + h * HD + ks * 8, kp);
            cp_async16(sKl + kr * QW + ks * 4, qkl + krow * 1024 + 512 + h * HD + ks * 8, kp);
        }
    }
    CP_COMMIT();
    #pragma unroll
    for (int l = 0; l < 2; l++) {
        int li = tid + l * 256;
        int r = li >> 4, c4 = (li & 15) * 4;
        cp_async16(sV + r * VP2 + c4, vsrc + QKV_ROW(r) * 512 + h * HD + c4, true);
    }
    CP_COMMIT();

    for (int c = 0; c < 4; c++) {
        if (c == 0) { CP_WAIT1(); } else { CP_WAIT0(); }
        __syncthreads();
        if (c < 3) {
            int s0 = 64 * (c + 1);
            uint32_t* khn = sKh + ((c + 1) & 1) * 64 * QW;
            uint32_t* kln = sKl + ((c + 1) & 1) * 64 * QW;
            #pragma unroll
            for (int l = 0; l < 2; l++) {
                int li = tid + l * 256;
                int kr = li >> 3, ks = li & 7;
                int s = s0 + kr;
                bool kp = s < TT;
                size_t krow = QKV_ROW(kp ? s : 0);
                cp_async16(khn + kr * QW + ks * 4, qkh + krow * 1024 + 512 + h * HD + ks * 8, kp);
                cp_async16(kln + kr * QW + ks * 4, qkl + krow * 1024 + 512 + h * HD + ks * 8, kp);
            }
            CP_COMMIT();
        }

        const uint32_t uKhc = uKh + (uint32_t)((c & 1) * 64 * QW) * 4u;
        const uint32_t uKlc = uKl + (uint32_t)((c & 1) * 64 * QW) * 4u;

        float acc[2][4];
        #pragma unroll
        for (int j = 0; j < 2; j++)
            #pragma unroll
            for (int f = 0; f < 4; f++) acc[j][f] = 0.f;

        #pragma unroll
        for (int ks = 0; ks < 32; ks += 8) {
            uint32_t ah[4], al[4], th[4], tl[4];
            ldsm4(ah, uQh + 4u * (qa_off + (uint32_t)ks));
            ldsm4(al, uQl + 4u * (qa_off + (uint32_t)ks));
            ldsm4(th, uKhc + 4u * (kb_off + (uint32_t)ks));
            ldsm4(tl, uKlc + 4u * (kb_off + (uint32_t)ks));
            uint32_t bh[2][2] = {{th[0], th[1]}, {th[2], th[3]}};
            uint32_t bl[2][2] = {{tl[0], tl[1]}, {tl[2], tl[3]}};
            #pragma unroll
            for (int nt = 0; nt < 2; nt++) {
                mma_m16n8k16_bf16(acc[nt], ah, bh[nt]);
                mma_m16n8k16_bf16(acc[nt], ah, bl[nt]);
                mma_m16n8k16_bf16(acc[nt], al, bh[nt]);
            }
        }

        int row = wm * 16 + g;
        #pragma unroll
        for (int nt = 0; nt < 2; nt++) {
            int col = c * 64 + wn * 16 + nt * 8 + 2 * tig;
            *(float2*)&sP[row * PP2 + col] =
                make_float2(acc[nt][0] * scale, acc[nt][1] * scale);
            *(float2*)&sP[(row + 8) * PP2 + col] =
                make_float2(acc[nt][2] * scale, acc[nt][3] * scale);
        }
    }
    __syncthreads();

    for (int rr = 0; rr < 4; rr++) {
        int r = warp * 4 + rr;
        int t = t0 + r;
        if (t >= TT) break;
        float p[8];
        float m = -1e30f;
        #pragma unroll
        for (int i2 = 0; i2 < 8; i2++) {
            int s = lane + 32 * i2;
            float v = (s < TT) ? sP[r * PP2 + s] : -1e30f;
            p[i2] = v;
            m = fmaxf(m, v);
        }
        m = warp_max(m);
        int a9 = (t / 9) * 9, a27 = (t / 27) * 27, a81 = (t / 81) * 81;
        float z9 = 0.f, z27 = 0.f, z81 = 0.f, z243 = 0.f;
        #pragma unroll
        for (int i2 = 0; i2 < 8; i2++) {
            int s = lane + 32 * i2;
            float e = (s < TT) ? __expf(p[i2] - m) : 0.f;
            p[i2] = e;
            z243 += e;
            if (s >= a81 && s < a81 + 81) z81 += e;
            if (s >= a27 && s < a27 + 27) z27 += e;
            if (s >= a9  && s < a9  + 9)  z9  += e;
        }
        z9 = warp_sum(z9); z27 = warp_sum(z27);
        z81 = warp_sum(z81); z243 = warp_sum(z243);
        float w9   = __shfl_sync(0xffffffffu, gv.x, rr) / z9;
        float w27  = __shfl_sync(0xffffffffu, gv.y, rr) / z27;
        float w81  = __shfl_sync(0xffffffffu, gv.z, rr) / z81;
        float w243 = __shfl_sync(0xffffffffu, gv.w, rr) / z243;
        #pragma unroll
        for (int i2 = 0; i2 < 8; i2++) {
            int s = lane + 32 * i2;
            float val = 0.f;
            if (s < TT) {
                float cf = w243;
                if (s >= a81 && s < a81 + 81) cf += w81;
                if (s >= a27 && s < a27 + 27) cf += w27;
                if (s >= a9  && s < a9  + 9)  cf += w9;
                val = __uint_as_float(f2tf32(p[i2] * cf));
            }
            sP[r * PP2 + s] = val;
        }
    }

    float acc2[2][4];
    #pragma unroll
    for (int j = 0; j < 2; j++)
        #pragma unroll
        for (int f = 0; f < 4; f++) acc2[j][f] = 0.f;

    for (int c = 0; c < 8; c++) {
        CP_WAIT0();
        __syncthreads();
        if (c < 7) {
            int vc = 32 * (c + 1);
            float* vbn = sV + ((c + 1) & 1) * 32 * VP2;
            #pragma unroll
            for (int l = 0; l < 2; l++) {
                int li = tid + l * 256;
                int r = li >> 4, c4 = (li & 15) * 4;
                int s = vc + r;
                bool pr = s < TT;
                int ss = pr ? s : TT - 1;
                cp_async16(vbn + r * VP2 + c4, vsrc + QKV_ROW(ss) * 512 + h * HD + c4, pr);
            }
            CP_COMMIT();
        }

        const float* vb = sV + (c & 1) * 32 * VP2;
        int vc0 = c * 32;
        #pragma unroll
        for (int kk = 0; kk < 32; kk += 8) {
            uint32_t af[4];
            ldsm4(af, uP + 4u * (pa_off + (uint32_t)(vc0 + kk)));
            uint32_t bf[2][2];
            #pragma unroll
            for (int nt = 0; nt < 2; nt++) {
                int nc = wn * 16 + nt * 8 + g;
                bf[nt][0] = __float_as_uint(vb[(kk + tig)     * VP2 + nc]);
                bf[nt][1] = __float_as_uint(vb[(kk + tig + 4) * VP2 + nc]);
            }
            #pragma unroll
            for (int nt = 0; nt < 2; nt++)
                mma_m16n8k8(acc2[nt], af, bf[nt]);
        }
    }

    {
        int row = wm * 16 + g;
        #pragma unroll
        for (int nt = 0; nt < 2; nt++) {
            int col = wn * 16 + nt * 8 + 2 * tig;
            int t = t0 + row;
            if (t < TT) {
                *(float2*)(eo + QKV_ROW(t) * CC + h * HD + col) =
                    make_float2(__uint_as_float(f2tf32(acc2[nt][0])),
                                __uint_as_float(f2tf32(acc2[nt][1])));
            }
            if (t + 8 < TT) {
                *(float2*)(eo + QKV_ROW(t + 8) * CC + h * HD + col) =
                    make_float2(__uint_as_float(f2tf32(acc2[nt][2])),
                                __uint_as_float(f2tf32(acc2[nt][3])));
            }
        }
    }
    #undef QKV_ROW
}

// ============================================================================
extern "C" void kernel_launch(void* const* d_in, const int* in_sizes, int n_in,
                              void* d_out, int out_size)
{
    const float* x      = (const float*)d_in[0];
    const float* qkv_w  = (const float*)d_in[1];
    const float* proj_w = (const float*)d_in[2];
    const float* proj_b = (const float*)d_in[3];
    const float* te_w   = (const float*)d_in[4];
    const float* te_b   = (const float*)d_in[5];
    float* out = (float*)d_out;

    float *gate_p, *eo_p, *xtf_p, *w1t_p, *w2t_p, *v_p;
    __nv_bfloat16 *qkh_p, *qkl_p;
    cudaGetSymbolAddress((void**)&qkh_p,  g_qkh);
    cudaGetSymbolAddress((void**)&qkl_p,  g_qkl);
    cudaGetSymbolAddress((void**)&v_p,    g_v);
    cudaGetSymbolAddress((void**)&gate_p, g_gate);
    cudaGetSymbolAddress((void**)&eo_p,   g_eo);
    cudaGetSymbolAddress((void**)&xtf_p,  g_xtf);
    cudaGetSymbolAddress((void**)&w1t_p,  g_w1t);
    cudaGetSymbolAddress((void**)&w2t_p,  g_w2t);

    cudaFuncSetAttribute(attn_tc2_kernel, cudaFuncAttributeMaxDynamicSharedMemorySize,
                         K3_SMEM_BYTES);
    cudaFuncSetAttribute(gemm_tf32<false, true>,
                         cudaFuncAttributeMaxDynamicSharedMemorySize, GEMM_SMEM_BYTES);
    cudaFuncSetAttribute(gemm_tf32<true, false>,
                         cudaFuncAttributeMaxDynamicSharedMemorySize, GEMM_SMEM_BYTES);

    // K0: round x; round+transpose w1, w2 (n-major for LDSM B-fragments)
    cvt_tf32_kernel<<<592, 256>>>(x, xtf_p, MROWS * CC / 4);
    cvt_transpose_kernel<<<dim3(NQKV / 32, CC / 32), 256>>>(qkv_w, w1t_p, CC, NQKV);
    cvt_transpose_kernel<<<dim3(CC / 32, CC / 32), 256>>>(proj_w, w2t_p, CC, CC);

    // K1: qkv = x @ qkv_w — q/k bf16 hi/lo planes, v tf32 plane
    gemm_tf32<false, true><<<dim3(NQKV / 128, (MROWS + 127) / 128), 256, GEMM_SMEM_BYTES>>>(
        xtf_p, w1t_p, nullptr, nullptr, qkh_p, qkl_p, v_p, MROWS, NQKV, CC);

    // K2: gate = softmax(x @ te_w + te_b)
    gate_kernel<<<(MROWS + 7) / 8, 256>>>(x, te_w, te_b, gate_p);

    // K3: 2-CTA/SM attention, bf16x3 QK^T, LDSM fragments
    attn_tc2_kernel<<<dim3(8, BB * HH * NJ), 256, K3_SMEM_BYTES>>>(
        qkh_p, qkl_p, v_p, gate_p, eo_p);

    // K4: out = eo @ proj_w + proj_b
    gemm_tf32<true, false><<<dim3(CC / 128, (MROWS + 127) / 128), 256, GEMM_SMEM_BYTES>>>(
        eo_p, w2t_p, proj_b, out, nullptr, nullptr, nullptr, MROWS, CC, CC);
}